// round 2
// baseline (speedup 1.0000x reference)
#include <cuda_runtime.h>
#include <cuda_bf16.h>
#include <math.h>

// ---------------------------------------------------------------------------
// Problem constants
// ---------------------------------------------------------------------------
#define S_LEN   2048
#define HIDDEN  4096
#define NHEADS  32
#define NKV     8
#define HDIM    128
#define GROUPS  (NHEADS / NKV)

// ---------------------------------------------------------------------------
// Device scratch (allocation-free rule: __device__ globals)
// ---------------------------------------------------------------------------
__device__ float g_qtmp[S_LEN * NHEADS * HDIM];   // [s][h*128+d]  32MB
__device__ float g_ktmp[S_LEN * NKV * HDIM];      // [s][kv*128+d]  8MB
__device__ float g_vtmp[S_LEN * NKV * HDIM];      //                8MB
__device__ float g_qheads[NHEADS * S_LEN * HDIM]; // [h][s][d]     32MB
__device__ float g_attn[S_LEN * NHEADS * HDIM];   // [s][h*128+d]  32MB

// ---------------------------------------------------------------------------
// SGEMM: C[M,N] = A[M,K] @ B[K,N], all row-major fp32.
// 128x128 block tile, BK=16, 256 threads, 8x8 per thread.
// ---------------------------------------------------------------------------
__global__ __launch_bounds__(256) void sgemm128(const float* __restrict__ A,
                                                const float* __restrict__ B,
                                                float* __restrict__ C,
                                                int M, int N, int K) {
    __shared__ float As[16][128];   // [k][m]
    __shared__ float Bs[16][128];   // [k][n]

    const int bm = blockIdx.y * 128;
    const int bn = blockIdx.x * 128;
    const int tid = threadIdx.x;
    const int tx = tid & 15;        // n-dir
    const int ty = tid >> 4;        // m-dir

    const int arow = tid >> 2;          // 0..63
    const int acol = (tid & 3) * 4;     // 0..12
    const int brow = tid >> 5;          // 0..7
    const int bcol = (tid & 31) * 4;    // 0..124

    float acc[8][8];
#pragma unroll
    for (int i = 0; i < 8; i++)
#pragma unroll
        for (int j = 0; j < 8; j++) acc[i][j] = 0.f;

    for (int k0 = 0; k0 < K; k0 += 16) {
#pragma unroll
        for (int r = 0; r < 2; r++) {
            int row = arow + r * 64;
            float4 a4 = *(const float4*)&A[(size_t)(bm + row) * K + k0 + acol];
            As[acol + 0][row] = a4.x;
            As[acol + 1][row] = a4.y;
            As[acol + 2][row] = a4.z;
            As[acol + 3][row] = a4.w;
        }
#pragma unroll
        for (int r = 0; r < 2; r++) {
            int row = brow + r * 8;
            *(float4*)&Bs[row][bcol] =
                *(const float4*)&B[(size_t)(k0 + row) * N + bn + bcol];
        }
        __syncthreads();

#pragma unroll
        for (int kk = 0; kk < 16; kk++) {
            float ra[8], rb[8];
            *(float4*)&ra[0] = *(const float4*)&As[kk][ty * 8];
            *(float4*)&ra[4] = *(const float4*)&As[kk][ty * 8 + 4];
            *(float4*)&rb[0] = *(const float4*)&Bs[kk][tx * 8];
            *(float4*)&rb[4] = *(const float4*)&Bs[kk][tx * 8 + 4];
#pragma unroll
            for (int i = 0; i < 8; i++)
#pragma unroll
                for (int j = 0; j < 8; j++)
                    acc[i][j] = fmaf(ra[i], rb[j], acc[i][j]);
        }
        __syncthreads();
    }

#pragma unroll
    for (int i = 0; i < 8; i++) {
        size_t base = (size_t)(bm + ty * 8 + i) * N + bn + tx * 8;
        *(float4*)&C[base]     = make_float4(acc[i][0], acc[i][1], acc[i][2], acc[i][3]);
        *(float4*)&C[base + 4] = make_float4(acc[i][4], acc[i][5], acc[i][6], acc[i][7]);
    }
}

// ---------------------------------------------------------------------------
// Per-(s,h) RMSNorm over 128 dims + RoPE.  in: [s][H*128+d], out: [h][s][d]
// Position of token s is s itself (position_ids = arange(B*S)); deriving it
// from blockIdx sidesteps the int32/int64 ambiguity of the pos input.
// blockDim = 128, grid = (S, H)
// ---------------------------------------------------------------------------
__global__ __launch_bounds__(128) void norm_rope_kernel(
    const float* __restrict__ inp, const float* __restrict__ w,
    float* __restrict__ out, int H) {
    const int s = blockIdx.x;
    const int h = blockIdx.y;
    const int d = threadIdx.x;

    float x = inp[((size_t)s * H + h) * HDIM + d];
    float ss = x * x;
#pragma unroll
    for (int o = 16; o; o >>= 1) ss += __shfl_xor_sync(0xffffffffu, ss, o);

    __shared__ float wss[4];
    __shared__ float xs[HDIM];
    if ((d & 31) == 0) wss[d >> 5] = ss;
    __syncthreads();
    float var = (wss[0] + wss[1] + wss[2] + wss[3]) * (1.0f / 128.0f);
    float xn = x * rsqrtf(var + 1e-6f) * w[d];
    xs[d] = xn;
    __syncthreads();

    if (d < 64) {
        float p = (float)s;   // position_ids == arange
        float e = (float)(2 * d) * (1.0f / 128.0f);
        float invf = powf(1000000.0f, -e);
        float f = p * invf;
        float si, c;
        sincosf(f, &si, &c);
        float x1 = xs[d], x2 = xs[d + 64];
        size_t base = ((size_t)h * S_LEN + s) * HDIM;
        out[base + d]      = x1 * c - x2 * si;
        out[base + d + 64] = x2 * c + x1 * si;
    }
}

// ---------------------------------------------------------------------------
// V transpose: [s][kv*128+d] -> [kv][s][d]
// ---------------------------------------------------------------------------
__global__ void v_transpose_kernel(const float* __restrict__ vt,
                                   float* __restrict__ out) {
    size_t i = (size_t)blockIdx.x * blockDim.x + threadIdx.x;
    if (i >= (size_t)S_LEN * NKV * HDIM) return;
    int s  = (int)(i >> 10);
    int c  = (int)(i & 1023);
    int kv = c >> 7;
    int d  = c & 127;
    out[((size_t)kv * S_LEN + s) * HDIM + d] = vt[i];
}

// ---------------------------------------------------------------------------
// Attention: per (head, 128-row q tile).  Two passes over KV (64-wide tiles):
//  pass1: exact row max / exp-sum (online).
//  pass2: recompute scores, write normalized probs (zero upper triangle),
//         accumulate attn = P @ V via shared-memory P tile.
// Q pre-scaled by 1/sqrt(128).
// grid = (16, 32), 256 threads, dynamic smem 165,888 B.
// ---------------------------------------------------------------------------
#define ATT_SMEM_FLOATS (128 * 128 + 128 * 64 + 64 * 128 + 128 * 68)
#define ATT_SMEM_BYTES  (ATT_SMEM_FLOATS * 4)

__global__ __launch_bounds__(256) void attention_kernel(
    const float* __restrict__ Q,      // [32][S][128]
    const float* __restrict__ Kc,     // [8][S][128]
    const float* __restrict__ Vc,     // [8][S][128]
    float* __restrict__ probs,        // [32][S][S]
    float* __restrict__ attnf) {      // [S][4096]
    extern __shared__ float sm[];
    float* Qs = sm;                   // [d][r]  128x128
    float* Ks = Qs + 128 * 128;       // [d][c]  128x64
    float* Vs = Ks + 128 * 64;        // [c][d]  64x128
    float* Ps = Vs + 64 * 128;        // [r][68] 128x68

    const int h   = blockIdx.y;
    const int q0  = blockIdx.x * 128;
    const int kvh = h >> 2;
    const int tid = threadIdx.x;
    const int tx  = tid & 15;         // 16 groups
    const int ty  = tid >> 4;         // 16 groups of 8 rows
    const float scale = 0.08838834764831845f;  // 1/sqrt(128)

    // ---- load Q tile transposed, pre-scaled ----
    {
        const int r0 = tid >> 5;
        const int dd = (tid & 31) * 4;
#pragma unroll
        for (int rr = 0; rr < 16; rr++) {
            int r = r0 + rr * 8;
            float4 q4 = *(const float4*)&Q[((size_t)h * S_LEN + (q0 + r)) * HDIM + dd];
            Qs[(dd + 0) * 128 + r] = q4.x * scale;
            Qs[(dd + 1) * 128 + r] = q4.y * scale;
            Qs[(dd + 2) * 128 + r] = q4.z * scale;
            Qs[(dd + 3) * 128 + r] = q4.w * scale;
        }
    }

    float m[8], l[8];
#pragma unroll
    for (int i = 0; i < 8; i++) { m[i] = -1e30f; l[i] = 0.f; }
    const int row_last = q0 + 127;
    const int nvalid = (row_last >> 6) + 1;
    __syncthreads();

    // ================= PASS 1: stats =================
    for (int jt = 0; jt < nvalid; jt++) {
        const int c0 = jt * 64;
        {
            const int dd = (tid & 31) * 4;
#pragma unroll
            for (int rr = 0; rr < 8; rr++) {
                int c = (tid >> 5) + rr * 8;
                float4 k4 = *(const float4*)&Kc[((size_t)kvh * S_LEN + (c0 + c)) * HDIM + dd];
                Ks[(dd + 0) * 64 + c] = k4.x;
                Ks[(dd + 1) * 64 + c] = k4.y;
                Ks[(dd + 2) * 64 + c] = k4.z;
                Ks[(dd + 3) * 64 + c] = k4.w;
            }
        }
        __syncthreads();

        float sreg[8][4];
#pragma unroll
        for (int i = 0; i < 8; i++)
#pragma unroll
            for (int j = 0; j < 4; j++) sreg[i][j] = 0.f;

        for (int d = 0; d < 128; d++) {
            float rq[8], rk[4];
            *(float4*)&rq[0] = *(const float4*)&Qs[d * 128 + ty * 8];
            *(float4*)&rq[4] = *(const float4*)&Qs[d * 128 + ty * 8 + 4];
            *(float4*)&rk[0] = *(const float4*)&Ks[d * 64 + tx * 4];
#pragma unroll
            for (int i = 0; i < 8; i++)
#pragma unroll
                for (int j = 0; j < 4; j++)
                    sreg[i][j] = fmaf(rq[i], rk[j], sreg[i][j]);
        }

#pragma unroll
        for (int i = 0; i < 8; i++) {
            int grow = q0 + ty * 8 + i;
            float tmax = -1e30f;
#pragma unroll
            for (int j = 0; j < 4; j++) {
                if (c0 + tx * 4 + j > grow) sreg[i][j] = -1e30f;
                tmax = fmaxf(tmax, sreg[i][j]);
            }
#pragma unroll
            for (int o = 8; o; o >>= 1)
                tmax = fmaxf(tmax, __shfl_xor_sync(0xffffffffu, tmax, o));
            float mn = fmaxf(m[i], tmax);
            float corr = __expf(m[i] - mn);
            float ssum = 0.f;
#pragma unroll
            for (int j = 0; j < 4; j++) ssum += __expf(sreg[i][j] - mn);
#pragma unroll
            for (int o = 8; o; o >>= 1)
                ssum += __shfl_xor_sync(0xffffffffu, ssum, o);
            l[i] = l[i] * corr + ssum;
            m[i] = mn;
        }
        __syncthreads();
    }

    float linv[8];
#pragma unroll
    for (int i = 0; i < 8; i++) linv[i] = 1.0f / l[i];

    float acc[8][8];
#pragma unroll
    for (int i = 0; i < 8; i++)
#pragma unroll
        for (int j = 0; j < 8; j++) acc[i][j] = 0.f;

    // ================= PASS 2: probs + P@V =================
    for (int jt = 0; jt < S_LEN / 64; jt++) {
        const int c0 = jt * 64;
        if (c0 > row_last) {
            float4 z = make_float4(0.f, 0.f, 0.f, 0.f);
#pragma unroll
            for (int i = 0; i < 8; i++) {
                int grow = q0 + ty * 8 + i;
                *(float4*)&probs[((size_t)h * S_LEN + grow) * S_LEN + c0 + tx * 4] = z;
            }
            continue;
        }
        {
            const int dd = (tid & 31) * 4;
#pragma unroll
            for (int rr = 0; rr < 8; rr++) {
                int c = (tid >> 5) + rr * 8;
                size_t gk = ((size_t)kvh * S_LEN + (c0 + c)) * HDIM + dd;
                float4 k4 = *(const float4*)&Kc[gk];
                Ks[(dd + 0) * 64 + c] = k4.x;
                Ks[(dd + 1) * 64 + c] = k4.y;
                Ks[(dd + 2) * 64 + c] = k4.z;
                Ks[(dd + 3) * 64 + c] = k4.w;
                *(float4*)&Vs[c * 128 + dd] = *(const float4*)&Vc[gk];
            }
        }
        __syncthreads();

        float sreg[8][4];
#pragma unroll
        for (int i = 0; i < 8; i++)
#pragma unroll
            for (int j = 0; j < 4; j++) sreg[i][j] = 0.f;

        for (int d = 0; d < 128; d++) {
            float rq[8], rk[4];
            *(float4*)&rq[0] = *(const float4*)&Qs[d * 128 + ty * 8];
            *(float4*)&rq[4] = *(const float4*)&Qs[d * 128 + ty * 8 + 4];
            *(float4*)&rk[0] = *(const float4*)&Ks[d * 64 + tx * 4];
#pragma unroll
            for (int i = 0; i < 8; i++)
#pragma unroll
                for (int j = 0; j < 4; j++)
                    sreg[i][j] = fmaf(rq[i], rk[j], sreg[i][j]);
        }

#pragma unroll
        for (int i = 0; i < 8; i++) {
            int grow = q0 + ty * 8 + i;
            float p[4];
#pragma unroll
            for (int j = 0; j < 4; j++) {
                float sv = (c0 + tx * 4 + j > grow) ? -1e30f : sreg[i][j];
                p[j] = __expf(sv - m[i]) * linv[i];
            }
            *(float4*)&Ps[(ty * 8 + i) * 68 + tx * 4] = *(float4*)p;
            *(float4*)&probs[((size_t)h * S_LEN + grow) * S_LEN + c0 + tx * 4] = *(float4*)p;
        }
        __syncthreads();

        for (int kk = 0; kk < 64; kk++) {
            float rv[8];
            *(float4*)&rv[0] = *(const float4*)&Vs[kk * 128 + tx * 8];
            *(float4*)&rv[4] = *(const float4*)&Vs[kk * 128 + tx * 8 + 4];
#pragma unroll
            for (int i = 0; i < 8; i++) {
                float rp = Ps[(ty * 8 + i) * 68 + kk];
#pragma unroll
                for (int j = 0; j < 8; j++)
                    acc[i][j] = fmaf(rp, rv[j], acc[i][j]);
            }
        }
        __syncthreads();
    }

    // ---- write attn in [s][h*128+d] layout (plain GEMM A for O-proj) ----
#pragma unroll
    for (int i = 0; i < 8; i++) {
        size_t base = (size_t)(q0 + ty * 8 + i) * (NHEADS * HDIM) + h * HDIM + tx * 8;
        *(float4*)&attnf[base]     = make_float4(acc[i][0], acc[i][1], acc[i][2], acc[i][3]);
        *(float4*)&attnf[base + 4] = make_float4(acc[i][4], acc[i][5], acc[i][6], acc[i][7]);
    }
}

// ---------------------------------------------------------------------------
// Launch
// ---------------------------------------------------------------------------
extern "C" void kernel_launch(void* const* d_in, const int* in_sizes, int n_in,
                              void* d_out, int out_size) {
    const float* X            = (const float*)d_in[0];
    const float* Wq           = (const float*)d_in[2];
    const float* Wk           = (const float*)d_in[3];
    const float* Wv           = (const float*)d_in[4];
    const float* Wo           = (const float*)d_in[5];
    const float* qw           = (const float*)d_in[6];
    const float* kw           = (const float*)d_in[7];

    float* out   = (float*)d_out;
    float* new_k = out + (size_t)S_LEN * HIDDEN;
    float* new_v = new_k + (size_t)NKV * S_LEN * HDIM;
    float* probs = new_v + (size_t)NKV * S_LEN * HDIM;

    float *qtmp, *ktmp, *vtmp, *qheads, *attnf;
    cudaGetSymbolAddress((void**)&qtmp, g_qtmp);
    cudaGetSymbolAddress((void**)&ktmp, g_ktmp);
    cudaGetSymbolAddress((void**)&vtmp, g_vtmp);
    cudaGetSymbolAddress((void**)&qheads, g_qheads);
    cudaGetSymbolAddress((void**)&attnf, g_attn);

    // QKV projections
    sgemm128<<<dim3(NHEADS * HDIM / 128, S_LEN / 128), 256>>>(X, Wq, qtmp, S_LEN, NHEADS * HDIM, HIDDEN);
    sgemm128<<<dim3(NKV * HDIM / 128, S_LEN / 128), 256>>>(X, Wk, ktmp, S_LEN, NKV * HDIM, HIDDEN);
    sgemm128<<<dim3(NKV * HDIM / 128, S_LEN / 128), 256>>>(X, Wv, vtmp, S_LEN, NKV * HDIM, HIDDEN);

    // RMSNorm + RoPE (k written directly into d_out's new_k region)
    norm_rope_kernel<<<dim3(S_LEN, NHEADS), 128>>>(qtmp, qw, qheads, NHEADS);
    norm_rope_kernel<<<dim3(S_LEN, NKV), 128>>>(ktmp, kw, new_k, NKV);

    // V transpose into d_out's new_v region
    {
        int total = S_LEN * NKV * HDIM;
        v_transpose_kernel<<<(total + 255) / 256, 256>>>(vtmp, new_v);
    }

    // Attention (reads new_k/new_v from d_out, writes probs + attn scratch)
    cudaFuncSetAttribute(attention_kernel,
                         cudaFuncAttributeMaxDynamicSharedMemorySize, ATT_SMEM_BYTES);
    attention_kernel<<<dim3(S_LEN / 128, NHEADS), 256, ATT_SMEM_BYTES>>>(
        qheads, new_k, new_v, probs, attnf);

    // O projection
    sgemm128<<<dim3(HIDDEN / 128, S_LEN / 128), 256>>>(attnf, Wo, out, S_LEN, HIDDEN, HIDDEN);
}

// round 4
// speedup vs baseline: 1.5275x; 1.5275x over previous
#include <cuda_runtime.h>
#include <cuda_bf16.h>
#include <math.h>
#include <stdint.h>

// ---------------------------------------------------------------------------
// Problem constants
// ---------------------------------------------------------------------------
#define S_LEN   2048
#define HIDDEN  4096
#define NHEADS  32
#define NKV     8
#define HDIM    128

// ---------------------------------------------------------------------------
// Device scratch
// ---------------------------------------------------------------------------
__device__ float g_qtmp[S_LEN * NHEADS * HDIM];
__device__ float g_ktmp[S_LEN * NKV * HDIM];
__device__ float g_vtmp[S_LEN * NKV * HDIM];
__device__ float g_qheads[NHEADS * S_LEN * HDIM];

__device__ __nv_bfloat16 g_xhi[S_LEN * HIDDEN];
__device__ __nv_bfloat16 g_xlo[S_LEN * HIDDEN];
__device__ __nv_bfloat16 g_ahi[S_LEN * HIDDEN];
__device__ __nv_bfloat16 g_alo[S_LEN * HIDDEN];
__device__ __nv_bfloat16 g_wqthi[HIDDEN * HIDDEN];
__device__ __nv_bfloat16 g_wqtlo[HIDDEN * HIDDEN];
__device__ __nv_bfloat16 g_wkthi[(NKV * HDIM) * HIDDEN];
__device__ __nv_bfloat16 g_wktlo[(NKV * HDIM) * HIDDEN];
__device__ __nv_bfloat16 g_wvthi[(NKV * HDIM) * HIDDEN];
__device__ __nv_bfloat16 g_wvtlo[(NKV * HDIM) * HIDDEN];
__device__ __nv_bfloat16 g_wothi[HIDDEN * HIDDEN];
__device__ __nv_bfloat16 g_wotlo[HIDDEN * HIDDEN];

// ---------------------------------------------------------------------------
// Low-level helpers (base-ISA only: cp.async / ldmatrix / mma.sync)
// ---------------------------------------------------------------------------
__device__ __forceinline__ uint32_t smem_to_u32(const void* p) {
    uint32_t a;
    asm("{ .reg .u64 t; cvta.to.shared.u64 t, %1; cvt.u32.u64 %0, t; }"
        : "=r"(a) : "l"(p));
    return a;
}
__device__ __forceinline__ void cpasync16(uint32_t saddr, const void* g) {
    asm volatile("cp.async.cg.shared.global [%0], [%1], 16;"
                 :: "r"(saddr), "l"(g));
}
#define CP_COMMIT() asm volatile("cp.async.commit_group;" ::: "memory")
#define CP_WAIT(n)  asm volatile("cp.async.wait_group %0;" :: "n"(n) : "memory")

__device__ __forceinline__ void ldsm_x4(uint32_t addr, uint32_t r[4]) {
    asm volatile("ldmatrix.sync.aligned.m8n8.x4.shared.b16 {%0,%1,%2,%3}, [%4];"
        : "=r"(r[0]), "=r"(r[1]), "=r"(r[2]), "=r"(r[3]) : "r"(addr));
}
__device__ __forceinline__ void mma16816(float d[4], const uint32_t a[4],
                                         const uint32_t b0, const uint32_t b1) {
    asm volatile(
        "mma.sync.aligned.m16n8k16.row.col.f32.bf16.bf16.f32 "
        "{%0,%1,%2,%3}, {%4,%5,%6,%7}, {%8,%9}, {%0,%1,%2,%3};"
        : "+f"(d[0]), "+f"(d[1]), "+f"(d[2]), "+f"(d[3])
        : "r"(a[0]), "r"(a[1]), "r"(a[2]), "r"(a[3]), "r"(b0), "r"(b1));
}

// ---------------------------------------------------------------------------
// Tensor-core GEMM via mma.sync:
//   C[M, Ntot] = A[M,4096] @ B^T,  B stored [Ntot][4096], bf16 hi/lo splits.
//   3-term: Ah*Bh + Al*Bh + Ah*Bl, fp32 accum.
//   CTA 128x128, BK=32, 256 threads (8 warps, 2x4, warp tile 64x32),
//   2-stage cp.async pipeline, smem pitch 40 bf16 (80B, ldmatrix conflict-free)
// ---------------------------------------------------------------------------
#define SPITCH      40
#define TILE_ELEMS  (128 * SPITCH)          // 5120 bf16
#define STAGE_ELEMS (4 * TILE_ELEMS)        // Ah,Al,Bh,Bl
#define GEMM_SMEM_BYTES (2 * STAGE_ELEMS * 2)  // 81920 B
#define NCHUNKS     (HIDDEN / 32)           // 128

__global__ __launch_bounds__(256) void gemm_mma(
    const __nv_bfloat16* __restrict__ Ahi, const __nv_bfloat16* __restrict__ Alo,
    const __nv_bfloat16* __restrict__ Bhi, const __nv_bfloat16* __restrict__ Blo,
    float* __restrict__ C, int Ntot) {
    extern __shared__ __align__(16) __nv_bfloat16 smbuf[];
    const uint32_t sb = smem_to_u32(smbuf);
    const int tid  = threadIdx.x;
    const int lane = tid & 31;
    const int wid  = tid >> 5;
    const int m0 = blockIdx.y * 128;
    const int n0 = blockIdx.x * 128;
    const int wm = (wid >> 2) * 64;
    const int wn = (wid & 3) * 32;
    const int quad = lane >> 3;
    const int wi   = lane & 7;

    // cp.async chunk mapping (2 chunks of 16B per tile per thread)
    const int r0c = tid >> 1;                 // unused placeholder removal-safe
    (void)r0c;

    float acc[4][4][4];
#pragma unroll
    for (int mt = 0; mt < 4; mt++)
#pragma unroll
        for (int nt = 0; nt < 4; nt++)
#pragma unroll
            for (int q = 0; q < 4; q++) acc[mt][nt][q] = 0.f;

    // ---- stage loader ----
    auto load_stage = [&](int buf, int chunk) {
        const int k0 = chunk * 32;
        const uint32_t sbase = sb + (uint32_t)buf * STAGE_ELEMS * 2;
#pragma unroll
        for (int t = 0; t < 2; t++) {
            int c = tid + t * 256;            // 0..511
            int row = c >> 2;
            int kc  = (c & 3) * 8;
            uint32_t so = sbase + (uint32_t)(row * SPITCH + kc) * 2;
            size_t goA = (size_t)(m0 + row) * HIDDEN + k0 + kc;
            size_t goB = (size_t)(n0 + row) * HIDDEN + k0 + kc;
            cpasync16(so,                      Ahi + goA);
            cpasync16(so + TILE_ELEMS * 2,     Alo + goA);
            cpasync16(so + 2 * TILE_ELEMS * 2, Bhi + goB);
            cpasync16(so + 3 * TILE_ELEMS * 2, Blo + goB);
        }
    };

    load_stage(0, 0);
    CP_COMMIT();

    for (int chunk = 0; chunk < NCHUNKS; chunk++) {
        if (chunk + 1 < NCHUNKS) {
            load_stage((chunk + 1) & 1, chunk + 1);
            CP_COMMIT();
            CP_WAIT(1);
        } else {
            CP_WAIT(0);
        }
        __syncthreads();

        const uint32_t stage = sb + (uint32_t)(chunk & 1) * STAGE_ELEMS * 2;
        // a-frag address offsets within tile
        const int arow = (quad & 1) * 8 + wi;
        const int acol = (quad >> 1) * 8;
        const int brow = (quad >> 1) * 8 + wi;
        const int bcol = (quad & 1) * 8;

#pragma unroll
        for (int term = 0; term < 3; term++) {
            const uint32_t aT = stage + (term == 1 ? TILE_ELEMS * 2 : 0);
            const uint32_t bT = stage + 2 * TILE_ELEMS * 2 +
                                (term == 2 ? TILE_ELEMS * 2 : 0);
#pragma unroll
            for (int kk = 0; kk < 2; kk++) {
                uint32_t a[4][4], b[2][4];
#pragma unroll
                for (int mt = 0; mt < 4; mt++) {
                    int r = wm + mt * 16 + arow;
                    int cc = kk * 16 + acol;
                    ldsm_x4(aT + (uint32_t)(r * SPITCH + cc) * 2, a[mt]);
                }
#pragma unroll
                for (int nt2 = 0; nt2 < 2; nt2++) {
                    int r = wn + nt2 * 16 + brow;
                    int cc = kk * 16 + bcol;
                    ldsm_x4(bT + (uint32_t)(r * SPITCH + cc) * 2, b[nt2]);
                }
#pragma unroll
                for (int mt = 0; mt < 4; mt++)
#pragma unroll
                    for (int nt = 0; nt < 4; nt++)
                        mma16816(acc[mt][nt], a[mt],
                                 b[nt >> 1][(nt & 1) * 2],
                                 b[nt >> 1][(nt & 1) * 2 + 1]);
            }
        }
        __syncthreads();
    }

    // ---- epilogue ----
    const int erow = lane >> 2;
    const int ecol = (lane & 3) * 2;
#pragma unroll
    for (int mt = 0; mt < 4; mt++) {
#pragma unroll
        for (int nt = 0; nt < 4; nt++) {
            int r = m0 + wm + mt * 16 + erow;
            int c = n0 + wn + nt * 8 + ecol;
            *(float2*)&C[(size_t)r * Ntot + c] =
                make_float2(acc[mt][nt][0], acc[mt][nt][1]);
            *(float2*)&C[(size_t)(r + 8) * Ntot + c] =
                make_float2(acc[mt][nt][2], acc[mt][nt][3]);
        }
    }
}

// ---------------------------------------------------------------------------
// f32 -> bf16 hi/lo split
// ---------------------------------------------------------------------------
__global__ void split_kernel(const float* __restrict__ x,
                             __nv_bfloat16* __restrict__ hi,
                             __nv_bfloat16* __restrict__ lo, int n) {
    int i = blockIdx.x * 256 + threadIdx.x;
    if (i >= n) return;
    float v = x[i];
    __nv_bfloat16 h = __float2bfloat16(v);
    hi[i] = h;
    lo[i] = __float2bfloat16(v - __bfloat162float(h));
}

// ---------------------------------------------------------------------------
// W [K=4096][N] f32 -> W^T hi/lo [N][4096] bf16
// ---------------------------------------------------------------------------
__global__ __launch_bounds__(256) void transpose_split(
    const float* __restrict__ W, __nv_bfloat16* __restrict__ hi,
    __nv_bfloat16* __restrict__ lo, int N) {
    __shared__ float t[32][33];
    const int n0 = blockIdx.x * 32;
    const int k0 = blockIdx.y * 32;
    const int tx = threadIdx.x;
    for (int r = threadIdx.y; r < 32; r += 8)
        t[r][tx] = W[(size_t)(k0 + r) * N + n0 + tx];
    __syncthreads();
    for (int r = threadIdx.y; r < 32; r += 8) {
        float v = t[tx][r];
        __nv_bfloat16 h = __float2bfloat16(v);
        size_t o = (size_t)(n0 + r) * HIDDEN + k0 + tx;
        hi[o] = h;
        lo[o] = __float2bfloat16(v - __bfloat162float(h));
    }
}

// ---------------------------------------------------------------------------
// RMSNorm + RoPE (position = s, since position_ids = arange)
// ---------------------------------------------------------------------------
__global__ __launch_bounds__(128) void norm_rope_kernel(
    const float* __restrict__ inp, const float* __restrict__ w,
    float* __restrict__ out, int H) {
    const int s = blockIdx.x;
    const int h = blockIdx.y;
    const int d = threadIdx.x;

    float x = inp[((size_t)s * H + h) * HDIM + d];
    float ss = x * x;
#pragma unroll
    for (int o = 16; o; o >>= 1) ss += __shfl_xor_sync(0xffffffffu, ss, o);

    __shared__ float wss[4];
    __shared__ float xs[HDIM];
    if ((d & 31) == 0) wss[d >> 5] = ss;
    __syncthreads();
    float var = (wss[0] + wss[1] + wss[2] + wss[3]) * (1.0f / 128.0f);
    float xn = x * rsqrtf(var + 1e-6f) * w[d];
    xs[d] = xn;
    __syncthreads();

    if (d < 64) {
        float p = (float)s;
        float e = (float)(2 * d) * (1.0f / 128.0f);
        float invf = powf(1000000.0f, -e);
        float f = p * invf;
        float si, c;
        sincosf(f, &si, &c);
        float x1 = xs[d], x2 = xs[d + 64];
        size_t base = ((size_t)h * S_LEN + s) * HDIM;
        out[base + d]      = x1 * c - x2 * si;
        out[base + d + 64] = x2 * c + x1 * si;
    }
}

// ---------------------------------------------------------------------------
// V transpose: [s][kv*128+d] -> [kv][s][d]
// ---------------------------------------------------------------------------
__global__ void v_transpose_kernel(const float* __restrict__ vt,
                                   float* __restrict__ out) {
    size_t i = (size_t)blockIdx.x * blockDim.x + threadIdx.x;
    if (i >= (size_t)S_LEN * NKV * HDIM) return;
    int s  = (int)(i >> 10);
    int c  = (int)(i & 1023);
    int kv = c >> 7;
    int d  = c & 127;
    out[((size_t)kv * S_LEN + s) * HDIM + d] = vt[i];
}

// ---------------------------------------------------------------------------
// Attention (SIMT two-pass fp32) — epilogue writes bf16 hi/lo splits
// ---------------------------------------------------------------------------
#define ATT_SMEM_FLOATS (128 * 128 + 128 * 64 + 64 * 128 + 128 * 68)
#define ATT_SMEM_BYTES  (ATT_SMEM_FLOATS * 4)

__global__ __launch_bounds__(256) void attention_kernel(
    const float* __restrict__ Q, const float* __restrict__ Kc,
    const float* __restrict__ Vc, float* __restrict__ probs,
    __nv_bfloat16* __restrict__ ahi, __nv_bfloat16* __restrict__ alo) {
    extern __shared__ float sm[];
    float* Qs = sm;
    float* Ks = Qs + 128 * 128;
    float* Vs = Ks + 128 * 64;
    float* Ps = Vs + 64 * 128;

    const int h   = blockIdx.y;
    const int q0  = blockIdx.x * 128;
    const int kvh = h >> 2;
    const int tid = threadIdx.x;
    const int tx  = tid & 15;
    const int ty  = tid >> 4;
    const float scale = 0.08838834764831845f;

    {
        const int r0 = tid >> 5;
        const int dd = (tid & 31) * 4;
#pragma unroll
        for (int rr = 0; rr < 16; rr++) {
            int r = r0 + rr * 8;
            float4 q4 = *(const float4*)&Q[((size_t)h * S_LEN + (q0 + r)) * HDIM + dd];
            Qs[(dd + 0) * 128 + r] = q4.x * scale;
            Qs[(dd + 1) * 128 + r] = q4.y * scale;
            Qs[(dd + 2) * 128 + r] = q4.z * scale;
            Qs[(dd + 3) * 128 + r] = q4.w * scale;
        }
    }

    float m[8], l[8];
#pragma unroll
    for (int i = 0; i < 8; i++) { m[i] = -1e30f; l[i] = 0.f; }
    const int row_last = q0 + 127;
    const int nvalid = (row_last >> 6) + 1;
    __syncthreads();

    for (int jt = 0; jt < nvalid; jt++) {
        const int c0 = jt * 64;
        {
            const int dd = (tid & 31) * 4;
#pragma unroll
            for (int rr = 0; rr < 8; rr++) {
                int c = (tid >> 5) + rr * 8;
                float4 k4 = *(const float4*)&Kc[((size_t)kvh * S_LEN + (c0 + c)) * HDIM + dd];
                Ks[(dd + 0) * 64 + c] = k4.x;
                Ks[(dd + 1) * 64 + c] = k4.y;
                Ks[(dd + 2) * 64 + c] = k4.z;
                Ks[(dd + 3) * 64 + c] = k4.w;
            }
        }
        __syncthreads();

        float sreg[8][4];
#pragma unroll
        for (int i = 0; i < 8; i++)
#pragma unroll
            for (int j = 0; j < 4; j++) sreg[i][j] = 0.f;

        for (int d = 0; d < 128; d++) {
            float rq[8], rk[4];
            *(float4*)&rq[0] = *(const float4*)&Qs[d * 128 + ty * 8];
            *(float4*)&rq[4] = *(const float4*)&Qs[d * 128 + ty * 8 + 4];
            *(float4*)&rk[0] = *(const float4*)&Ks[d * 64 + tx * 4];
#pragma unroll
            for (int i = 0; i < 8; i++)
#pragma unroll
                for (int j = 0; j < 4; j++)
                    sreg[i][j] = fmaf(rq[i], rk[j], sreg[i][j]);
        }

#pragma unroll
        for (int i = 0; i < 8; i++) {
            int grow = q0 + ty * 8 + i;
            float tmax = -1e30f;
#pragma unroll
            for (int j = 0; j < 4; j++) {
                if (c0 + tx * 4 + j > grow) sreg[i][j] = -1e30f;
                tmax = fmaxf(tmax, sreg[i][j]);
            }
#pragma unroll
            for (int o = 8; o; o >>= 1)
                tmax = fmaxf(tmax, __shfl_xor_sync(0xffffffffu, tmax, o));
            float mn = fmaxf(m[i], tmax);
            float corr = __expf(m[i] - mn);
            float ssum = 0.f;
#pragma unroll
            for (int j = 0; j < 4; j++) ssum += __expf(sreg[i][j] - mn);
#pragma unroll
            for (int o = 8; o; o >>= 1)
                ssum += __shfl_xor_sync(0xffffffffu, ssum, o);
            l[i] = l[i] * corr + ssum;
            m[i] = mn;
        }
        __syncthreads();
    }

    float linv[8];
#pragma unroll
    for (int i = 0; i < 8; i++) linv[i] = 1.0f / l[i];

    float acc[8][8];
#pragma unroll
    for (int i = 0; i < 8; i++)
#pragma unroll
        for (int j = 0; j < 8; j++) acc[i][j] = 0.f;

    for (int jt = 0; jt < S_LEN / 64; jt++) {
        const int c0 = jt * 64;
        if (c0 > row_last) {
            float4 z = make_float4(0.f, 0.f, 0.f, 0.f);
#pragma unroll
            for (int i = 0; i < 8; i++) {
                int grow = q0 + ty * 8 + i;
                *(float4*)&probs[((size_t)h * S_LEN + grow) * S_LEN + c0 + tx * 4] = z;
            }
            continue;
        }
        {
            const int dd = (tid & 31) * 4;
#pragma unroll
            for (int rr = 0; rr < 8; rr++) {
                int c = (tid >> 5) + rr * 8;
                size_t gk = ((size_t)kvh * S_LEN + (c0 + c)) * HDIM + dd;
                float4 k4 = *(const float4*)&Kc[gk];
                Ks[(dd + 0) * 64 + c] = k4.x;
                Ks[(dd + 1) * 64 + c] = k4.y;
                Ks[(dd + 2) * 64 + c] = k4.z;
                Ks[(dd + 3) * 64 + c] = k4.w;
                *(float4*)&Vs[c * 128 + dd] = *(const float4*)&Vc[gk];
            }
        }
        __syncthreads();

        float sreg[8][4];
#pragma unroll
        for (int i = 0; i < 8; i++)
#pragma unroll
            for (int j = 0; j < 4; j++) sreg[i][j] = 0.f;

        for (int d = 0; d < 128; d++) {
            float rq[8], rk[4];
            *(float4*)&rq[0] = *(const float4*)&Qs[d * 128 + ty * 8];
            *(float4*)&rq[4] = *(const float4*)&Qs[d * 128 + ty * 8 + 4];
            *(float4*)&rk[0] = *(const float4*)&Ks[d * 64 + tx * 4];
#pragma unroll
            for (int i = 0; i < 8; i++)
#pragma unroll
                for (int j = 0; j < 4; j++)
                    sreg[i][j] = fmaf(rq[i], rk[j], sreg[i][j]);
        }

#pragma unroll
        for (int i = 0; i < 8; i++) {
            int grow = q0 + ty * 8 + i;
            float p[4];
#pragma unroll
            for (int j = 0; j < 4; j++) {
                float sv = (c0 + tx * 4 + j > grow) ? -1e30f : sreg[i][j];
                p[j] = __expf(sv - m[i]) * linv[i];
            }
            *(float4*)&Ps[(ty * 8 + i) * 68 + tx * 4] = *(float4*)p;
            *(float4*)&probs[((size_t)h * S_LEN + grow) * S_LEN + c0 + tx * 4] = *(float4*)p;
        }
        __syncthreads();

        for (int kk = 0; kk < 64; kk++) {
            float rv[8];
            *(float4*)&rv[0] = *(const float4*)&Vs[kk * 128 + tx * 8];
            *(float4*)&rv[4] = *(const float4*)&Vs[kk * 128 + tx * 8 + 4];
#pragma unroll
            for (int i = 0; i < 8; i++) {
                float rp = Ps[(ty * 8 + i) * 68 + kk];
#pragma unroll
                for (int j = 0; j < 8; j++)
                    acc[i][j] = fmaf(rp, rv[j], acc[i][j]);
            }
        }
        __syncthreads();
    }

#pragma unroll
    for (int i = 0; i < 8; i++) {
        size_t base = (size_t)(q0 + ty * 8 + i) * HIDDEN + h * HDIM + tx * 8;
#pragma unroll
        for (int j = 0; j < 8; j += 2) {
            float v0 = acc[i][j], v1 = acc[i][j + 1];
            __nv_bfloat16 h0 = __float2bfloat16(v0);
            __nv_bfloat16 h1 = __float2bfloat16(v1);
            __nv_bfloat162 hp; hp.x = h0; hp.y = h1;
            __nv_bfloat162 lp;
            lp.x = __float2bfloat16(v0 - __bfloat162float(h0));
            lp.y = __float2bfloat16(v1 - __bfloat162float(h1));
            *(__nv_bfloat162*)&ahi[base + j] = hp;
            *(__nv_bfloat162*)&alo[base + j] = lp;
        }
    }
}

// ---------------------------------------------------------------------------
// Launch
// ---------------------------------------------------------------------------
extern "C" void kernel_launch(void* const* d_in, const int* in_sizes, int n_in,
                              void* d_out, int out_size) {
    const float* X  = (const float*)d_in[0];
    const float* Wq = (const float*)d_in[2];
    const float* Wk = (const float*)d_in[3];
    const float* Wv = (const float*)d_in[4];
    const float* Wo = (const float*)d_in[5];
    const float* qw = (const float*)d_in[6];
    const float* kw = (const float*)d_in[7];

    float* out   = (float*)d_out;
    float* new_k = out + (size_t)S_LEN * HIDDEN;
    float* new_v = new_k + (size_t)NKV * S_LEN * HDIM;
    float* probs = new_v + (size_t)NKV * S_LEN * HDIM;

    float *qtmp, *ktmp, *vtmp, *qheads;
    __nv_bfloat16 *xhi, *xlo, *ahi, *alo;
    __nv_bfloat16 *wqh, *wql, *wkh, *wkl, *wvh, *wvl, *woh, *wol;
    cudaGetSymbolAddress((void**)&qtmp, g_qtmp);
    cudaGetSymbolAddress((void**)&ktmp, g_ktmp);
    cudaGetSymbolAddress((void**)&vtmp, g_vtmp);
    cudaGetSymbolAddress((void**)&qheads, g_qheads);
    cudaGetSymbolAddress((void**)&xhi, g_xhi);
    cudaGetSymbolAddress((void**)&xlo, g_xlo);
    cudaGetSymbolAddress((void**)&ahi, g_ahi);
    cudaGetSymbolAddress((void**)&alo, g_alo);
    cudaGetSymbolAddress((void**)&wqh, g_wqthi);
    cudaGetSymbolAddress((void**)&wql, g_wqtlo);
    cudaGetSymbolAddress((void**)&wkh, g_wkthi);
    cudaGetSymbolAddress((void**)&wkl, g_wktlo);
    cudaGetSymbolAddress((void**)&wvh, g_wvthi);
    cudaGetSymbolAddress((void**)&wvl, g_wvtlo);
    cudaGetSymbolAddress((void**)&woh, g_wothi);
    cudaGetSymbolAddress((void**)&wol, g_wotlo);

    // ---- conversions ----
    {
        int n = S_LEN * HIDDEN;
        split_kernel<<<(n + 255) / 256, 256>>>(X, xhi, xlo, n);
    }
    transpose_split<<<dim3(HIDDEN / 32, HIDDEN / 32), dim3(32, 8)>>>(Wq, wqh, wql, HIDDEN);
    transpose_split<<<dim3((NKV * HDIM) / 32, HIDDEN / 32), dim3(32, 8)>>>(Wk, wkh, wkl, NKV * HDIM);
    transpose_split<<<dim3((NKV * HDIM) / 32, HIDDEN / 32), dim3(32, 8)>>>(Wv, wvh, wvl, NKV * HDIM);
    transpose_split<<<dim3(HIDDEN / 32, HIDDEN / 32), dim3(32, 8)>>>(Wo, woh, wol, HIDDEN);

    // ---- projections on tensor cores (mma.sync) ----
    cudaFuncSetAttribute(gemm_mma, cudaFuncAttributeMaxDynamicSharedMemorySize,
                         GEMM_SMEM_BYTES);
    gemm_mma<<<dim3(HIDDEN / 128, S_LEN / 128), 256, GEMM_SMEM_BYTES>>>(
        xhi, xlo, wqh, wql, qtmp, HIDDEN);
    gemm_mma<<<dim3((NKV * HDIM) / 128, S_LEN / 128), 256, GEMM_SMEM_BYTES>>>(
        xhi, xlo, wkh, wkl, ktmp, NKV * HDIM);
    gemm_mma<<<dim3((NKV * HDIM) / 128, S_LEN / 128), 256, GEMM_SMEM_BYTES>>>(
        xhi, xlo, wvh, wvl, vtmp, NKV * HDIM);

    // ---- RMSNorm + RoPE ----
    norm_rope_kernel<<<dim3(S_LEN, NHEADS), 128>>>(qtmp, qw, qheads, NHEADS);
    norm_rope_kernel<<<dim3(S_LEN, NKV), 128>>>(ktmp, kw, new_k, NKV);

    // ---- V transpose ----
    {
        int total = S_LEN * NKV * HDIM;
        v_transpose_kernel<<<(total + 255) / 256, 256>>>(vtmp, new_v);
    }

    // ---- attention ----
    cudaFuncSetAttribute(attention_kernel,
                         cudaFuncAttributeMaxDynamicSharedMemorySize, ATT_SMEM_BYTES);
    attention_kernel<<<dim3(S_LEN / 128, NHEADS), 256, ATT_SMEM_BYTES>>>(
        qheads, new_k, new_v, probs, ahi, alo);

    // ---- O projection ----
    gemm_mma<<<dim3(HIDDEN / 128, S_LEN / 128), 256, GEMM_SMEM_BYTES>>>(
        ahi, alo, woh, wol, out, HIDDEN);
}

// round 5
// speedup vs baseline: 2.6110x; 1.7094x over previous
#include <cuda_runtime.h>
#include <cuda_bf16.h>
#include <math.h>
#include <stdint.h>

// ---------------------------------------------------------------------------
// Problem constants
// ---------------------------------------------------------------------------
#define S_LEN   2048
#define HIDDEN  4096
#define NHEADS  32
#define NKV     8
#define HDIM    128

// ---------------------------------------------------------------------------
// Device scratch
// ---------------------------------------------------------------------------
__device__ float g_qtmp[S_LEN * NHEADS * HDIM];
__device__ float g_ktmp[S_LEN * NKV * HDIM];
__device__ float g_vtmp[S_LEN * NKV * HDIM];

__device__ __nv_bfloat16 g_xhi[S_LEN * HIDDEN];
__device__ __nv_bfloat16 g_xlo[S_LEN * HIDDEN];
__device__ __nv_bfloat16 g_ahi[S_LEN * HIDDEN];
__device__ __nv_bfloat16 g_alo[S_LEN * HIDDEN];
__device__ __nv_bfloat16 g_qhi[NHEADS * S_LEN * HDIM];   // [h][s][d], pre-scaled
__device__ __nv_bfloat16 g_qlo[NHEADS * S_LEN * HDIM];
__device__ __nv_bfloat16 g_khi[NKV * S_LEN * HDIM];      // [kv][s][d]
__device__ __nv_bfloat16 g_klo[NKV * S_LEN * HDIM];
__device__ __nv_bfloat16 g_vthi[NKV * HDIM * S_LEN];     // [kv][d][s]
__device__ __nv_bfloat16 g_vtlo[NKV * HDIM * S_LEN];
__device__ __nv_bfloat16 g_wqthi[HIDDEN * HIDDEN];
__device__ __nv_bfloat16 g_wqtlo[HIDDEN * HIDDEN];
__device__ __nv_bfloat16 g_wkthi[(NKV * HDIM) * HIDDEN];
__device__ __nv_bfloat16 g_wktlo[(NKV * HDIM) * HIDDEN];
__device__ __nv_bfloat16 g_wvthi[(NKV * HDIM) * HIDDEN];
__device__ __nv_bfloat16 g_wvtlo[(NKV * HDIM) * HIDDEN];
__device__ __nv_bfloat16 g_wothi[HIDDEN * HIDDEN];
__device__ __nv_bfloat16 g_wotlo[HIDDEN * HIDDEN];

// ---------------------------------------------------------------------------
// Low-level helpers (base ISA: cp.async / ldmatrix / mma.sync)
// ---------------------------------------------------------------------------
__device__ __forceinline__ uint32_t smem_to_u32(const void* p) {
    uint32_t a;
    asm("{ .reg .u64 t; cvta.to.shared.u64 t, %1; cvt.u32.u64 %0, t; }"
        : "=r"(a) : "l"(p));
    return a;
}
__device__ __forceinline__ void cpasync16(uint32_t saddr, const void* g) {
    asm volatile("cp.async.cg.shared.global [%0], [%1], 16;"
                 :: "r"(saddr), "l"(g));
}
#define CP_COMMIT() asm volatile("cp.async.commit_group;" ::: "memory")
#define CP_WAIT(n)  asm volatile("cp.async.wait_group %0;" :: "n"(n) : "memory")

__device__ __forceinline__ void ldsm_x4(uint32_t addr, uint32_t r[4]) {
    asm volatile("ldmatrix.sync.aligned.m8n8.x4.shared.b16 {%0,%1,%2,%3}, [%4];"
        : "=r"(r[0]), "=r"(r[1]), "=r"(r[2]), "=r"(r[3]) : "r"(addr));
}
__device__ __forceinline__ void mma16816(float d[4], const uint32_t a[4],
                                         const uint32_t b0, const uint32_t b1) {
    asm volatile(
        "mma.sync.aligned.m16n8k16.row.col.f32.bf16.bf16.f32 "
        "{%0,%1,%2,%3}, {%4,%5,%6,%7}, {%8,%9}, {%0,%1,%2,%3};"
        : "+f"(d[0]), "+f"(d[1]), "+f"(d[2]), "+f"(d[3])
        : "r"(a[0]), "r"(a[1]), "r"(a[2]), "r"(a[3]), "r"(b0), "r"(b1));
}

// ---------------------------------------------------------------------------
// Projection GEMM via mma.sync (unchanged from round 4; passing, rel_err 3e-5)
// ---------------------------------------------------------------------------
#define SPITCH      40
#define TILE_ELEMS  (128 * SPITCH)
#define STAGE_ELEMS (4 * TILE_ELEMS)
#define GEMM_SMEM_BYTES (2 * STAGE_ELEMS * 2)
#define NCHUNKS     (HIDDEN / 32)

__global__ __launch_bounds__(256) void gemm_mma(
    const __nv_bfloat16* __restrict__ Ahi, const __nv_bfloat16* __restrict__ Alo,
    const __nv_bfloat16* __restrict__ Bhi, const __nv_bfloat16* __restrict__ Blo,
    float* __restrict__ C, int Ntot) {
    extern __shared__ __align__(16) __nv_bfloat16 smbuf[];
    const uint32_t sb = smem_to_u32(smbuf);
    const int tid  = threadIdx.x;
    const int lane = tid & 31;
    const int wid  = tid >> 5;
    const int m0 = blockIdx.y * 128;
    const int n0 = blockIdx.x * 128;
    const int wm = (wid >> 2) * 64;
    const int wn = (wid & 3) * 32;
    const int quad = lane >> 3;
    const int wi   = lane & 7;

    float acc[4][4][4];
#pragma unroll
    for (int mt = 0; mt < 4; mt++)
#pragma unroll
        for (int nt = 0; nt < 4; nt++)
#pragma unroll
            for (int q = 0; q < 4; q++) acc[mt][nt][q] = 0.f;

    auto load_stage = [&](int buf, int chunk) {
        const int k0 = chunk * 32;
        const uint32_t sbase = sb + (uint32_t)buf * STAGE_ELEMS * 2;
#pragma unroll
        for (int t = 0; t < 2; t++) {
            int c = tid + t * 256;
            int row = c >> 2;
            int kc  = (c & 3) * 8;
            uint32_t so = sbase + (uint32_t)(row * SPITCH + kc) * 2;
            size_t goA = (size_t)(m0 + row) * HIDDEN + k0 + kc;
            size_t goB = (size_t)(n0 + row) * HIDDEN + k0 + kc;
            cpasync16(so,                      Ahi + goA);
            cpasync16(so + TILE_ELEMS * 2,     Alo + goA);
            cpasync16(so + 2 * TILE_ELEMS * 2, Bhi + goB);
            cpasync16(so + 3 * TILE_ELEMS * 2, Blo + goB);
        }
    };

    load_stage(0, 0);
    CP_COMMIT();

    for (int chunk = 0; chunk < NCHUNKS; chunk++) {
        if (chunk + 1 < NCHUNKS) {
            load_stage((chunk + 1) & 1, chunk + 1);
            CP_COMMIT();
            CP_WAIT(1);
        } else {
            CP_WAIT(0);
        }
        __syncthreads();

        const uint32_t stage = sb + (uint32_t)(chunk & 1) * STAGE_ELEMS * 2;
        const int arow = (quad & 1) * 8 + wi;
        const int acol = (quad >> 1) * 8;
        const int brow = (quad >> 1) * 8 + wi;
        const int bcol = (quad & 1) * 8;

#pragma unroll
        for (int term = 0; term < 3; term++) {
            const uint32_t aT = stage + (term == 1 ? TILE_ELEMS * 2 : 0);
            const uint32_t bT = stage + 2 * TILE_ELEMS * 2 +
                                (term == 2 ? TILE_ELEMS * 2 : 0);
#pragma unroll
            for (int kk = 0; kk < 2; kk++) {
                uint32_t a[4][4], b[2][4];
#pragma unroll
                for (int mt = 0; mt < 4; mt++) {
                    int r = wm + mt * 16 + arow;
                    int cc = kk * 16 + acol;
                    ldsm_x4(aT + (uint32_t)(r * SPITCH + cc) * 2, a[mt]);
                }
#pragma unroll
                for (int nt2 = 0; nt2 < 2; nt2++) {
                    int r = wn + nt2 * 16 + brow;
                    int cc = kk * 16 + bcol;
                    ldsm_x4(bT + (uint32_t)(r * SPITCH + cc) * 2, b[nt2]);
                }
#pragma unroll
                for (int mt = 0; mt < 4; mt++)
#pragma unroll
                    for (int nt = 0; nt < 4; nt++)
                        mma16816(acc[mt][nt], a[mt],
                                 b[nt >> 1][(nt & 1) * 2],
                                 b[nt >> 1][(nt & 1) * 2 + 1]);
            }
        }
        __syncthreads();
    }

    const int erow = lane >> 2;
    const int ecol = (lane & 3) * 2;
#pragma unroll
    for (int mt = 0; mt < 4; mt++) {
#pragma unroll
        for (int nt = 0; nt < 4; nt++) {
            int r = m0 + wm + mt * 16 + erow;
            int c = n0 + wn + nt * 8 + ecol;
            *(float2*)&C[(size_t)r * Ntot + c] =
                make_float2(acc[mt][nt][0], acc[mt][nt][1]);
            *(float2*)&C[(size_t)(r + 8) * Ntot + c] =
                make_float2(acc[mt][nt][2], acc[mt][nt][3]);
        }
    }
}

// ---------------------------------------------------------------------------
// f32 -> bf16 hi/lo split
// ---------------------------------------------------------------------------
__global__ void split_kernel(const float* __restrict__ x,
                             __nv_bfloat16* __restrict__ hi,
                             __nv_bfloat16* __restrict__ lo, int n) {
    int i = blockIdx.x * 256 + threadIdx.x;
    if (i >= n) return;
    float v = x[i];
    __nv_bfloat16 h = __float2bfloat16(v);
    hi[i] = h;
    lo[i] = __float2bfloat16(v - __bfloat162float(h));
}

// ---------------------------------------------------------------------------
// W [K=4096][N] f32 -> W^T hi/lo [N][4096] bf16
// ---------------------------------------------------------------------------
__global__ __launch_bounds__(256) void transpose_split(
    const float* __restrict__ W, __nv_bfloat16* __restrict__ hi,
    __nv_bfloat16* __restrict__ lo, int N) {
    __shared__ float t[32][33];
    const int n0 = blockIdx.x * 32;
    const int k0 = blockIdx.y * 32;
    const int tx = threadIdx.x;
    for (int r = threadIdx.y; r < 32; r += 8)
        t[r][tx] = W[(size_t)(k0 + r) * N + n0 + tx];
    __syncthreads();
    for (int r = threadIdx.y; r < 32; r += 8) {
        float v = t[tx][r];
        __nv_bfloat16 h = __float2bfloat16(v);
        size_t o = (size_t)(n0 + r) * HIDDEN + k0 + tx;
        hi[o] = h;
        lo[o] = __float2bfloat16(v - __bfloat162float(h));
    }
}

// ---------------------------------------------------------------------------
// RMSNorm + RoPE for Q: writes pre-scaled bf16 hi/lo splits [h][s][d]
// ---------------------------------------------------------------------------
__global__ __launch_bounds__(128) void norm_rope_q(
    const float* __restrict__ inp, const float* __restrict__ w,
    __nv_bfloat16* __restrict__ qhi, __nv_bfloat16* __restrict__ qlo) {
    const int s = blockIdx.x;
    const int h = blockIdx.y;
    const int d = threadIdx.x;

    float x = inp[((size_t)s * NHEADS + h) * HDIM + d];
    float ss = x * x;
#pragma unroll
    for (int o = 16; o; o >>= 1) ss += __shfl_xor_sync(0xffffffffu, ss, o);
    __shared__ float wss[4];
    __shared__ float xs[HDIM];
    if ((d & 31) == 0) wss[d >> 5] = ss;
    __syncthreads();
    float var = (wss[0] + wss[1] + wss[2] + wss[3]) * (1.0f / 128.0f);
    xs[d] = x * rsqrtf(var + 1e-6f) * w[d];
    __syncthreads();

    if (d < 64) {
        const float scale = 0.08838834764831845f;
        float p = (float)s;
        float e = (float)(2 * d) * (1.0f / 128.0f);
        float invf = powf(1000000.0f, -e);
        float si, c;
        sincosf(p * invf, &si, &c);
        float x1 = xs[d], x2 = xs[d + 64];
        float r1 = (x1 * c - x2 * si) * scale;
        float r2 = (x2 * c + x1 * si) * scale;
        size_t base = ((size_t)h * S_LEN + s) * HDIM;
        __nv_bfloat16 h1 = __float2bfloat16(r1);
        __nv_bfloat16 h2 = __float2bfloat16(r2);
        qhi[base + d]      = h1;
        qhi[base + d + 64] = h2;
        qlo[base + d]      = __float2bfloat16(r1 - __bfloat162float(h1));
        qlo[base + d + 64] = __float2bfloat16(r2 - __bfloat162float(h2));
    }
}

// ---------------------------------------------------------------------------
// RMSNorm + RoPE for K: writes f32 new_k [kv][s][d] + bf16 hi/lo splits
// ---------------------------------------------------------------------------
__global__ __launch_bounds__(128) void norm_rope_k(
    const float* __restrict__ inp, const float* __restrict__ w,
    float* __restrict__ outf,
    __nv_bfloat16* __restrict__ khi, __nv_bfloat16* __restrict__ klo) {
    const int s = blockIdx.x;
    const int h = blockIdx.y;
    const int d = threadIdx.x;

    float x = inp[((size_t)s * NKV + h) * HDIM + d];
    float ss = x * x;
#pragma unroll
    for (int o = 16; o; o >>= 1) ss += __shfl_xor_sync(0xffffffffu, ss, o);
    __shared__ float wss[4];
    __shared__ float xs[HDIM];
    if ((d & 31) == 0) wss[d >> 5] = ss;
    __syncthreads();
    float var = (wss[0] + wss[1] + wss[2] + wss[3]) * (1.0f / 128.0f);
    xs[d] = x * rsqrtf(var + 1e-6f) * w[d];
    __syncthreads();

    if (d < 64) {
        float p = (float)s;
        float e = (float)(2 * d) * (1.0f / 128.0f);
        float invf = powf(1000000.0f, -e);
        float si, c;
        sincosf(p * invf, &si, &c);
        float x1 = xs[d], x2 = xs[d + 64];
        float r1 = x1 * c - x2 * si;
        float r2 = x2 * c + x1 * si;
        size_t base = ((size_t)h * S_LEN + s) * HDIM;
        outf[base + d]      = r1;
        outf[base + d + 64] = r2;
        __nv_bfloat16 h1 = __float2bfloat16(r1);
        __nv_bfloat16 h2 = __float2bfloat16(r2);
        khi[base + d]      = h1;
        khi[base + d + 64] = h2;
        klo[base + d]      = __float2bfloat16(r1 - __bfloat162float(h1));
        klo[base + d + 64] = __float2bfloat16(r2 - __bfloat162float(h2));
    }
}

// ---------------------------------------------------------------------------
// V: [s][kv*128+d] -> new_v f32 [kv][s][d]  +  V^T splits [kv][d][s] bf16
// grid (S/32, 128/32, 8), block (32,8)
// ---------------------------------------------------------------------------
__global__ __launch_bounds__(256) void v_split_transpose(
    const float* __restrict__ vt, float* __restrict__ outf,
    __nv_bfloat16* __restrict__ vthi, __nv_bfloat16* __restrict__ vtlo) {
    __shared__ float t[32][33];
    const int kv = blockIdx.z;
    const int s0 = blockIdx.x * 32;
    const int d0 = blockIdx.y * 32;
    const int tx = threadIdx.x;
    for (int r = threadIdx.y; r < 32; r += 8) {
        float v = vt[(size_t)(s0 + r) * (NKV * HDIM) + kv * HDIM + d0 + tx];
        t[r][tx] = v;
        outf[((size_t)kv * S_LEN + s0 + r) * HDIM + d0 + tx] = v;
    }
    __syncthreads();
    for (int r = threadIdx.y; r < 32; r += 8) {
        float v = t[tx][r];   // [s=s0+tx][d=d0+r]
        __nv_bfloat16 h = __float2bfloat16(v);
        size_t o = ((size_t)kv * HDIM + d0 + r) * S_LEN + s0 + tx;
        vthi[o] = h;
        vtlo[o] = __float2bfloat16(v - __bfloat162float(h));
    }
}

// ---------------------------------------------------------------------------
// Tensor-core attention (mma.sync, hi/lo 3-term for QK^T and P@V)
// CTA: (head, 128 q rows), 8 warps x 16 rows. Two passes over 64-wide KV tiles.
// ---------------------------------------------------------------------------
#define AT_QP 136
#define AT_VP 72
#define SQHI 0
#define SQLO (128 * AT_QP)
#define SKHI (2 * 128 * AT_QP)
#define SKLO (SKHI + 64 * AT_QP)
#define SVHI (SKLO + 64 * AT_QP)
#define SVLO (SVHI + 128 * AT_VP)
#define SPHI (SVLO + 128 * AT_VP)
#define SPLO (SPHI + 128 * AT_VP)
#define AT_SMEM_ELEMS (SPLO + 128 * AT_VP)
#define AT_SMEM_BYTES (AT_SMEM_ELEMS * 2)

__global__ __launch_bounds__(256) void attention_mma(
    const __nv_bfloat16* __restrict__ qhi, const __nv_bfloat16* __restrict__ qlo,
    const __nv_bfloat16* __restrict__ khi, const __nv_bfloat16* __restrict__ klo,
    const __nv_bfloat16* __restrict__ vthi, const __nv_bfloat16* __restrict__ vtlo,
    float* __restrict__ probs,
    __nv_bfloat16* __restrict__ ahi, __nv_bfloat16* __restrict__ alo) {
    extern __shared__ __align__(16) __nv_bfloat16 smbuf[];
    const uint32_t sb = smem_to_u32(smbuf);
    const int h   = blockIdx.y;
    const int kvh = h >> 2;
    const int q0  = (int)(gridDim.x - 1 - blockIdx.x) * 128;  // heavy tiles first
    const int tid = threadIdx.x;
    const int lane = tid & 31;
    const int wid  = tid >> 5;
    const int quad = lane >> 3, wi = lane & 7;
    const int wm   = wid * 16;
    const int arow = (quad & 1) * 8 + wi, acol = (quad >> 1) * 8;
    const int brow = (quad >> 1) * 8 + wi, bcol = (quad & 1) * 8;
    const int erow = lane >> 2, fc = (lane & 3) * 2;
    const int grow0 = q0 + wm + erow;
    const int grow1 = grow0 + 8;

    // ---- load Q hi/lo ----
#pragma unroll
    for (int i = 0; i < 8; i++) {
        int idx = tid + i * 256;
        int row = idx >> 4, ch = idx & 15;
        size_t go = ((size_t)h * S_LEN + q0 + row) * HDIM + ch * 8;
        cpasync16(sb + (uint32_t)(SQHI + row * AT_QP + ch * 8) * 2, qhi + go);
        cpasync16(sb + (uint32_t)(SQLO + row * AT_QP + ch * 8) * 2, qlo + go);
    }
    CP_COMMIT(); CP_WAIT(0);
    __syncthreads();

    const int nvalid = ((q0 + 127) >> 6) + 1;
    float m0 = -1e30f, m1 = -1e30f, l0 = 0.f, l1 = 0.f;

    // ================= PASS 1 =================
    for (int jt = 0; jt < nvalid; jt++) {
        const int c0 = jt * 64;
#pragma unroll
        for (int i = 0; i < 4; i++) {
            int idx = tid + i * 256;
            int row = idx >> 4, ch = idx & 15;
            size_t go = ((size_t)kvh * S_LEN + c0 + row) * HDIM + ch * 8;
            cpasync16(sb + (uint32_t)(SKHI + row * AT_QP + ch * 8) * 2, khi + go);
            cpasync16(sb + (uint32_t)(SKLO + row * AT_QP + ch * 8) * 2, klo + go);
        }
        CP_COMMIT(); CP_WAIT(0);
        __syncthreads();

        float s[8][4];
#pragma unroll
        for (int nt = 0; nt < 8; nt++)
#pragma unroll
            for (int q = 0; q < 4; q++) s[nt][q] = 0.f;

#pragma unroll
        for (int term = 0; term < 3; term++) {
            const int qb = (term == 1) ? SQLO : SQHI;
            const int kb = (term == 2) ? SKLO : SKHI;
#pragma unroll
            for (int kk = 0; kk < 8; kk++) {
                uint32_t a[4], b[4][4];
                ldsm_x4(sb + (uint32_t)(qb + (wm + arow) * AT_QP + kk * 16 + acol) * 2, a);
#pragma unroll
                for (int nt2 = 0; nt2 < 4; nt2++)
                    ldsm_x4(sb + (uint32_t)(kb + (nt2 * 16 + brow) * AT_QP + kk * 16 + bcol) * 2, b[nt2]);
#pragma unroll
                for (int nt = 0; nt < 8; nt++)
                    mma16816(s[nt], a, b[nt >> 1][(nt & 1) * 2], b[nt >> 1][(nt & 1) * 2 + 1]);
            }
        }

        // mask + online stats
        float tm0 = -1e30f, tm1 = -1e30f;
#pragma unroll
        for (int nt = 0; nt < 8; nt++) {
            int cb = c0 + nt * 8 + fc;
            if (cb     > grow0) s[nt][0] = -1e30f;
            if (cb + 1 > grow0) s[nt][1] = -1e30f;
            if (cb     > grow1) s[nt][2] = -1e30f;
            if (cb + 1 > grow1) s[nt][3] = -1e30f;
            tm0 = fmaxf(tm0, fmaxf(s[nt][0], s[nt][1]));
            tm1 = fmaxf(tm1, fmaxf(s[nt][2], s[nt][3]));
        }
        tm0 = fmaxf(tm0, __shfl_xor_sync(0xffffffffu, tm0, 1));
        tm0 = fmaxf(tm0, __shfl_xor_sync(0xffffffffu, tm0, 2));
        tm1 = fmaxf(tm1, __shfl_xor_sync(0xffffffffu, tm1, 1));
        tm1 = fmaxf(tm1, __shfl_xor_sync(0xffffffffu, tm1, 2));
        float mn0 = fmaxf(m0, tm0), mn1 = fmaxf(m1, tm1);
        float su0 = 0.f, su1 = 0.f;
#pragma unroll
        for (int nt = 0; nt < 8; nt++) {
            su0 += __expf(s[nt][0] - mn0) + __expf(s[nt][1] - mn0);
            su1 += __expf(s[nt][2] - mn1) + __expf(s[nt][3] - mn1);
        }
        su0 += __shfl_xor_sync(0xffffffffu, su0, 1);
        su0 += __shfl_xor_sync(0xffffffffu, su0, 2);
        su1 += __shfl_xor_sync(0xffffffffu, su1, 1);
        su1 += __shfl_xor_sync(0xffffffffu, su1, 2);
        l0 = l0 * __expf(m0 - mn0) + su0; m0 = mn0;
        l1 = l1 * __expf(m1 - mn1) + su1; m1 = mn1;
        __syncthreads();
    }
    const float li0 = 1.0f / l0, li1 = 1.0f / l1;

    float o[16][4];
#pragma unroll
    for (int nt = 0; nt < 16; nt++)
#pragma unroll
        for (int q = 0; q < 4; q++) o[nt][q] = 0.f;

    // ================= PASS 2 =================
    for (int jt = 0; jt < S_LEN / 64; jt++) {
        const int c0 = jt * 64;
        if (c0 > q0 + 127) {
            float2 z = make_float2(0.f, 0.f);
#pragma unroll
            for (int nt = 0; nt < 8; nt++) {
                int col = c0 + nt * 8 + fc;
                *(float2*)&probs[((size_t)h * S_LEN + grow0) * S_LEN + col] = z;
                *(float2*)&probs[((size_t)h * S_LEN + grow1) * S_LEN + col] = z;
            }
            continue;
        }
        // load K + Vt tiles (hi/lo)
#pragma unroll
        for (int i = 0; i < 4; i++) {
            int idx = tid + i * 256;
            int row = idx >> 4, ch = idx & 15;
            size_t go = ((size_t)kvh * S_LEN + c0 + row) * HDIM + ch * 8;
            cpasync16(sb + (uint32_t)(SKHI + row * AT_QP + ch * 8) * 2, khi + go);
            cpasync16(sb + (uint32_t)(SKLO + row * AT_QP + ch * 8) * 2, klo + go);
        }
#pragma unroll
        for (int i = 0; i < 4; i++) {
            int idx = tid + i * 256;
            int row = idx >> 3, ch = idx & 7;
            size_t go = ((size_t)kvh * HDIM + row) * S_LEN + c0 + ch * 8;
            cpasync16(sb + (uint32_t)(SVHI + row * AT_VP + ch * 8) * 2, vthi + go);
            cpasync16(sb + (uint32_t)(SVLO + row * AT_VP + ch * 8) * 2, vtlo + go);
        }
        CP_COMMIT(); CP_WAIT(0);
        __syncthreads();

        float s[8][4];
#pragma unroll
        for (int nt = 0; nt < 8; nt++)
#pragma unroll
            for (int q = 0; q < 4; q++) s[nt][q] = 0.f;
#pragma unroll
        for (int term = 0; term < 3; term++) {
            const int qb = (term == 1) ? SQLO : SQHI;
            const int kb = (term == 2) ? SKLO : SKHI;
#pragma unroll
            for (int kk = 0; kk < 8; kk++) {
                uint32_t a[4], b[4][4];
                ldsm_x4(sb + (uint32_t)(qb + (wm + arow) * AT_QP + kk * 16 + acol) * 2, a);
#pragma unroll
                for (int nt2 = 0; nt2 < 4; nt2++)
                    ldsm_x4(sb + (uint32_t)(kb + (nt2 * 16 + brow) * AT_QP + kk * 16 + bcol) * 2, b[nt2]);
#pragma unroll
                for (int nt = 0; nt < 8; nt++)
                    mma16816(s[nt], a, b[nt >> 1][(nt & 1) * 2], b[nt >> 1][(nt & 1) * 2 + 1]);
            }
        }

        // probs + P split to smem
        const int pr0 = wm + erow, pr1 = pr0 + 8;
#pragma unroll
        for (int nt = 0; nt < 8; nt++) {
            int cb = c0 + nt * 8 + fc;
            float sv0 = (cb     > grow0) ? -1e30f : s[nt][0];
            float sv1 = (cb + 1 > grow0) ? -1e30f : s[nt][1];
            float sv2 = (cb     > grow1) ? -1e30f : s[nt][2];
            float sv3 = (cb + 1 > grow1) ? -1e30f : s[nt][3];
            float p0 = __expf(sv0 - m0) * li0;
            float p1 = __expf(sv1 - m0) * li0;
            float p2 = __expf(sv2 - m1) * li1;
            float p3 = __expf(sv3 - m1) * li1;
            *(float2*)&probs[((size_t)h * S_LEN + grow0) * S_LEN + cb] = make_float2(p0, p1);
            *(float2*)&probs[((size_t)h * S_LEN + grow1) * S_LEN + cb] = make_float2(p2, p3);
            int cl = nt * 8 + fc;
            __nv_bfloat16 h0 = __float2bfloat16(p0), h1 = __float2bfloat16(p1);
            __nv_bfloat16 h2 = __float2bfloat16(p2), h3 = __float2bfloat16(p3);
            __nv_bfloat162 hp01; hp01.x = h0; hp01.y = h1;
            __nv_bfloat162 hp23; hp23.x = h2; hp23.y = h3;
            __nv_bfloat162 lp01, lp23;
            lp01.x = __float2bfloat16(p0 - __bfloat162float(h0));
            lp01.y = __float2bfloat16(p1 - __bfloat162float(h1));
            lp23.x = __float2bfloat16(p2 - __bfloat162float(h2));
            lp23.y = __float2bfloat16(p3 - __bfloat162float(h3));
            *(__nv_bfloat162*)&smbuf[SPHI + pr0 * AT_VP + cl] = hp01;
            *(__nv_bfloat162*)&smbuf[SPHI + pr1 * AT_VP + cl] = hp23;
            *(__nv_bfloat162*)&smbuf[SPLO + pr0 * AT_VP + cl] = lp01;
            *(__nv_bfloat162*)&smbuf[SPLO + pr1 * AT_VP + cl] = lp23;
        }
        __syncwarp();

        // P @ V  (A=P rows owned by this warp; B=Vt)
#pragma unroll
        for (int term = 0; term < 3; term++) {
            const int pb = (term == 1) ? SPLO : SPHI;
            const int vb = (term == 2) ? SVLO : SVHI;
#pragma unroll
            for (int kk = 0; kk < 4; kk++) {
                uint32_t a[4], b[8][4];
                ldsm_x4(sb + (uint32_t)(pb + (wm + arow) * AT_VP + kk * 16 + acol) * 2, a);
#pragma unroll
                for (int nt2 = 0; nt2 < 8; nt2++)
                    ldsm_x4(sb + (uint32_t)(vb + (nt2 * 16 + brow) * AT_VP + kk * 16 + bcol) * 2, b[nt2]);
#pragma unroll
                for (int nt = 0; nt < 16; nt++)
                    mma16816(o[nt], a, b[nt >> 1][(nt & 1) * 2], b[nt >> 1][(nt & 1) * 2 + 1]);
            }
        }
        __syncthreads();
    }

    // ---- epilogue: split O to bf16 hi/lo in [s][h*128+d] layout ----
#pragma unroll
    for (int nt = 0; nt < 16; nt++) {
        int d = nt * 8 + fc;
        size_t b0 = (size_t)grow0 * HIDDEN + h * HDIM + d;
        size_t b1 = (size_t)grow1 * HIDDEN + h * HDIM + d;
        float v0 = o[nt][0], v1 = o[nt][1], v2 = o[nt][2], v3 = o[nt][3];
        __nv_bfloat16 h0 = __float2bfloat16(v0), h1 = __float2bfloat16(v1);
        __nv_bfloat16 h2 = __float2bfloat16(v2), h3 = __float2bfloat16(v3);
        __nv_bfloat162 hp01; hp01.x = h0; hp01.y = h1;
        __nv_bfloat162 hp23; hp23.x = h2; hp23.y = h3;
        __nv_bfloat162 lp01, lp23;
        lp01.x = __float2bfloat16(v0 - __bfloat162float(h0));
        lp01.y = __float2bfloat16(v1 - __bfloat162float(h1));
        lp23.x = __float2bfloat16(v2 - __bfloat162float(h2));
        lp23.y = __float2bfloat16(v3 - __bfloat162float(h3));
        *(__nv_bfloat162*)&ahi[b0] = hp01;
        *(__nv_bfloat162*)&ahi[b1] = hp23;
        *(__nv_bfloat162*)&alo[b0] = lp01;
        *(__nv_bfloat162*)&alo[b1] = lp23;
    }
}

// ---------------------------------------------------------------------------
// Launch
// ---------------------------------------------------------------------------
extern "C" void kernel_launch(void* const* d_in, const int* in_sizes, int n_in,
                              void* d_out, int out_size) {
    const float* X  = (const float*)d_in[0];
    const float* Wq = (const float*)d_in[2];
    const float* Wk = (const float*)d_in[3];
    const float* Wv = (const float*)d_in[4];
    const float* Wo = (const float*)d_in[5];
    const float* qw = (const float*)d_in[6];
    const float* kw = (const float*)d_in[7];

    float* out   = (float*)d_out;
    float* new_k = out + (size_t)S_LEN * HIDDEN;
    float* new_v = new_k + (size_t)NKV * S_LEN * HDIM;
    float* probs = new_v + (size_t)NKV * S_LEN * HDIM;

    float *qtmp, *ktmp, *vtmp;
    __nv_bfloat16 *xhi, *xlo, *ahi, *alo, *qhi, *qlo, *khi, *klo, *vthi, *vtlo;
    __nv_bfloat16 *wqh, *wql, *wkh, *wkl, *wvh, *wvl, *woh, *wol;
    cudaGetSymbolAddress((void**)&qtmp, g_qtmp);
    cudaGetSymbolAddress((void**)&ktmp, g_ktmp);
    cudaGetSymbolAddress((void**)&vtmp, g_vtmp);
    cudaGetSymbolAddress((void**)&xhi, g_xhi);
    cudaGetSymbolAddress((void**)&xlo, g_xlo);
    cudaGetSymbolAddress((void**)&ahi, g_ahi);
    cudaGetSymbolAddress((void**)&alo, g_alo);
    cudaGetSymbolAddress((void**)&qhi, g_qhi);
    cudaGetSymbolAddress((void**)&qlo, g_qlo);
    cudaGetSymbolAddress((void**)&khi, g_khi);
    cudaGetSymbolAddress((void**)&klo, g_klo);
    cudaGetSymbolAddress((void**)&vthi, g_vthi);
    cudaGetSymbolAddress((void**)&vtlo, g_vtlo);
    cudaGetSymbolAddress((void**)&wqh, g_wqthi);
    cudaGetSymbolAddress((void**)&wql, g_wqtlo);
    cudaGetSymbolAddress((void**)&wkh, g_wkthi);
    cudaGetSymbolAddress((void**)&wkl, g_wktlo);
    cudaGetSymbolAddress((void**)&wvh, g_wvthi);
    cudaGetSymbolAddress((void**)&wvl, g_wvtlo);
    cudaGetSymbolAddress((void**)&woh, g_wothi);
    cudaGetSymbolAddress((void**)&wol, g_wotlo);

    // ---- conversions ----
    {
        int n = S_LEN * HIDDEN;
        split_kernel<<<(n + 255) / 256, 256>>>(X, xhi, xlo, n);
    }
    transpose_split<<<dim3(HIDDEN / 32, HIDDEN / 32), dim3(32, 8)>>>(Wq, wqh, wql, HIDDEN);
    transpose_split<<<dim3((NKV * HDIM) / 32, HIDDEN / 32), dim3(32, 8)>>>(Wk, wkh, wkl, NKV * HDIM);
    transpose_split<<<dim3((NKV * HDIM) / 32, HIDDEN / 32), dim3(32, 8)>>>(Wv, wvh, wvl, NKV * HDIM);
    transpose_split<<<dim3(HIDDEN / 32, HIDDEN / 32), dim3(32, 8)>>>(Wo, woh, wol, HIDDEN);

    // ---- projections ----
    cudaFuncSetAttribute(gemm_mma, cudaFuncAttributeMaxDynamicSharedMemorySize,
                         GEMM_SMEM_BYTES);
    gemm_mma<<<dim3(HIDDEN / 128, S_LEN / 128), 256, GEMM_SMEM_BYTES>>>(
        xhi, xlo, wqh, wql, qtmp, HIDDEN);
    gemm_mma<<<dim3((NKV * HDIM) / 128, S_LEN / 128), 256, GEMM_SMEM_BYTES>>>(
        xhi, xlo, wkh, wkl, ktmp, NKV * HDIM);
    gemm_mma<<<dim3((NKV * HDIM) / 128, S_LEN / 128), 256, GEMM_SMEM_BYTES>>>(
        xhi, xlo, wvh, wvl, vtmp, NKV * HDIM);

    // ---- RMSNorm + RoPE + splits ----
    norm_rope_q<<<dim3(S_LEN, NHEADS), 128>>>(qtmp, qw, qhi, qlo);
    norm_rope_k<<<dim3(S_LEN, NKV), 128>>>(ktmp, kw, new_k, khi, klo);

    // ---- V transpose + split ----
    v_split_transpose<<<dim3(S_LEN / 32, HDIM / 32, NKV), dim3(32, 8)>>>(
        vtmp, new_v, vthi, vtlo);

    // ---- attention (tensor cores) ----
    cudaFuncSetAttribute(attention_mma,
                         cudaFuncAttributeMaxDynamicSharedMemorySize, AT_SMEM_BYTES);
    attention_mma<<<dim3(S_LEN / 128, NHEADS), 256, AT_SMEM_BYTES>>>(
        qhi, qlo, khi, klo, vthi, vtlo, probs, ahi, alo);

    // ---- O projection ----
    gemm_mma<<<dim3(HIDDEN / 128, S_LEN / 128), 256, GEMM_SMEM_BYTES>>>(
        ahi, alo, woh, wol, out, HIDDEN);
}

// round 6
// speedup vs baseline: 2.8453x; 1.0897x over previous
#include <cuda_runtime.h>
#include <cuda_bf16.h>
#include <math.h>
#include <stdint.h>

// ---------------------------------------------------------------------------
// Problem constants
// ---------------------------------------------------------------------------
#define S_LEN   2048
#define HIDDEN  4096
#define NHEADS  32
#define NKV     8
#define HDIM    128

// ---------------------------------------------------------------------------
// Device scratch
// ---------------------------------------------------------------------------
__device__ float g_qtmp[S_LEN * NHEADS * HDIM];
__device__ float g_ktmp[S_LEN * NKV * HDIM];
__device__ float g_vtmp[S_LEN * NKV * HDIM];

__device__ __nv_bfloat16 g_xhi[S_LEN * HIDDEN];
__device__ __nv_bfloat16 g_xlo[S_LEN * HIDDEN];
__device__ __nv_bfloat16 g_ahi[S_LEN * HIDDEN];
__device__ __nv_bfloat16 g_alo[S_LEN * HIDDEN];
__device__ __nv_bfloat16 g_qhi[NHEADS * S_LEN * HDIM];   // [h][s][d], pre-scaled
__device__ __nv_bfloat16 g_qlo[NHEADS * S_LEN * HDIM];
__device__ __nv_bfloat16 g_khi[NKV * S_LEN * HDIM];      // [kv][s][d]
__device__ __nv_bfloat16 g_klo[NKV * S_LEN * HDIM];
__device__ __nv_bfloat16 g_vthi[NKV * HDIM * S_LEN];     // [kv][d][s]
__device__ __nv_bfloat16 g_vtlo[NKV * HDIM * S_LEN];
__device__ __nv_bfloat16 g_wqthi[HIDDEN * HIDDEN];
__device__ __nv_bfloat16 g_wqtlo[HIDDEN * HIDDEN];
__device__ __nv_bfloat16 g_wkthi[(NKV * HDIM) * HIDDEN];
__device__ __nv_bfloat16 g_wktlo[(NKV * HDIM) * HIDDEN];
__device__ __nv_bfloat16 g_wvthi[(NKV * HDIM) * HIDDEN];
__device__ __nv_bfloat16 g_wvtlo[(NKV * HDIM) * HIDDEN];
__device__ __nv_bfloat16 g_wothi[HIDDEN * HIDDEN];
__device__ __nv_bfloat16 g_wotlo[HIDDEN * HIDDEN];

// ---------------------------------------------------------------------------
// Low-level helpers
// ---------------------------------------------------------------------------
__device__ __forceinline__ uint32_t smem_to_u32(const void* p) {
    uint32_t a;
    asm("{ .reg .u64 t; cvta.to.shared.u64 t, %1; cvt.u32.u64 %0, t; }"
        : "=r"(a) : "l"(p));
    return a;
}
__device__ __forceinline__ void cpasync16(uint32_t saddr, const void* g) {
    asm volatile("cp.async.cg.shared.global [%0], [%1], 16;"
                 :: "r"(saddr), "l"(g));
}
#define CP_COMMIT() asm volatile("cp.async.commit_group;" ::: "memory")
#define CP_WAIT(n)  asm volatile("cp.async.wait_group %0;" :: "n"(n) : "memory")

__device__ __forceinline__ void ldsm_x4(uint32_t addr, uint32_t r[4]) {
    asm volatile("ldmatrix.sync.aligned.m8n8.x4.shared.b16 {%0,%1,%2,%3}, [%4];"
        : "=r"(r[0]), "=r"(r[1]), "=r"(r[2]), "=r"(r[3]) : "r"(addr));
}
__device__ __forceinline__ void mma16816(float d[4], const uint32_t a[4],
                                         const uint32_t b0, const uint32_t b1) {
    asm volatile(
        "mma.sync.aligned.m16n8k16.row.col.f32.bf16.bf16.f32 "
        "{%0,%1,%2,%3}, {%4,%5,%6,%7}, {%8,%9}, {%0,%1,%2,%3};"
        : "+f"(d[0]), "+f"(d[1]), "+f"(d[2]), "+f"(d[3])
        : "r"(a[0]), "r"(a[1]), "r"(a[2]), "r"(a[3]), "r"(b0), "r"(b1));
}

// ---------------------------------------------------------------------------
// Projection GEMM v2: BK=64, double-buffered, fragment-reuse across terms.
// C[M,Ntot] = A[M,4096] @ B^T, hi/lo 3-term. blockIdx.z selects operand set
// (used to fuse the K and V projections into one launch).
// CTA 128x128, 256 threads, 8 warps (2x4), warp tile 64x32.
// ---------------------------------------------------------------------------
#define SP2   72
#define T2    (128 * SP2)                 // elems per tile buffer
#define STG2  (4 * T2)                    // Ah,Al,Bh,Bl
#define GEMM_SMEM_BYTES (2 * STG2 * 2)    // 147456 B
#define NCH2  (HIDDEN / 64)               // 64 chunks

__global__ __launch_bounds__(256) void gemm_mma(
    const __nv_bfloat16* __restrict__ Ahi, const __nv_bfloat16* __restrict__ Alo,
    const __nv_bfloat16* __restrict__ Bhi0, const __nv_bfloat16* __restrict__ Blo0,
    float* __restrict__ C0,
    const __nv_bfloat16* __restrict__ Bhi1, const __nv_bfloat16* __restrict__ Blo1,
    float* __restrict__ C1, int Ntot) {
    extern __shared__ __align__(16) __nv_bfloat16 smbuf[];
    const __nv_bfloat16* Bhi = blockIdx.z ? Bhi1 : Bhi0;
    const __nv_bfloat16* Blo = blockIdx.z ? Blo1 : Blo0;
    float* C = blockIdx.z ? C1 : C0;

    const uint32_t sb = smem_to_u32(smbuf);
    const int tid  = threadIdx.x;
    const int lane = tid & 31;
    const int wid  = tid >> 5;
    const int m0 = blockIdx.y * 128;
    const int n0 = blockIdx.x * 128;
    const int wm = (wid >> 2) * 64;
    const int wn = (wid & 3) * 32;
    const int quad = lane >> 3;
    const int wi   = lane & 7;
    const int arow = (quad & 1) * 8 + wi;
    const int acol = (quad >> 1) * 8;
    const int brow = (quad >> 1) * 8 + wi;
    const int bcol = (quad & 1) * 8;

    float acc[4][4][4];
#pragma unroll
    for (int mt = 0; mt < 4; mt++)
#pragma unroll
        for (int nt = 0; nt < 4; nt++)
#pragma unroll
            for (int q = 0; q < 4; q++) acc[mt][nt][q] = 0.f;

    auto load_stage = [&](int buf, int chunk) {
        const int k0 = chunk * 64;
        const uint32_t sbase = sb + (uint32_t)buf * STG2 * 2;
#pragma unroll
        for (int t = 0; t < 4; t++) {
            int c = tid + t * 256;            // 0..1023
            int row = c >> 3;
            int kc  = (c & 7) * 8;
            uint32_t so = sbase + (uint32_t)(row * SP2 + kc) * 2;
            size_t goA = (size_t)(m0 + row) * HIDDEN + k0 + kc;
            size_t goB = (size_t)(n0 + row) * HIDDEN + k0 + kc;
            cpasync16(so,              Ahi + goA);
            cpasync16(so + T2 * 2,     Alo + goA);
            cpasync16(so + 2 * T2 * 2, Bhi + goB);
            cpasync16(so + 3 * T2 * 2, Blo + goB);
        }
    };

    load_stage(0, 0);
    CP_COMMIT();

    for (int chunk = 0; chunk < NCH2; chunk++) {
        if (chunk + 1 < NCH2) {
            load_stage((chunk + 1) & 1, chunk + 1);
            CP_COMMIT();
            CP_WAIT(1);
        } else {
            CP_WAIT(0);
        }
        __syncthreads();

        const uint32_t stage = sb + (uint32_t)(chunk & 1) * STG2 * 2;
#pragma unroll
        for (int kk = 0; kk < 4; kk++) {
            uint32_t aH[4][4], aL[4][4], bH[2][4], bL[2][4];
#pragma unroll
            for (int mt = 0; mt < 4; mt++) {
                uint32_t ao = (uint32_t)((wm + mt * 16 + arow) * SP2 + kk * 16 + acol) * 2;
                ldsm_x4(stage + ao, aH[mt]);
                ldsm_x4(stage + T2 * 2 + ao, aL[mt]);
            }
#pragma unroll
            for (int nt2 = 0; nt2 < 2; nt2++) {
                uint32_t bo = (uint32_t)((wn + nt2 * 16 + brow) * SP2 + kk * 16 + bcol) * 2;
                ldsm_x4(stage + 2 * T2 * 2 + bo, bH[nt2]);
                ldsm_x4(stage + 3 * T2 * 2 + bo, bL[nt2]);
            }
#pragma unroll
            for (int mt = 0; mt < 4; mt++)
#pragma unroll
                for (int nt = 0; nt < 4; nt++) {
                    uint32_t h0 = bH[nt >> 1][(nt & 1) * 2];
                    uint32_t h1 = bH[nt >> 1][(nt & 1) * 2 + 1];
                    uint32_t l0 = bL[nt >> 1][(nt & 1) * 2];
                    uint32_t l1 = bL[nt >> 1][(nt & 1) * 2 + 1];
                    mma16816(acc[mt][nt], aH[mt], h0, h1);
                    mma16816(acc[mt][nt], aL[mt], h0, h1);
                    mma16816(acc[mt][nt], aH[mt], l0, l1);
                }
        }
        __syncthreads();
    }

    const int erow = lane >> 2;
    const int ecol = (lane & 3) * 2;
#pragma unroll
    for (int mt = 0; mt < 4; mt++) {
#pragma unroll
        for (int nt = 0; nt < 4; nt++) {
            int r = m0 + wm + mt * 16 + erow;
            int c = n0 + wn + nt * 8 + ecol;
            *(float2*)&C[(size_t)r * Ntot + c] =
                make_float2(acc[mt][nt][0], acc[mt][nt][1]);
            *(float2*)&C[(size_t)(r + 8) * Ntot + c] =
                make_float2(acc[mt][nt][2], acc[mt][nt][3]);
        }
    }
}

// ---------------------------------------------------------------------------
// f32 -> bf16 hi/lo split
// ---------------------------------------------------------------------------
__global__ void split_kernel(const float* __restrict__ x,
                             __nv_bfloat16* __restrict__ hi,
                             __nv_bfloat16* __restrict__ lo, int n) {
    int i = blockIdx.x * 256 + threadIdx.x;
    if (i >= n) return;
    float v = x[i];
    __nv_bfloat16 h = __float2bfloat16(v);
    hi[i] = h;
    lo[i] = __float2bfloat16(v - __bfloat162float(h));
}

// ---------------------------------------------------------------------------
// W [K=4096][N] f32 -> W^T hi/lo [N][4096] bf16
// ---------------------------------------------------------------------------
__global__ __launch_bounds__(256) void transpose_split(
    const float* __restrict__ W, __nv_bfloat16* __restrict__ hi,
    __nv_bfloat16* __restrict__ lo, int N) {
    __shared__ float t[32][33];
    const int n0 = blockIdx.x * 32;
    const int k0 = blockIdx.y * 32;
    const int tx = threadIdx.x;
    for (int r = threadIdx.y; r < 32; r += 8)
        t[r][tx] = W[(size_t)(k0 + r) * N + n0 + tx];
    __syncthreads();
    for (int r = threadIdx.y; r < 32; r += 8) {
        float v = t[tx][r];
        __nv_bfloat16 h = __float2bfloat16(v);
        size_t o = (size_t)(n0 + r) * HIDDEN + k0 + tx;
        hi[o] = h;
        lo[o] = __float2bfloat16(v - __bfloat162float(h));
    }
}

// ---------------------------------------------------------------------------
// RMSNorm + RoPE for Q: pre-scaled bf16 hi/lo splits [h][s][d]
// ---------------------------------------------------------------------------
__global__ __launch_bounds__(128) void norm_rope_q(
    const float* __restrict__ inp, const float* __restrict__ w,
    __nv_bfloat16* __restrict__ qhi, __nv_bfloat16* __restrict__ qlo) {
    const int s = blockIdx.x;
    const int h = blockIdx.y;
    const int d = threadIdx.x;

    float x = inp[((size_t)s * NHEADS + h) * HDIM + d];
    float ss = x * x;
#pragma unroll
    for (int o = 16; o; o >>= 1) ss += __shfl_xor_sync(0xffffffffu, ss, o);
    __shared__ float wss[4];
    __shared__ float xs[HDIM];
    if ((d & 31) == 0) wss[d >> 5] = ss;
    __syncthreads();
    float var = (wss[0] + wss[1] + wss[2] + wss[3]) * (1.0f / 128.0f);
    xs[d] = x * rsqrtf(var + 1e-6f) * w[d];
    __syncthreads();

    if (d < 64) {
        const float scale = 0.08838834764831845f;
        float p = (float)s;
        float e = (float)(2 * d) * (1.0f / 128.0f);
        float invf = powf(1000000.0f, -e);
        float si, c;
        sincosf(p * invf, &si, &c);
        float x1 = xs[d], x2 = xs[d + 64];
        float r1 = (x1 * c - x2 * si) * scale;
        float r2 = (x2 * c + x1 * si) * scale;
        size_t base = ((size_t)h * S_LEN + s) * HDIM;
        __nv_bfloat16 h1 = __float2bfloat16(r1);
        __nv_bfloat16 h2 = __float2bfloat16(r2);
        qhi[base + d]      = h1;
        qhi[base + d + 64] = h2;
        qlo[base + d]      = __float2bfloat16(r1 - __bfloat162float(h1));
        qlo[base + d + 64] = __float2bfloat16(r2 - __bfloat162float(h2));
    }
}

// ---------------------------------------------------------------------------
// RMSNorm + RoPE for K: f32 new_k [kv][s][d] + bf16 hi/lo splits
// ---------------------------------------------------------------------------
__global__ __launch_bounds__(128) void norm_rope_k(
    const float* __restrict__ inp, const float* __restrict__ w,
    float* __restrict__ outf,
    __nv_bfloat16* __restrict__ khi, __nv_bfloat16* __restrict__ klo) {
    const int s = blockIdx.x;
    const int h = blockIdx.y;
    const int d = threadIdx.x;

    float x = inp[((size_t)s * NKV + h) * HDIM + d];
    float ss = x * x;
#pragma unroll
    for (int o = 16; o; o >>= 1) ss += __shfl_xor_sync(0xffffffffu, ss, o);
    __shared__ float wss[4];
    __shared__ float xs[HDIM];
    if ((d & 31) == 0) wss[d >> 5] = ss;
    __syncthreads();
    float var = (wss[0] + wss[1] + wss[2] + wss[3]) * (1.0f / 128.0f);
    xs[d] = x * rsqrtf(var + 1e-6f) * w[d];
    __syncthreads();

    if (d < 64) {
        float p = (float)s;
        float e = (float)(2 * d) * (1.0f / 128.0f);
        float invf = powf(1000000.0f, -e);
        float si, c;
        sincosf(p * invf, &si, &c);
        float x1 = xs[d], x2 = xs[d + 64];
        float r1 = x1 * c - x2 * si;
        float r2 = x2 * c + x1 * si;
        size_t base = ((size_t)h * S_LEN + s) * HDIM;
        outf[base + d]      = r1;
        outf[base + d + 64] = r2;
        __nv_bfloat16 h1 = __float2bfloat16(r1);
        __nv_bfloat16 h2 = __float2bfloat16(r2);
        khi[base + d]      = h1;
        khi[base + d + 64] = h2;
        klo[base + d]      = __float2bfloat16(r1 - __bfloat162float(h1));
        klo[base + d + 64] = __float2bfloat16(r2 - __bfloat162float(h2));
    }
}

// ---------------------------------------------------------------------------
// V: [s][kv*128+d] -> new_v f32 [kv][s][d] + V^T splits [kv][d][s] bf16
// ---------------------------------------------------------------------------
__global__ __launch_bounds__(256) void v_split_transpose(
    const float* __restrict__ vt, float* __restrict__ outf,
    __nv_bfloat16* __restrict__ vthi, __nv_bfloat16* __restrict__ vtlo) {
    __shared__ float t[32][33];
    const int kv = blockIdx.z;
    const int s0 = blockIdx.x * 32;
    const int d0 = blockIdx.y * 32;
    const int tx = threadIdx.x;
    for (int r = threadIdx.y; r < 32; r += 8) {
        float v = vt[(size_t)(s0 + r) * (NKV * HDIM) + kv * HDIM + d0 + tx];
        t[r][tx] = v;
        outf[((size_t)kv * S_LEN + s0 + r) * HDIM + d0 + tx] = v;
    }
    __syncthreads();
    for (int r = threadIdx.y; r < 32; r += 8) {
        float v = t[tx][r];
        __nv_bfloat16 h = __float2bfloat16(v);
        size_t o = ((size_t)kv * HDIM + d0 + r) * S_LEN + s0 + tx;
        vthi[o] = h;
        vtlo[o] = __float2bfloat16(v - __bfloat162float(h));
    }
}

// ---------------------------------------------------------------------------
// Tensor-core attention (unchanged from round 5 — passing, ~0.45ms)
// ---------------------------------------------------------------------------
#define AT_QP 136
#define AT_VP 72
#define SQHI 0
#define SQLO (128 * AT_QP)
#define SKHI (2 * 128 * AT_QP)
#define SKLO (SKHI + 64 * AT_QP)
#define SVHI (SKLO + 64 * AT_QP)
#define SVLO (SVHI + 128 * AT_VP)
#define SPHI (SVLO + 128 * AT_VP)
#define SPLO (SPHI + 128 * AT_VP)
#define AT_SMEM_ELEMS (SPLO + 128 * AT_VP)
#define AT_SMEM_BYTES (AT_SMEM_ELEMS * 2)

__global__ __launch_bounds__(256) void attention_mma(
    const __nv_bfloat16* __restrict__ qhi, const __nv_bfloat16* __restrict__ qlo,
    const __nv_bfloat16* __restrict__ khi, const __nv_bfloat16* __restrict__ klo,
    const __nv_bfloat16* __restrict__ vthi, const __nv_bfloat16* __restrict__ vtlo,
    float* __restrict__ probs,
    __nv_bfloat16* __restrict__ ahi, __nv_bfloat16* __restrict__ alo) {
    extern __shared__ __align__(16) __nv_bfloat16 smbuf[];
    const uint32_t sb = smem_to_u32(smbuf);
    const int h   = blockIdx.y;
    const int kvh = h >> 2;
    const int q0  = (int)(gridDim.x - 1 - blockIdx.x) * 128;
    const int tid = threadIdx.x;
    const int lane = tid & 31;
    const int wid  = tid >> 5;
    const int quad = lane >> 3, wi = lane & 7;
    const int wm   = wid * 16;
    const int arow = (quad & 1) * 8 + wi, acol = (quad >> 1) * 8;
    const int brow = (quad >> 1) * 8 + wi, bcol = (quad & 1) * 8;
    const int erow = lane >> 2, fc = (lane & 3) * 2;
    const int grow0 = q0 + wm + erow;
    const int grow1 = grow0 + 8;

#pragma unroll
    for (int i = 0; i < 8; i++) {
        int idx = tid + i * 256;
        int row = idx >> 4, ch = idx & 15;
        size_t go = ((size_t)h * S_LEN + q0 + row) * HDIM + ch * 8;
        cpasync16(sb + (uint32_t)(SQHI + row * AT_QP + ch * 8) * 2, qhi + go);
        cpasync16(sb + (uint32_t)(SQLO + row * AT_QP + ch * 8) * 2, qlo + go);
    }
    CP_COMMIT(); CP_WAIT(0);
    __syncthreads();

    const int nvalid = ((q0 + 127) >> 6) + 1;
    float m0 = -1e30f, m1 = -1e30f, l0 = 0.f, l1 = 0.f;

    for (int jt = 0; jt < nvalid; jt++) {
        const int c0 = jt * 64;
#pragma unroll
        for (int i = 0; i < 4; i++) {
            int idx = tid + i * 256;
            int row = idx >> 4, ch = idx & 15;
            size_t go = ((size_t)kvh * S_LEN + c0 + row) * HDIM + ch * 8;
            cpasync16(sb + (uint32_t)(SKHI + row * AT_QP + ch * 8) * 2, khi + go);
            cpasync16(sb + (uint32_t)(SKLO + row * AT_QP + ch * 8) * 2, klo + go);
        }
        CP_COMMIT(); CP_WAIT(0);
        __syncthreads();

        float s[8][4];
#pragma unroll
        for (int nt = 0; nt < 8; nt++)
#pragma unroll
            for (int q = 0; q < 4; q++) s[nt][q] = 0.f;

#pragma unroll
        for (int term = 0; term < 3; term++) {
            const int qb = (term == 1) ? SQLO : SQHI;
            const int kb = (term == 2) ? SKLO : SKHI;
#pragma unroll
            for (int kk = 0; kk < 8; kk++) {
                uint32_t a[4], b[4][4];
                ldsm_x4(sb + (uint32_t)(qb + (wm + arow) * AT_QP + kk * 16 + acol) * 2, a);
#pragma unroll
                for (int nt2 = 0; nt2 < 4; nt2++)
                    ldsm_x4(sb + (uint32_t)(kb + (nt2 * 16 + brow) * AT_QP + kk * 16 + bcol) * 2, b[nt2]);
#pragma unroll
                for (int nt = 0; nt < 8; nt++)
                    mma16816(s[nt], a, b[nt >> 1][(nt & 1) * 2], b[nt >> 1][(nt & 1) * 2 + 1]);
            }
        }

        float tm0 = -1e30f, tm1 = -1e30f;
#pragma unroll
        for (int nt = 0; nt < 8; nt++) {
            int cb = c0 + nt * 8 + fc;
            if (cb     > grow0) s[nt][0] = -1e30f;
            if (cb + 1 > grow0) s[nt][1] = -1e30f;
            if (cb     > grow1) s[nt][2] = -1e30f;
            if (cb + 1 > grow1) s[nt][3] = -1e30f;
            tm0 = fmaxf(tm0, fmaxf(s[nt][0], s[nt][1]));
            tm1 = fmaxf(tm1, fmaxf(s[nt][2], s[nt][3]));
        }
        tm0 = fmaxf(tm0, __shfl_xor_sync(0xffffffffu, tm0, 1));
        tm0 = fmaxf(tm0, __shfl_xor_sync(0xffffffffu, tm0, 2));
        tm1 = fmaxf(tm1, __shfl_xor_sync(0xffffffffu, tm1, 1));
        tm1 = fmaxf(tm1, __shfl_xor_sync(0xffffffffu, tm1, 2));
        float mn0 = fmaxf(m0, tm0), mn1 = fmaxf(m1, tm1);
        float su0 = 0.f, su1 = 0.f;
#pragma unroll
        for (int nt = 0; nt < 8; nt++) {
            su0 += __expf(s[nt][0] - mn0) + __expf(s[nt][1] - mn0);
            su1 += __expf(s[nt][2] - mn1) + __expf(s[nt][3] - mn1);
        }
        su0 += __shfl_xor_sync(0xffffffffu, su0, 1);
        su0 += __shfl_xor_sync(0xffffffffu, su0, 2);
        su1 += __shfl_xor_sync(0xffffffffu, su1, 1);
        su1 += __shfl_xor_sync(0xffffffffu, su1, 2);
        l0 = l0 * __expf(m0 - mn0) + su0; m0 = mn0;
        l1 = l1 * __expf(m1 - mn1) + su1; m1 = mn1;
        __syncthreads();
    }
    const float li0 = 1.0f / l0, li1 = 1.0f / l1;

    float o[16][4];
#pragma unroll
    for (int nt = 0; nt < 16; nt++)
#pragma unroll
        for (int q = 0; q < 4; q++) o[nt][q] = 0.f;

    for (int jt = 0; jt < S_LEN / 64; jt++) {
        const int c0 = jt * 64;
        if (c0 > q0 + 127) {
            float2 z = make_float2(0.f, 0.f);
#pragma unroll
            for (int nt = 0; nt < 8; nt++) {
                int col = c0 + nt * 8 + fc;
                *(float2*)&probs[((size_t)h * S_LEN + grow0) * S_LEN + col] = z;
                *(float2*)&probs[((size_t)h * S_LEN + grow1) * S_LEN + col] = z;
            }
            continue;
        }
#pragma unroll
        for (int i = 0; i < 4; i++) {
            int idx = tid + i * 256;
            int row = idx >> 4, ch = idx & 15;
            size_t go = ((size_t)kvh * S_LEN + c0 + row) * HDIM + ch * 8;
            cpasync16(sb + (uint32_t)(SKHI + row * AT_QP + ch * 8) * 2, khi + go);
            cpasync16(sb + (uint32_t)(SKLO + row * AT_QP + ch * 8) * 2, klo + go);
        }
#pragma unroll
        for (int i = 0; i < 4; i++) {
            int idx = tid + i * 256;
            int row = idx >> 3, ch = idx & 7;
            size_t go = ((size_t)kvh * HDIM + row) * S_LEN + c0 + ch * 8;
            cpasync16(sb + (uint32_t)(SVHI + row * AT_VP + ch * 8) * 2, vthi + go);
            cpasync16(sb + (uint32_t)(SVLO + row * AT_VP + ch * 8) * 2, vtlo + go);
        }
        CP_COMMIT(); CP_WAIT(0);
        __syncthreads();

        float s[8][4];
#pragma unroll
        for (int nt = 0; nt < 8; nt++)
#pragma unroll
            for (int q = 0; q < 4; q++) s[nt][q] = 0.f;
#pragma unroll
        for (int term = 0; term < 3; term++) {
            const int qb = (term == 1) ? SQLO : SQHI;
            const int kb = (term == 2) ? SKLO : SKHI;
#pragma unroll
            for (int kk = 0; kk < 8; kk++) {
                uint32_t a[4], b[4][4];
                ldsm_x4(sb + (uint32_t)(qb + (wm + arow) * AT_QP + kk * 16 + acol) * 2, a);
#pragma unroll
                for (int nt2 = 0; nt2 < 4; nt2++)
                    ldsm_x4(sb + (uint32_t)(kb + (nt2 * 16 + brow) * AT_QP + kk * 16 + bcol) * 2, b[nt2]);
#pragma unroll
                for (int nt = 0; nt < 8; nt++)
                    mma16816(s[nt], a, b[nt >> 1][(nt & 1) * 2], b[nt >> 1][(nt & 1) * 2 + 1]);
            }
        }

        const int pr0 = wm + erow, pr1 = pr0 + 8;
#pragma unroll
        for (int nt = 0; nt < 8; nt++) {
            int cb = c0 + nt * 8 + fc;
            float sv0 = (cb     > grow0) ? -1e30f : s[nt][0];
            float sv1 = (cb + 1 > grow0) ? -1e30f : s[nt][1];
            float sv2 = (cb     > grow1) ? -1e30f : s[nt][2];
            float sv3 = (cb + 1 > grow1) ? -1e30f : s[nt][3];
            float p0 = __expf(sv0 - m0) * li0;
            float p1 = __expf(sv1 - m0) * li0;
            float p2 = __expf(sv2 - m1) * li1;
            float p3 = __expf(sv3 - m1) * li1;
            *(float2*)&probs[((size_t)h * S_LEN + grow0) * S_LEN + cb] = make_float2(p0, p1);
            *(float2*)&probs[((size_t)h * S_LEN + grow1) * S_LEN + cb] = make_float2(p2, p3);
            int cl = nt * 8 + fc;
            __nv_bfloat16 h0 = __float2bfloat16(p0), h1 = __float2bfloat16(p1);
            __nv_bfloat16 h2 = __float2bfloat16(p2), h3 = __float2bfloat16(p3);
            __nv_bfloat162 hp01; hp01.x = h0; hp01.y = h1;
            __nv_bfloat162 hp23; hp23.x = h2; hp23.y = h3;
            __nv_bfloat162 lp01, lp23;
            lp01.x = __float2bfloat16(p0 - __bfloat162float(h0));
            lp01.y = __float2bfloat16(p1 - __bfloat162float(h1));
            lp23.x = __float2bfloat16(p2 - __bfloat162float(h2));
            lp23.y = __float2bfloat16(p3 - __bfloat162float(h3));
            *(__nv_bfloat162*)&smbuf[SPHI + pr0 * AT_VP + cl] = hp01;
            *(__nv_bfloat162*)&smbuf[SPHI + pr1 * AT_VP + cl] = hp23;
            *(__nv_bfloat162*)&smbuf[SPLO + pr0 * AT_VP + cl] = lp01;
            *(__nv_bfloat162*)&smbuf[SPLO + pr1 * AT_VP + cl] = lp23;
        }
        __syncwarp();

#pragma unroll
        for (int term = 0; term < 3; term++) {
            const int pb = (term == 1) ? SPLO : SPHI;
            const int vb = (term == 2) ? SVLO : SVHI;
#pragma unroll
            for (int kk = 0; kk < 4; kk++) {
                uint32_t a[4], b[8][4];
                ldsm_x4(sb + (uint32_t)(pb + (wm + arow) * AT_VP + kk * 16 + acol) * 2, a);
#pragma unroll
                for (int nt2 = 0; nt2 < 8; nt2++)
                    ldsm_x4(sb + (uint32_t)(vb + (nt2 * 16 + brow) * AT_VP + kk * 16 + bcol) * 2, b[nt2]);
#pragma unroll
                for (int nt = 0; nt < 16; nt++)
                    mma16816(o[nt], a, b[nt >> 1][(nt & 1) * 2], b[nt >> 1][(nt & 1) * 2 + 1]);
            }
        }
        __syncthreads();
    }

#pragma unroll
    for (int nt = 0; nt < 16; nt++) {
        int d = nt * 8 + fc;
        size_t b0 = (size_t)grow0 * HIDDEN + h * HDIM + d;
        size_t b1 = (size_t)grow1 * HIDDEN + h * HDIM + d;
        float v0 = o[nt][0], v1 = o[nt][1], v2 = o[nt][2], v3 = o[nt][3];
        __nv_bfloat16 h0 = __float2bfloat16(v0), h1 = __float2bfloat16(v1);
        __nv_bfloat16 h2 = __float2bfloat16(v2), h3 = __float2bfloat16(v3);
        __nv_bfloat162 hp01; hp01.x = h0; hp01.y = h1;
        __nv_bfloat162 hp23; hp23.x = h2; hp23.y = h3;
        __nv_bfloat162 lp01, lp23;
        lp01.x = __float2bfloat16(v0 - __bfloat162float(h0));
        lp01.y = __float2bfloat16(v1 - __bfloat162float(h1));
        lp23.x = __float2bfloat16(v2 - __bfloat162float(h2));
        lp23.y = __float2bfloat16(v3 - __bfloat162float(h3));
        *(__nv_bfloat162*)&ahi[b0] = hp01;
        *(__nv_bfloat162*)&ahi[b1] = hp23;
        *(__nv_bfloat162*)&alo[b0] = lp01;
        *(__nv_bfloat162*)&alo[b1] = lp23;
    }
}

// ---------------------------------------------------------------------------
// Launch
// ---------------------------------------------------------------------------
extern "C" void kernel_launch(void* const* d_in, const int* in_sizes, int n_in,
                              void* d_out, int out_size) {
    const float* X  = (const float*)d_in[0];
    const float* Wq = (const float*)d_in[2];
    const float* Wk = (const float*)d_in[3];
    const float* Wv = (const float*)d_in[4];
    const float* Wo = (const float*)d_in[5];
    const float* qw = (const float*)d_in[6];
    const float* kw = (const float*)d_in[7];

    float* out   = (float*)d_out;
    float* new_k = out + (size_t)S_LEN * HIDDEN;
    float* new_v = new_k + (size_t)NKV * S_LEN * HDIM;
    float* probs = new_v + (size_t)NKV * S_LEN * HDIM;

    float *qtmp, *ktmp, *vtmp;
    __nv_bfloat16 *xhi, *xlo, *ahi, *alo, *qhi, *qlo, *khi, *klo, *vthi, *vtlo;
    __nv_bfloat16 *wqh, *wql, *wkh, *wkl, *wvh, *wvl, *woh, *wol;
    cudaGetSymbolAddress((void**)&qtmp, g_qtmp);
    cudaGetSymbolAddress((void**)&ktmp, g_ktmp);
    cudaGetSymbolAddress((void**)&vtmp, g_vtmp);
    cudaGetSymbolAddress((void**)&xhi, g_xhi);
    cudaGetSymbolAddress((void**)&xlo, g_xlo);
    cudaGetSymbolAddress((void**)&ahi, g_ahi);
    cudaGetSymbolAddress((void**)&alo, g_alo);
    cudaGetSymbolAddress((void**)&qhi, g_qhi);
    cudaGetSymbolAddress((void**)&qlo, g_qlo);
    cudaGetSymbolAddress((void**)&khi, g_khi);
    cudaGetSymbolAddress((void**)&klo, g_klo);
    cudaGetSymbolAddress((void**)&vthi, g_vthi);
    cudaGetSymbolAddress((void**)&vtlo, g_vtlo);
    cudaGetSymbolAddress((void**)&wqh, g_wqthi);
    cudaGetSymbolAddress((void**)&wql, g_wqtlo);
    cudaGetSymbolAddress((void**)&wkh, g_wkthi);
    cudaGetSymbolAddress((void**)&wkl, g_wktlo);
    cudaGetSymbolAddress((void**)&wvh, g_wvthi);
    cudaGetSymbolAddress((void**)&wvl, g_wvtlo);
    cudaGetSymbolAddress((void**)&woh, g_wothi);
    cudaGetSymbolAddress((void**)&wol, g_wotlo);

    // ---- conversions ----
    {
        int n = S_LEN * HIDDEN;
        split_kernel<<<(n + 255) / 256, 256>>>(X, xhi, xlo, n);
    }
    transpose_split<<<dim3(HIDDEN / 32, HIDDEN / 32), dim3(32, 8)>>>(Wq, wqh, wql, HIDDEN);
    transpose_split<<<dim3((NKV * HDIM) / 32, HIDDEN / 32), dim3(32, 8)>>>(Wk, wkh, wkl, NKV * HDIM);
    transpose_split<<<dim3((NKV * HDIM) / 32, HIDDEN / 32), dim3(32, 8)>>>(Wv, wvh, wvl, NKV * HDIM);
    transpose_split<<<dim3(HIDDEN / 32, HIDDEN / 32), dim3(32, 8)>>>(Wo, woh, wol, HIDDEN);

    // ---- projections (Q alone; K+V fused via blockIdx.z) ----
    cudaFuncSetAttribute(gemm_mma, cudaFuncAttributeMaxDynamicSharedMemorySize,
                         GEMM_SMEM_BYTES);
    gemm_mma<<<dim3(HIDDEN / 128, S_LEN / 128, 1), 256, GEMM_SMEM_BYTES>>>(
        xhi, xlo, wqh, wql, qtmp, wqh, wql, qtmp, HIDDEN);
    gemm_mma<<<dim3((NKV * HDIM) / 128, S_LEN / 128, 2), 256, GEMM_SMEM_BYTES>>>(
        xhi, xlo, wkh, wkl, ktmp, wvh, wvl, vtmp, NKV * HDIM);

    // ---- RMSNorm + RoPE + splits ----
    norm_rope_q<<<dim3(S_LEN, NHEADS), 128>>>(qtmp, qw, qhi, qlo);
    norm_rope_k<<<dim3(S_LEN, NKV), 128>>>(ktmp, kw, new_k, khi, klo);

    // ---- V transpose + split ----
    v_split_transpose<<<dim3(S_LEN / 32, HDIM / 32, NKV), dim3(32, 8)>>>(
        vtmp, new_v, vthi, vtlo);

    // ---- attention ----
    cudaFuncSetAttribute(attention_mma,
                         cudaFuncAttributeMaxDynamicSharedMemorySize, AT_SMEM_BYTES);
    attention_mma<<<dim3(S_LEN / 128, NHEADS), 256, AT_SMEM_BYTES>>>(
        qhi, qlo, khi, klo, vthi, vtlo, probs, ahi, alo);

    // ---- O projection ----
    gemm_mma<<<dim3(HIDDEN / 128, S_LEN / 128, 1), 256, GEMM_SMEM_BYTES>>>(
        ahi, alo, woh, wol, out, woh, wol, out, HIDDEN);
}

// round 7
// speedup vs baseline: 3.0262x; 1.0636x over previous
#include <cuda_runtime.h>
#include <cuda_bf16.h>
#include <math.h>
#include <stdint.h>

// ---------------------------------------------------------------------------
// Problem constants
// ---------------------------------------------------------------------------
#define S_LEN   2048
#define HIDDEN  4096
#define NHEADS  32
#define NKV     8
#define HDIM    128

// ---------------------------------------------------------------------------
// Device scratch
// ---------------------------------------------------------------------------
__device__ float g_qtmp[S_LEN * NHEADS * HDIM];
__device__ float g_ktmp[S_LEN * NKV * HDIM];
__device__ float g_vtmp[S_LEN * NKV * HDIM];

__device__ __nv_bfloat16 g_xhi[S_LEN * HIDDEN];
__device__ __nv_bfloat16 g_xlo[S_LEN * HIDDEN];
__device__ __nv_bfloat16 g_ahi[S_LEN * HIDDEN];
__device__ __nv_bfloat16 g_alo[S_LEN * HIDDEN];
__device__ __nv_bfloat16 g_qhi[NHEADS * S_LEN * HDIM];   // [h][s][d], pre-scaled
__device__ __nv_bfloat16 g_qlo[NHEADS * S_LEN * HDIM];
__device__ __nv_bfloat16 g_khi[NKV * S_LEN * HDIM];      // [kv][s][d]
__device__ __nv_bfloat16 g_klo[NKV * S_LEN * HDIM];
__device__ __nv_bfloat16 g_vthi[NKV * HDIM * S_LEN];     // [kv][d][s]
__device__ __nv_bfloat16 g_vtlo[NKV * HDIM * S_LEN];
__device__ __nv_bfloat16 g_wqthi[HIDDEN * HIDDEN];
__device__ __nv_bfloat16 g_wqtlo[HIDDEN * HIDDEN];
__device__ __nv_bfloat16 g_wkthi[(NKV * HDIM) * HIDDEN];
__device__ __nv_bfloat16 g_wktlo[(NKV * HDIM) * HIDDEN];
__device__ __nv_bfloat16 g_wvthi[(NKV * HDIM) * HIDDEN];
__device__ __nv_bfloat16 g_wvtlo[(NKV * HDIM) * HIDDEN];
__device__ __nv_bfloat16 g_wothi[HIDDEN * HIDDEN];
__device__ __nv_bfloat16 g_wotlo[HIDDEN * HIDDEN];

// ---------------------------------------------------------------------------
// Low-level helpers
// ---------------------------------------------------------------------------
__device__ __forceinline__ uint32_t smem_to_u32(const void* p) {
    uint32_t a;
    asm("{ .reg .u64 t; cvta.to.shared.u64 t, %1; cvt.u32.u64 %0, t; }"
        : "=r"(a) : "l"(p));
    return a;
}
__device__ __forceinline__ void cpasync16(uint32_t saddr, const void* g) {
    asm volatile("cp.async.cg.shared.global [%0], [%1], 16;"
                 :: "r"(saddr), "l"(g));
}
#define CP_COMMIT() asm volatile("cp.async.commit_group;" ::: "memory")
#define CP_WAIT(n)  asm volatile("cp.async.wait_group %0;" :: "n"(n) : "memory")

__device__ __forceinline__ void ldsm_x4(uint32_t addr, uint32_t r[4]) {
    asm volatile("ldmatrix.sync.aligned.m8n8.x4.shared.b16 {%0,%1,%2,%3}, [%4];"
        : "=r"(r[0]), "=r"(r[1]), "=r"(r[2]), "=r"(r[3]) : "r"(addr));
}
__device__ __forceinline__ void mma16816(float d[4], const uint32_t a[4],
                                         const uint32_t b0, const uint32_t b1) {
    asm volatile(
        "mma.sync.aligned.m16n8k16.row.col.f32.bf16.bf16.f32 "
        "{%0,%1,%2,%3}, {%4,%5,%6,%7}, {%8,%9}, {%0,%1,%2,%3};"
        : "+f"(d[0]), "+f"(d[1]), "+f"(d[2]), "+f"(d[3])
        : "r"(a[0]), "r"(a[1]), "r"(a[2]), "r"(a[3]), "r"(b0), "r"(b1));
}

// ---------------------------------------------------------------------------
// Projection GEMM v3: CTA tile 256x128, BK=64, warp tile 64x64 (8 warps 4mx2n),
// double-buffered cp.async, hi/lo 3-term. blockIdx.z selects one of up to 3
// operand sets (fusing Q, K, V projections in one launch).
// ---------------------------------------------------------------------------
#define SP3       72
#define A3_ELEMS  (256 * SP3)             // 18432
#define B3_ELEMS  (128 * SP3)             // 9216
#define STG3      (2 * A3_ELEMS + 2 * B3_ELEMS)  // 55296 elems
#define GEMM3_SMEM (2 * STG3 * 2)         // 221184 B
#define NCH3      (HIDDEN / 64)           // 64

__global__ __launch_bounds__(256) void gemm_mma3(
    const __nv_bfloat16* __restrict__ Ahi, const __nv_bfloat16* __restrict__ Alo,
    const __nv_bfloat16* __restrict__ Bh0, const __nv_bfloat16* __restrict__ Bl0,
    float* __restrict__ C0, int N0,
    const __nv_bfloat16* __restrict__ Bh1, const __nv_bfloat16* __restrict__ Bl1,
    float* __restrict__ C1, int N1,
    const __nv_bfloat16* __restrict__ Bh2, const __nv_bfloat16* __restrict__ Bl2,
    float* __restrict__ C2, int N2) {
    extern __shared__ __align__(16) __nv_bfloat16 smbuf[];
    const __nv_bfloat16* Bhi;
    const __nv_bfloat16* Blo;
    float* C;
    int Ntot;
    if (blockIdx.z == 0)      { Bhi = Bh0; Blo = Bl0; C = C0; Ntot = N0; }
    else if (blockIdx.z == 1) { Bhi = Bh1; Blo = Bl1; C = C1; Ntot = N1; }
    else                      { Bhi = Bh2; Blo = Bl2; C = C2; Ntot = N2; }
    const int n0 = blockIdx.x * 128;
    if (n0 >= Ntot) return;
    const int m0 = blockIdx.y * 256;

    const uint32_t sb = smem_to_u32(smbuf);
    const int tid  = threadIdx.x;
    const int lane = tid & 31;
    const int wid  = tid >> 5;
    const int wm = (wid >> 1) * 64;       // 4 m-groups
    const int wn = (wid & 1) * 64;        // 2 n-groups
    const int quad = lane >> 3;
    const int wi   = lane & 7;
    const int arow = (quad & 1) * 8 + wi;
    const int acol = (quad >> 1) * 8;
    const int brow = (quad >> 1) * 8 + wi;
    const int bcol = (quad & 1) * 8;

    float acc[4][8][4];
#pragma unroll
    for (int mt = 0; mt < 4; mt++)
#pragma unroll
        for (int nt = 0; nt < 8; nt++)
#pragma unroll
            for (int q = 0; q < 4; q++) acc[mt][nt][q] = 0.f;

    auto load_stage = [&](int buf, int chunk) {
        const int k0 = chunk * 64;
        const uint32_t sbase = sb + (uint32_t)buf * STG3 * 2;
#pragma unroll
        for (int t = 0; t < 8; t++) {           // A: 256 rows x 64 cols
            int c = tid + t * 256;              // 0..2047
            int row = c >> 3;
            int kc  = (c & 7) * 8;
            uint32_t so = sbase + (uint32_t)(row * SP3 + kc) * 2;
            size_t goA = (size_t)(m0 + row) * HIDDEN + k0 + kc;
            cpasync16(so,                Ahi + goA);
            cpasync16(so + A3_ELEMS * 2, Alo + goA);
        }
#pragma unroll
        for (int t = 0; t < 4; t++) {           // B: 128 rows x 64 cols
            int c = tid + t * 256;              // 0..1023
            int row = c >> 3;
            int kc  = (c & 7) * 8;
            uint32_t so = sbase + (uint32_t)(2 * A3_ELEMS + row * SP3 + kc) * 2;
            size_t goB = (size_t)(n0 + row) * HIDDEN + k0 + kc;
            cpasync16(so,                Bhi + goB);
            cpasync16(so + B3_ELEMS * 2, Blo + goB);
        }
    };

    load_stage(0, 0);
    CP_COMMIT();

    for (int chunk = 0; chunk < NCH3; chunk++) {
        if (chunk + 1 < NCH3) {
            load_stage((chunk + 1) & 1, chunk + 1);
            CP_COMMIT();
            CP_WAIT(1);
        } else {
            CP_WAIT(0);
        }
        __syncthreads();

        const uint32_t stage = sb + (uint32_t)(chunk & 1) * STG3 * 2;
#pragma unroll
        for (int kk = 0; kk < 4; kk++) {
            uint32_t aH[4][4], aL[4][4], bH[4][4], bL[4][4];
#pragma unroll
            for (int mt = 0; mt < 4; mt++) {
                uint32_t ao = (uint32_t)((wm + mt * 16 + arow) * SP3 + kk * 16 + acol) * 2;
                ldsm_x4(stage + ao, aH[mt]);
                ldsm_x4(stage + A3_ELEMS * 2 + ao, aL[mt]);
            }
#pragma unroll
            for (int nt2 = 0; nt2 < 4; nt2++) {
                uint32_t bo = (uint32_t)(2 * A3_ELEMS + (wn + nt2 * 16 + brow) * SP3 +
                                         kk * 16 + bcol) * 2;
                ldsm_x4(stage + bo, bH[nt2]);
                ldsm_x4(stage + B3_ELEMS * 2 + bo, bL[nt2]);
            }
#pragma unroll
            for (int mt = 0; mt < 4; mt++)
#pragma unroll
                for (int nt = 0; nt < 8; nt++) {
                    uint32_t h0 = bH[nt >> 1][(nt & 1) * 2];
                    uint32_t h1 = bH[nt >> 1][(nt & 1) * 2 + 1];
                    uint32_t l0 = bL[nt >> 1][(nt & 1) * 2];
                    uint32_t l1 = bL[nt >> 1][(nt & 1) * 2 + 1];
                    mma16816(acc[mt][nt], aH[mt], h0, h1);
                    mma16816(acc[mt][nt], aL[mt], h0, h1);
                    mma16816(acc[mt][nt], aH[mt], l0, l1);
                }
        }
        __syncthreads();
    }

    const int erow = lane >> 2;
    const int ecol = (lane & 3) * 2;
#pragma unroll
    for (int mt = 0; mt < 4; mt++) {
#pragma unroll
        for (int nt = 0; nt < 8; nt++) {
            int r = m0 + wm + mt * 16 + erow;
            int c = n0 + wn + nt * 8 + ecol;
            *(float2*)&C[(size_t)r * Ntot + c] =
                make_float2(acc[mt][nt][0], acc[mt][nt][1]);
            *(float2*)&C[(size_t)(r + 8) * Ntot + c] =
                make_float2(acc[mt][nt][2], acc[mt][nt][3]);
        }
    }
}

// ---------------------------------------------------------------------------
// f32 -> bf16 hi/lo split
// ---------------------------------------------------------------------------
__global__ void split_kernel(const float* __restrict__ x,
                             __nv_bfloat16* __restrict__ hi,
                             __nv_bfloat16* __restrict__ lo, int n) {
    int i = blockIdx.x * 256 + threadIdx.x;
    if (i >= n) return;
    float v = x[i];
    __nv_bfloat16 h = __float2bfloat16(v);
    hi[i] = h;
    lo[i] = __float2bfloat16(v - __bfloat162float(h));
}

// ---------------------------------------------------------------------------
// W [K=4096][N] f32 -> W^T hi/lo [N][4096] bf16
// ---------------------------------------------------------------------------
__global__ __launch_bounds__(256) void transpose_split(
    const float* __restrict__ W, __nv_bfloat16* __restrict__ hi,
    __nv_bfloat16* __restrict__ lo, int N) {
    __shared__ float t[32][33];
    const int n0 = blockIdx.x * 32;
    const int k0 = blockIdx.y * 32;
    const int tx = threadIdx.x;
    for (int r = threadIdx.y; r < 32; r += 8)
        t[r][tx] = W[(size_t)(k0 + r) * N + n0 + tx];
    __syncthreads();
    for (int r = threadIdx.y; r < 32; r += 8) {
        float v = t[tx][r];
        __nv_bfloat16 h = __float2bfloat16(v);
        size_t o = (size_t)(n0 + r) * HIDDEN + k0 + tx;
        hi[o] = h;
        lo[o] = __float2bfloat16(v - __bfloat162float(h));
    }
}

// ---------------------------------------------------------------------------
// RMSNorm + RoPE for Q: pre-scaled bf16 hi/lo splits [h][s][d]
// ---------------------------------------------------------------------------
__global__ __launch_bounds__(128) void norm_rope_q(
    const float* __restrict__ inp, const float* __restrict__ w,
    __nv_bfloat16* __restrict__ qhi, __nv_bfloat16* __restrict__ qlo) {
    const int s = blockIdx.x;
    const int h = blockIdx.y;
    const int d = threadIdx.x;

    float x = inp[((size_t)s * NHEADS + h) * HDIM + d];
    float ss = x * x;
#pragma unroll
    for (int o = 16; o; o >>= 1) ss += __shfl_xor_sync(0xffffffffu, ss, o);
    __shared__ float wss[4];
    __shared__ float xs[HDIM];
    if ((d & 31) == 0) wss[d >> 5] = ss;
    __syncthreads();
    float var = (wss[0] + wss[1] + wss[2] + wss[3]) * (1.0f / 128.0f);
    xs[d] = x * rsqrtf(var + 1e-6f) * w[d];
    __syncthreads();

    if (d < 64) {
        const float scale = 0.08838834764831845f;
        float p = (float)s;
        float e = (float)(2 * d) * (1.0f / 128.0f);
        float invf = powf(1000000.0f, -e);
        float si, c;
        sincosf(p * invf, &si, &c);
        float x1 = xs[d], x2 = xs[d + 64];
        float r1 = (x1 * c - x2 * si) * scale;
        float r2 = (x2 * c + x1 * si) * scale;
        size_t base = ((size_t)h * S_LEN + s) * HDIM;
        __nv_bfloat16 h1 = __float2bfloat16(r1);
        __nv_bfloat16 h2 = __float2bfloat16(r2);
        qhi[base + d]      = h1;
        qhi[base + d + 64] = h2;
        qlo[base + d]      = __float2bfloat16(r1 - __bfloat162float(h1));
        qlo[base + d + 64] = __float2bfloat16(r2 - __bfloat162float(h2));
    }
}

// ---------------------------------------------------------------------------
// RMSNorm + RoPE for K: f32 new_k [kv][s][d] + bf16 hi/lo splits
// ---------------------------------------------------------------------------
__global__ __launch_bounds__(128) void norm_rope_k(
    const float* __restrict__ inp, const float* __restrict__ w,
    float* __restrict__ outf,
    __nv_bfloat16* __restrict__ khi, __nv_bfloat16* __restrict__ klo) {
    const int s = blockIdx.x;
    const int h = blockIdx.y;
    const int d = threadIdx.x;

    float x = inp[((size_t)s * NKV + h) * HDIM + d];
    float ss = x * x;
#pragma unroll
    for (int o = 16; o; o >>= 1) ss += __shfl_xor_sync(0xffffffffu, ss, o);
    __shared__ float wss[4];
    __shared__ float xs[HDIM];
    if ((d & 31) == 0) wss[d >> 5] = ss;
    __syncthreads();
    float var = (wss[0] + wss[1] + wss[2] + wss[3]) * (1.0f / 128.0f);
    xs[d] = x * rsqrtf(var + 1e-6f) * w[d];
    __syncthreads();

    if (d < 64) {
        float p = (float)s;
        float e = (float)(2 * d) * (1.0f / 128.0f);
        float invf = powf(1000000.0f, -e);
        float si, c;
        sincosf(p * invf, &si, &c);
        float x1 = xs[d], x2 = xs[d + 64];
        float r1 = x1 * c - x2 * si;
        float r2 = x2 * c + x1 * si;
        size_t base = ((size_t)h * S_LEN + s) * HDIM;
        outf[base + d]      = r1;
        outf[base + d + 64] = r2;
        __nv_bfloat16 h1 = __float2bfloat16(r1);
        __nv_bfloat16 h2 = __float2bfloat16(r2);
        khi[base + d]      = h1;
        khi[base + d + 64] = h2;
        klo[base + d]      = __float2bfloat16(r1 - __bfloat162float(h1));
        klo[base + d + 64] = __float2bfloat16(r2 - __bfloat162float(h2));
    }
}

// ---------------------------------------------------------------------------
// V: [s][kv*128+d] -> new_v f32 [kv][s][d] + V^T splits [kv][d][s] bf16
// ---------------------------------------------------------------------------
__global__ __launch_bounds__(256) void v_split_transpose(
    const float* __restrict__ vt, float* __restrict__ outf,
    __nv_bfloat16* __restrict__ vthi, __nv_bfloat16* __restrict__ vtlo) {
    __shared__ float t[32][33];
    const int kv = blockIdx.z;
    const int s0 = blockIdx.x * 32;
    const int d0 = blockIdx.y * 32;
    const int tx = threadIdx.x;
    for (int r = threadIdx.y; r < 32; r += 8) {
        float v = vt[(size_t)(s0 + r) * (NKV * HDIM) + kv * HDIM + d0 + tx];
        t[r][tx] = v;
        outf[((size_t)kv * S_LEN + s0 + r) * HDIM + d0 + tx] = v;
    }
    __syncthreads();
    for (int r = threadIdx.y; r < 32; r += 8) {
        float v = t[tx][r];
        __nv_bfloat16 h = __float2bfloat16(v);
        size_t o = ((size_t)kv * HDIM + d0 + r) * S_LEN + s0 + tx;
        vthi[o] = h;
        vtlo[o] = __float2bfloat16(v - __bfloat162float(h));
    }
}

// ---------------------------------------------------------------------------
// Tensor-core attention (unchanged — passing)
// ---------------------------------------------------------------------------
#define AT_QP 136
#define AT_VP 72
#define SQHI 0
#define SQLO (128 * AT_QP)
#define SKHI (2 * 128 * AT_QP)
#define SKLO (SKHI + 64 * AT_QP)
#define SVHI (SKLO + 64 * AT_QP)
#define SVLO (SVHI + 128 * AT_VP)
#define SPHI (SVLO + 128 * AT_VP)
#define SPLO (SPHI + 128 * AT_VP)
#define AT_SMEM_ELEMS (SPLO + 128 * AT_VP)
#define AT_SMEM_BYTES (AT_SMEM_ELEMS * 2)

__global__ __launch_bounds__(256) void attention_mma(
    const __nv_bfloat16* __restrict__ qhi, const __nv_bfloat16* __restrict__ qlo,
    const __nv_bfloat16* __restrict__ khi, const __nv_bfloat16* __restrict__ klo,
    const __nv_bfloat16* __restrict__ vthi, const __nv_bfloat16* __restrict__ vtlo,
    float* __restrict__ probs,
    __nv_bfloat16* __restrict__ ahi, __nv_bfloat16* __restrict__ alo) {
    extern __shared__ __align__(16) __nv_bfloat16 smbuf[];
    const uint32_t sb = smem_to_u32(smbuf);
    const int h   = blockIdx.y;
    const int kvh = h >> 2;
    const int q0  = (int)(gridDim.x - 1 - blockIdx.x) * 128;
    const int tid = threadIdx.x;
    const int lane = tid & 31;
    const int wid  = tid >> 5;
    const int quad = lane >> 3, wi = lane & 7;
    const int wm   = wid * 16;
    const int arow = (quad & 1) * 8 + wi, acol = (quad >> 1) * 8;
    const int brow = (quad >> 1) * 8 + wi, bcol = (quad & 1) * 8;
    const int erow = lane >> 2, fc = (lane & 3) * 2;
    const int grow0 = q0 + wm + erow;
    const int grow1 = grow0 + 8;

#pragma unroll
    for (int i = 0; i < 8; i++) {
        int idx = tid + i * 256;
        int row = idx >> 4, ch = idx & 15;
        size_t go = ((size_t)h * S_LEN + q0 + row) * HDIM + ch * 8;
        cpasync16(sb + (uint32_t)(SQHI + row * AT_QP + ch * 8) * 2, qhi + go);
        cpasync16(sb + (uint32_t)(SQLO + row * AT_QP + ch * 8) * 2, qlo + go);
    }
    CP_COMMIT(); CP_WAIT(0);
    __syncthreads();

    const int nvalid = ((q0 + 127) >> 6) + 1;
    float m0 = -1e30f, m1 = -1e30f, l0 = 0.f, l1 = 0.f;

    for (int jt = 0; jt < nvalid; jt++) {
        const int c0 = jt * 64;
#pragma unroll
        for (int i = 0; i < 4; i++) {
            int idx = tid + i * 256;
            int row = idx >> 4, ch = idx & 15;
            size_t go = ((size_t)kvh * S_LEN + c0 + row) * HDIM + ch * 8;
            cpasync16(sb + (uint32_t)(SKHI + row * AT_QP + ch * 8) * 2, khi + go);
            cpasync16(sb + (uint32_t)(SKLO + row * AT_QP + ch * 8) * 2, klo + go);
        }
        CP_COMMIT(); CP_WAIT(0);
        __syncthreads();

        float s[8][4];
#pragma unroll
        for (int nt = 0; nt < 8; nt++)
#pragma unroll
            for (int q = 0; q < 4; q++) s[nt][q] = 0.f;

#pragma unroll
        for (int term = 0; term < 3; term++) {
            const int qb = (term == 1) ? SQLO : SQHI;
            const int kb = (term == 2) ? SKLO : SKHI;
#pragma unroll
            for (int kk = 0; kk < 8; kk++) {
                uint32_t a[4], b[4][4];
                ldsm_x4(sb + (uint32_t)(qb + (wm + arow) * AT_QP + kk * 16 + acol) * 2, a);
#pragma unroll
                for (int nt2 = 0; nt2 < 4; nt2++)
                    ldsm_x4(sb + (uint32_t)(kb + (nt2 * 16 + brow) * AT_QP + kk * 16 + bcol) * 2, b[nt2]);
#pragma unroll
                for (int nt = 0; nt < 8; nt++)
                    mma16816(s[nt], a, b[nt >> 1][(nt & 1) * 2], b[nt >> 1][(nt & 1) * 2 + 1]);
            }
        }

        float tm0 = -1e30f, tm1 = -1e30f;
#pragma unroll
        for (int nt = 0; nt < 8; nt++) {
            int cb = c0 + nt * 8 + fc;
            if (cb     > grow0) s[nt][0] = -1e30f;
            if (cb + 1 > grow0) s[nt][1] = -1e30f;
            if (cb     > grow1) s[nt][2] = -1e30f;
            if (cb + 1 > grow1) s[nt][3] = -1e30f;
            tm0 = fmaxf(tm0, fmaxf(s[nt][0], s[nt][1]));
            tm1 = fmaxf(tm1, fmaxf(s[nt][2], s[nt][3]));
        }
        tm0 = fmaxf(tm0, __shfl_xor_sync(0xffffffffu, tm0, 1));
        tm0 = fmaxf(tm0, __shfl_xor_sync(0xffffffffu, tm0, 2));
        tm1 = fmaxf(tm1, __shfl_xor_sync(0xffffffffu, tm1, 1));
        tm1 = fmaxf(tm1, __shfl_xor_sync(0xffffffffu, tm1, 2));
        float mn0 = fmaxf(m0, tm0), mn1 = fmaxf(m1, tm1);
        float su0 = 0.f, su1 = 0.f;
#pragma unroll
        for (int nt = 0; nt < 8; nt++) {
            su0 += __expf(s[nt][0] - mn0) + __expf(s[nt][1] - mn0);
            su1 += __expf(s[nt][2] - mn1) + __expf(s[nt][3] - mn1);
        }
        su0 += __shfl_xor_sync(0xffffffffu, su0, 1);
        su0 += __shfl_xor_sync(0xffffffffu, su0, 2);
        su1 += __shfl_xor_sync(0xffffffffu, su1, 1);
        su1 += __shfl_xor_sync(0xffffffffu, su1, 2);
        l0 = l0 * __expf(m0 - mn0) + su0; m0 = mn0;
        l1 = l1 * __expf(m1 - mn1) + su1; m1 = mn1;
        __syncthreads();
    }
    const float li0 = 1.0f / l0, li1 = 1.0f / l1;

    float o[16][4];
#pragma unroll
    for (int nt = 0; nt < 16; nt++)
#pragma unroll
        for (int q = 0; q < 4; q++) o[nt][q] = 0.f;

    for (int jt = 0; jt < S_LEN / 64; jt++) {
        const int c0 = jt * 64;
        if (c0 > q0 + 127) {
            float2 z = make_float2(0.f, 0.f);
#pragma unroll
            for (int nt = 0; nt < 8; nt++) {
                int col = c0 + nt * 8 + fc;
                *(float2*)&probs[((size_t)h * S_LEN + grow0) * S_LEN + col] = z;
                *(float2*)&probs[((size_t)h * S_LEN + grow1) * S_LEN + col] = z;
            }
            continue;
        }
#pragma unroll
        for (int i = 0; i < 4; i++) {
            int idx = tid + i * 256;
            int row = idx >> 4, ch = idx & 15;
            size_t go = ((size_t)kvh * S_LEN + c0 + row) * HDIM + ch * 8;
            cpasync16(sb + (uint32_t)(SKHI + row * AT_QP + ch * 8) * 2, khi + go);
            cpasync16(sb + (uint32_t)(SKLO + row * AT_QP + ch * 8) * 2, klo + go);
        }
#pragma unroll
        for (int i = 0; i < 4; i++) {
            int idx = tid + i * 256;
            int row = idx >> 3, ch = idx & 7;
            size_t go = ((size_t)kvh * HDIM + row) * S_LEN + c0 + ch * 8;
            cpasync16(sb + (uint32_t)(SVHI + row * AT_VP + ch * 8) * 2, vthi + go);
            cpasync16(sb + (uint32_t)(SVLO + row * AT_VP + ch * 8) * 2, vtlo + go);
        }
        CP_COMMIT(); CP_WAIT(0);
        __syncthreads();

        float s[8][4];
#pragma unroll
        for (int nt = 0; nt < 8; nt++)
#pragma unroll
            for (int q = 0; q < 4; q++) s[nt][q] = 0.f;
#pragma unroll
        for (int term = 0; term < 3; term++) {
            const int qb = (term == 1) ? SQLO : SQHI;
            const int kb = (term == 2) ? SKLO : SKHI;
#pragma unroll
            for (int kk = 0; kk < 8; kk++) {
                uint32_t a[4], b[4][4];
                ldsm_x4(sb + (uint32_t)(qb + (wm + arow) * AT_QP + kk * 16 + acol) * 2, a);
#pragma unroll
                for (int nt2 = 0; nt2 < 4; nt2++)
                    ldsm_x4(sb + (uint32_t)(kb + (nt2 * 16 + brow) * AT_QP + kk * 16 + bcol) * 2, b[nt2]);
#pragma unroll
                for (int nt = 0; nt < 8; nt++)
                    mma16816(s[nt], a, b[nt >> 1][(nt & 1) * 2], b[nt >> 1][(nt & 1) * 2 + 1]);
            }
        }

        const int pr0 = wm + erow, pr1 = pr0 + 8;
#pragma unroll
        for (int nt = 0; nt < 8; nt++) {
            int cb = c0 + nt * 8 + fc;
            float sv0 = (cb     > grow0) ? -1e30f : s[nt][0];
            float sv1 = (cb + 1 > grow0) ? -1e30f : s[nt][1];
            float sv2 = (cb     > grow1) ? -1e30f : s[nt][2];
            float sv3 = (cb + 1 > grow1) ? -1e30f : s[nt][3];
            float p0 = __expf(sv0 - m0) * li0;
            float p1 = __expf(sv1 - m0) * li0;
            float p2 = __expf(sv2 - m1) * li1;
            float p3 = __expf(sv3 - m1) * li1;
            *(float2*)&probs[((size_t)h * S_LEN + grow0) * S_LEN + cb] = make_float2(p0, p1);
            *(float2*)&probs[((size_t)h * S_LEN + grow1) * S_LEN + cb] = make_float2(p2, p3);
            int cl = nt * 8 + fc;
            __nv_bfloat16 h0 = __float2bfloat16(p0), h1 = __float2bfloat16(p1);
            __nv_bfloat16 h2 = __float2bfloat16(p2), h3 = __float2bfloat16(p3);
            __nv_bfloat162 hp01; hp01.x = h0; hp01.y = h1;
            __nv_bfloat162 hp23; hp23.x = h2; hp23.y = h3;
            __nv_bfloat162 lp01, lp23;
            lp01.x = __float2bfloat16(p0 - __bfloat162float(h0));
            lp01.y = __float2bfloat16(p1 - __bfloat162float(h1));
            lp23.x = __float2bfloat16(p2 - __bfloat162float(h2));
            lp23.y = __float2bfloat16(p3 - __bfloat162float(h3));
            *(__nv_bfloat162*)&smbuf[SPHI + pr0 * AT_VP + cl] = hp01;
            *(__nv_bfloat162*)&smbuf[SPHI + pr1 * AT_VP + cl] = hp23;
            *(__nv_bfloat162*)&smbuf[SPLO + pr0 * AT_VP + cl] = lp01;
            *(__nv_bfloat162*)&smbuf[SPLO + pr1 * AT_VP + cl] = lp23;
        }
        __syncwarp();

#pragma unroll
        for (int term = 0; term < 3; term++) {
            const int pb = (term == 1) ? SPLO : SPHI;
            const int vb = (term == 2) ? SVLO : SVHI;
#pragma unroll
            for (int kk = 0; kk < 4; kk++) {
                uint32_t a[4], b[8][4];
                ldsm_x4(sb + (uint32_t)(pb + (wm + arow) * AT_VP + kk * 16 + acol) * 2, a);
#pragma unroll
                for (int nt2 = 0; nt2 < 8; nt2++)
                    ldsm_x4(sb + (uint32_t)(vb + (nt2 * 16 + brow) * AT_VP + kk * 16 + bcol) * 2, b[nt2]);
#pragma unroll
                for (int nt = 0; nt < 16; nt++)
                    mma16816(o[nt], a, b[nt >> 1][(nt & 1) * 2], b[nt >> 1][(nt & 1) * 2 + 1]);
            }
        }
        __syncthreads();
    }

#pragma unroll
    for (int nt = 0; nt < 16; nt++) {
        int d = nt * 8 + fc;
        size_t b0 = (size_t)grow0 * HIDDEN + h * HDIM + d;
        size_t b1 = (size_t)grow1 * HIDDEN + h * HDIM + d;
        float v0 = o[nt][0], v1 = o[nt][1], v2 = o[nt][2], v3 = o[nt][3];
        __nv_bfloat16 h0 = __float2bfloat16(v0), h1 = __float2bfloat16(v1);
        __nv_bfloat16 h2 = __float2bfloat16(v2), h3 = __float2bfloat16(v3);
        __nv_bfloat162 hp01; hp01.x = h0; hp01.y = h1;
        __nv_bfloat162 hp23; hp23.x = h2; hp23.y = h3;
        __nv_bfloat162 lp01, lp23;
        lp01.x = __float2bfloat16(v0 - __bfloat162float(h0));
        lp01.y = __float2bfloat16(v1 - __bfloat162float(h1));
        lp23.x = __float2bfloat16(v2 - __bfloat162float(h2));
        lp23.y = __float2bfloat16(v3 - __bfloat162float(h3));
        *(__nv_bfloat162*)&ahi[b0] = hp01;
        *(__nv_bfloat162*)&ahi[b1] = hp23;
        *(__nv_bfloat162*)&alo[b0] = lp01;
        *(__nv_bfloat162*)&alo[b1] = lp23;
    }
}

// ---------------------------------------------------------------------------
// Launch
// ---------------------------------------------------------------------------
extern "C" void kernel_launch(void* const* d_in, const int* in_sizes, int n_in,
                              void* d_out, int out_size) {
    const float* X  = (const float*)d_in[0];
    const float* Wq = (const float*)d_in[2];
    const float* Wk = (const float*)d_in[3];
    const float* Wv = (const float*)d_in[4];
    const float* Wo = (const float*)d_in[5];
    const float* qw = (const float*)d_in[6];
    const float* kw = (const float*)d_in[7];

    float* out   = (float*)d_out;
    float* new_k = out + (size_t)S_LEN * HIDDEN;
    float* new_v = new_k + (size_t)NKV * S_LEN * HDIM;
    float* probs = new_v + (size_t)NKV * S_LEN * HDIM;

    float *qtmp, *ktmp, *vtmp;
    __nv_bfloat16 *xhi, *xlo, *ahi, *alo, *qhi, *qlo, *khi, *klo, *vthi, *vtlo;
    __nv_bfloat16 *wqh, *wql, *wkh, *wkl, *wvh, *wvl, *woh, *wol;
    cudaGetSymbolAddress((void**)&qtmp, g_qtmp);
    cudaGetSymbolAddress((void**)&ktmp, g_ktmp);
    cudaGetSymbolAddress((void**)&vtmp, g_vtmp);
    cudaGetSymbolAddress((void**)&xhi, g_xhi);
    cudaGetSymbolAddress((void**)&xlo, g_xlo);
    cudaGetSymbolAddress((void**)&ahi, g_ahi);
    cudaGetSymbolAddress((void**)&alo, g_alo);
    cudaGetSymbolAddress((void**)&qhi, g_qhi);
    cudaGetSymbolAddress((void**)&qlo, g_qlo);
    cudaGetSymbolAddress((void**)&khi, g_khi);
    cudaGetSymbolAddress((void**)&klo, g_klo);
    cudaGetSymbolAddress((void**)&vthi, g_vthi);
    cudaGetSymbolAddress((void**)&vtlo, g_vtlo);
    cudaGetSymbolAddress((void**)&wqh, g_wqthi);
    cudaGetSymbolAddress((void**)&wql, g_wqtlo);
    cudaGetSymbolAddress((void**)&wkh, g_wkthi);
    cudaGetSymbolAddress((void**)&wkl, g_wktlo);
    cudaGetSymbolAddress((void**)&wvh, g_wvthi);
    cudaGetSymbolAddress((void**)&wvl, g_wvtlo);
    cudaGetSymbolAddress((void**)&woh, g_wothi);
    cudaGetSymbolAddress((void**)&wol, g_wotlo);

    // ---- conversions ----
    {
        int n = S_LEN * HIDDEN;
        split_kernel<<<(n + 255) / 256, 256>>>(X, xhi, xlo, n);
    }
    transpose_split<<<dim3(HIDDEN / 32, HIDDEN / 32), dim3(32, 8)>>>(Wq, wqh, wql, HIDDEN);
    transpose_split<<<dim3((NKV * HDIM) / 32, HIDDEN / 32), dim3(32, 8)>>>(Wk, wkh, wkl, NKV * HDIM);
    transpose_split<<<dim3((NKV * HDIM) / 32, HIDDEN / 32), dim3(32, 8)>>>(Wv, wvh, wvl, NKV * HDIM);
    transpose_split<<<dim3(HIDDEN / 32, HIDDEN / 32), dim3(32, 8)>>>(Wo, woh, wol, HIDDEN);

    // ---- Q, K, V projections fused in one launch ----
    cudaFuncSetAttribute(gemm_mma3, cudaFuncAttributeMaxDynamicSharedMemorySize,
                         GEMM3_SMEM);
    gemm_mma3<<<dim3(HIDDEN / 128, S_LEN / 256, 3), 256, GEMM3_SMEM>>>(
        xhi, xlo,
        wqh, wql, qtmp, HIDDEN,
        wkh, wkl, ktmp, NKV * HDIM,
        wvh, wvl, vtmp, NKV * HDIM);

    // ---- RMSNorm + RoPE + splits ----
    norm_rope_q<<<dim3(S_LEN, NHEADS), 128>>>(qtmp, qw, qhi, qlo);
    norm_rope_k<<<dim3(S_LEN, NKV), 128>>>(ktmp, kw, new_k, khi, klo);

    // ---- V transpose + split ----
    v_split_transpose<<<dim3(S_LEN / 32, HDIM / 32, NKV), dim3(32, 8)>>>(
        vtmp, new_v, vthi, vtlo);

    // ---- attention ----
    cudaFuncSetAttribute(attention_mma,
                         cudaFuncAttributeMaxDynamicSharedMemorySize, AT_SMEM_BYTES);
    attention_mma<<<dim3(S_LEN / 128, NHEADS), 256, AT_SMEM_BYTES>>>(
        qhi, qlo, khi, klo, vthi, vtlo, probs, ahi, alo);

    // ---- O projection ----
    gemm_mma3<<<dim3(HIDDEN / 128, S_LEN / 256, 1), 256, GEMM3_SMEM>>>(
        ahi, alo,
        woh, wol, out, HIDDEN,
        woh, wol, out, HIDDEN,
        woh, wol, out, HIDDEN);
}

// round 8
// speedup vs baseline: 3.1787x; 1.0504x over previous
#include <cuda_runtime.h>
#include <cuda_bf16.h>
#include <math.h>
#include <stdint.h>

// ---------------------------------------------------------------------------
// Problem constants
// ---------------------------------------------------------------------------
#define S_LEN   2048
#define HIDDEN  4096
#define NHEADS  32
#define NKV     8
#define HDIM    128

// ---------------------------------------------------------------------------
// Device scratch
// ---------------------------------------------------------------------------
__device__ float g_qtmp[S_LEN * NHEADS * HDIM];
__device__ float g_ktmp[S_LEN * NKV * HDIM];
__device__ float g_vtmp[S_LEN * NKV * HDIM];

__device__ __nv_bfloat16 g_xhi[S_LEN * HIDDEN];
__device__ __nv_bfloat16 g_xlo[S_LEN * HIDDEN];
__device__ __nv_bfloat16 g_ahi[S_LEN * HIDDEN];
__device__ __nv_bfloat16 g_alo[S_LEN * HIDDEN];
__device__ __nv_bfloat16 g_qhi[NHEADS * S_LEN * HDIM];   // [h][s][d], pre-scaled
__device__ __nv_bfloat16 g_qlo[NHEADS * S_LEN * HDIM];
__device__ __nv_bfloat16 g_khi[NKV * S_LEN * HDIM];      // [kv][s][d]
__device__ __nv_bfloat16 g_klo[NKV * S_LEN * HDIM];
__device__ __nv_bfloat16 g_vthi[NKV * HDIM * S_LEN];     // [kv][d][s]
__device__ __nv_bfloat16 g_vtlo[NKV * HDIM * S_LEN];
__device__ __nv_bfloat16 g_wqthi[HIDDEN * HIDDEN];
__device__ __nv_bfloat16 g_wqtlo[HIDDEN * HIDDEN];
__device__ __nv_bfloat16 g_wkthi[(NKV * HDIM) * HIDDEN];
__device__ __nv_bfloat16 g_wktlo[(NKV * HDIM) * HIDDEN];
__device__ __nv_bfloat16 g_wvthi[(NKV * HDIM) * HIDDEN];
__device__ __nv_bfloat16 g_wvtlo[(NKV * HDIM) * HIDDEN];
__device__ __nv_bfloat16 g_wothi[HIDDEN * HIDDEN];
__device__ __nv_bfloat16 g_wotlo[HIDDEN * HIDDEN];

// ---------------------------------------------------------------------------
// Low-level helpers
// ---------------------------------------------------------------------------
__device__ __forceinline__ uint32_t smem_to_u32(const void* p) {
    uint32_t a;
    asm("{ .reg .u64 t; cvta.to.shared.u64 t, %1; cvt.u32.u64 %0, t; }"
        : "=r"(a) : "l"(p));
    return a;
}
__device__ __forceinline__ void cpasync16(uint32_t saddr, const void* g) {
    asm volatile("cp.async.cg.shared.global [%0], [%1], 16;"
                 :: "r"(saddr), "l"(g));
}
#define CP_COMMIT() asm volatile("cp.async.commit_group;" ::: "memory")
#define CP_WAIT(n)  asm volatile("cp.async.wait_group %0;" :: "n"(n) : "memory")

__device__ __forceinline__ void ldsm_x4(uint32_t addr, uint32_t r[4]) {
    asm volatile("ldmatrix.sync.aligned.m8n8.x4.shared.b16 {%0,%1,%2,%3}, [%4];"
        : "=r"(r[0]), "=r"(r[1]), "=r"(r[2]), "=r"(r[3]) : "r"(addr));
}
__device__ __forceinline__ void mma16816(float d[4], const uint32_t a[4],
                                         const uint32_t b0, const uint32_t b1) {
    asm volatile(
        "mma.sync.aligned.m16n8k16.row.col.f32.bf16.bf16.f32 "
        "{%0,%1,%2,%3}, {%4,%5,%6,%7}, {%8,%9}, {%0,%1,%2,%3};"
        : "+f"(d[0]), "+f"(d[1]), "+f"(d[2]), "+f"(d[3])
        : "r"(a[0]), "r"(a[1]), "r"(a[2]), "r"(a[3]), "r"(b0), "r"(b1));
}

// ---------------------------------------------------------------------------
// Projection GEMM v4: 256x128 tile, BK=64, single-sync multistage mainloop,
// serpentine tile swizzle, exact-tile flat indexing, hi/lo 3-term.
// ---------------------------------------------------------------------------
#define SP3       72
#define A3_ELEMS  (256 * SP3)
#define B3_ELEMS  (128 * SP3)
#define STG3      (2 * A3_ELEMS + 2 * B3_ELEMS)
#define GEMM3_SMEM (2 * STG3 * 2)
#define NCH3      (HIDDEN / 64)

__global__ __launch_bounds__(256) void gemm_mma3(
    const __nv_bfloat16* __restrict__ Ahi, const __nv_bfloat16* __restrict__ Alo,
    const __nv_bfloat16* __restrict__ Bh0, const __nv_bfloat16* __restrict__ Bl0,
    float* __restrict__ C0, int N0,
    const __nv_bfloat16* __restrict__ Bh1, const __nv_bfloat16* __restrict__ Bl1,
    float* __restrict__ C1, int N1,
    const __nv_bfloat16* __restrict__ Bh2, const __nv_bfloat16* __restrict__ Bl2,
    float* __restrict__ C2, int N2) {
    extern __shared__ __align__(16) __nv_bfloat16 smbuf[];
    const __nv_bfloat16* Bhi;
    const __nv_bfloat16* Blo;
    float* C;
    int Ntot;
    if (blockIdx.z == 0)      { Bhi = Bh0; Blo = Bl0; C = C0; Ntot = N0; }
    else if (blockIdx.z == 1) { Bhi = Bh1; Blo = Bl1; C = C1; Ntot = N1; }
    else                      { Bhi = Bh2; Blo = Bl2; C = C2; Ntot = N2; }

    // serpentine swizzle over exact tile count
    const int nx_eff = Ntot >> 7;                 // N / 128
    const int flat = blockIdx.y * gridDim.x + blockIdx.x;
    if (flat >= nx_eff * (S_LEN / 256)) return;
    const int per = 4 * nx_eff;
    const int grp = flat / per, rem = flat % per;
    const int m0 = (grp * 4 + (rem & 3)) * 256;
    const int n0 = (rem >> 2) * 128;

    const uint32_t sb = smem_to_u32(smbuf);
    const int tid  = threadIdx.x;
    const int lane = tid & 31;
    const int wid  = tid >> 5;
    const int wm = (wid >> 1) * 64;
    const int wn = (wid & 1) * 64;
    const int quad = lane >> 3;
    const int wi   = lane & 7;
    const int arow = (quad & 1) * 8 + wi;
    const int acol = (quad >> 1) * 8;
    const int brow = (quad >> 1) * 8 + wi;
    const int bcol = (quad & 1) * 8;

    float acc[4][8][4];
#pragma unroll
    for (int mt = 0; mt < 4; mt++)
#pragma unroll
        for (int nt = 0; nt < 8; nt++)
#pragma unroll
            for (int q = 0; q < 4; q++) acc[mt][nt][q] = 0.f;

    auto load_stage = [&](int buf, int chunk) {
        const int k0 = chunk * 64;
        const uint32_t sbase = sb + (uint32_t)buf * STG3 * 2;
#pragma unroll
        for (int t = 0; t < 8; t++) {
            int c = tid + t * 256;
            int row = c >> 3;
            int kc  = (c & 7) * 8;
            uint32_t so = sbase + (uint32_t)(row * SP3 + kc) * 2;
            size_t goA = (size_t)(m0 + row) * HIDDEN + k0 + kc;
            cpasync16(so,                Ahi + goA);
            cpasync16(so + A3_ELEMS * 2, Alo + goA);
        }
#pragma unroll
        for (int t = 0; t < 4; t++) {
            int c = tid + t * 256;
            int row = c >> 3;
            int kc  = (c & 7) * 8;
            uint32_t so = sbase + (uint32_t)(2 * A3_ELEMS + row * SP3 + kc) * 2;
            size_t goB = (size_t)(n0 + row) * HIDDEN + k0 + kc;
            cpasync16(so,                Bhi + goB);
            cpasync16(so + B3_ELEMS * 2, Blo + goB);
        }
    };

    load_stage(0, 0);
    CP_COMMIT();

    for (int chunk = 0; chunk < NCH3; chunk++) {
        CP_WAIT(0);             // chunk's data (prefetched during prev compute)
        __syncthreads();        // visibility + protects buffer being overwritten
        if (chunk + 1 < NCH3) {
            load_stage((chunk + 1) & 1, chunk + 1);
            CP_COMMIT();
        }
        const uint32_t stage = sb + (uint32_t)(chunk & 1) * STG3 * 2;
#pragma unroll
        for (int kk = 0; kk < 4; kk++) {
            uint32_t aH[4][4], aL[4][4], bH[4][4], bL[4][4];
#pragma unroll
            for (int mt = 0; mt < 4; mt++) {
                uint32_t ao = (uint32_t)((wm + mt * 16 + arow) * SP3 + kk * 16 + acol) * 2;
                ldsm_x4(stage + ao, aH[mt]);
                ldsm_x4(stage + A3_ELEMS * 2 + ao, aL[mt]);
            }
#pragma unroll
            for (int nt2 = 0; nt2 < 4; nt2++) {
                uint32_t bo = (uint32_t)(2 * A3_ELEMS + (wn + nt2 * 16 + brow) * SP3 +
                                         kk * 16 + bcol) * 2;
                ldsm_x4(stage + bo, bH[nt2]);
                ldsm_x4(stage + B3_ELEMS * 2 + bo, bL[nt2]);
            }
#pragma unroll
            for (int mt = 0; mt < 4; mt++)
#pragma unroll
                for (int nt = 0; nt < 8; nt++) {
                    uint32_t h0 = bH[nt >> 1][(nt & 1) * 2];
                    uint32_t h1 = bH[nt >> 1][(nt & 1) * 2 + 1];
                    uint32_t l0 = bL[nt >> 1][(nt & 1) * 2];
                    uint32_t l1 = bL[nt >> 1][(nt & 1) * 2 + 1];
                    mma16816(acc[mt][nt], aH[mt], h0, h1);
                    mma16816(acc[mt][nt], aL[mt], h0, h1);
                    mma16816(acc[mt][nt], aH[mt], l0, l1);
                }
        }
    }

    __syncthreads();
    const int erow = lane >> 2;
    const int ecol = (lane & 3) * 2;
#pragma unroll
    for (int mt = 0; mt < 4; mt++) {
#pragma unroll
        for (int nt = 0; nt < 8; nt++) {
            int r = m0 + wm + mt * 16 + erow;
            int c = n0 + wn + nt * 8 + ecol;
            *(float2*)&C[(size_t)r * Ntot + c] =
                make_float2(acc[mt][nt][0], acc[mt][nt][1]);
            *(float2*)&C[(size_t)(r + 8) * Ntot + c] =
                make_float2(acc[mt][nt][2], acc[mt][nt][3]);
        }
    }
}

// ---------------------------------------------------------------------------
// f32 -> bf16 hi/lo split
// ---------------------------------------------------------------------------
__global__ void split_kernel(const float* __restrict__ x,
                             __nv_bfloat16* __restrict__ hi,
                             __nv_bfloat16* __restrict__ lo, int n) {
    int i = blockIdx.x * 256 + threadIdx.x;
    if (i >= n) return;
    float v = x[i];
    __nv_bfloat16 h = __float2bfloat16(v);
    hi[i] = h;
    lo[i] = __float2bfloat16(v - __bfloat162float(h));
}

// ---------------------------------------------------------------------------
// W [K=4096][N] f32 -> W^T hi/lo [N][4096] bf16
// ---------------------------------------------------------------------------
__global__ __launch_bounds__(256) void transpose_split(
    const float* __restrict__ W, __nv_bfloat16* __restrict__ hi,
    __nv_bfloat16* __restrict__ lo, int N) {
    __shared__ float t[32][33];
    const int n0 = blockIdx.x * 32;
    const int k0 = blockIdx.y * 32;
    const int tx = threadIdx.x;
    for (int r = threadIdx.y; r < 32; r += 8)
        t[r][tx] = W[(size_t)(k0 + r) * N + n0 + tx];
    __syncthreads();
    for (int r = threadIdx.y; r < 32; r += 8) {
        float v = t[tx][r];
        __nv_bfloat16 h = __float2bfloat16(v);
        size_t o = (size_t)(n0 + r) * HIDDEN + k0 + tx;
        hi[o] = h;
        lo[o] = __float2bfloat16(v - __bfloat162float(h));
    }
}

// ---------------------------------------------------------------------------
// RMSNorm + RoPE for Q (pre-scaled hi/lo splits)
// ---------------------------------------------------------------------------
__global__ __launch_bounds__(128) void norm_rope_q(
    const float* __restrict__ inp, const float* __restrict__ w,
    __nv_bfloat16* __restrict__ qhi, __nv_bfloat16* __restrict__ qlo) {
    const int s = blockIdx.x;
    const int h = blockIdx.y;
    const int d = threadIdx.x;

    float x = inp[((size_t)s * NHEADS + h) * HDIM + d];
    float ss = x * x;
#pragma unroll
    for (int o = 16; o; o >>= 1) ss += __shfl_xor_sync(0xffffffffu, ss, o);
    __shared__ float wss[4];
    __shared__ float xs[HDIM];
    if ((d & 31) == 0) wss[d >> 5] = ss;
    __syncthreads();
    float var = (wss[0] + wss[1] + wss[2] + wss[3]) * (1.0f / 128.0f);
    xs[d] = x * rsqrtf(var + 1e-6f) * w[d];
    __syncthreads();

    if (d < 64) {
        const float scale = 0.08838834764831845f;
        float p = (float)s;
        float e = (float)(2 * d) * (1.0f / 128.0f);
        float invf = powf(1000000.0f, -e);
        float si, c;
        sincosf(p * invf, &si, &c);
        float x1 = xs[d], x2 = xs[d + 64];
        float r1 = (x1 * c - x2 * si) * scale;
        float r2 = (x2 * c + x1 * si) * scale;
        size_t base = ((size_t)h * S_LEN + s) * HDIM;
        __nv_bfloat16 h1 = __float2bfloat16(r1);
        __nv_bfloat16 h2 = __float2bfloat16(r2);
        qhi[base + d]      = h1;
        qhi[base + d + 64] = h2;
        qlo[base + d]      = __float2bfloat16(r1 - __bfloat162float(h1));
        qlo[base + d + 64] = __float2bfloat16(r2 - __bfloat162float(h2));
    }
}

// ---------------------------------------------------------------------------
// RMSNorm + RoPE for K (f32 new_k + hi/lo splits)
// ---------------------------------------------------------------------------
__global__ __launch_bounds__(128) void norm_rope_k(
    const float* __restrict__ inp, const float* __restrict__ w,
    float* __restrict__ outf,
    __nv_bfloat16* __restrict__ khi, __nv_bfloat16* __restrict__ klo) {
    const int s = blockIdx.x;
    const int h = blockIdx.y;
    const int d = threadIdx.x;

    float x = inp[((size_t)s * NKV + h) * HDIM + d];
    float ss = x * x;
#pragma unroll
    for (int o = 16; o; o >>= 1) ss += __shfl_xor_sync(0xffffffffu, ss, o);
    __shared__ float wss[4];
    __shared__ float xs[HDIM];
    if ((d & 31) == 0) wss[d >> 5] = ss;
    __syncthreads();
    float var = (wss[0] + wss[1] + wss[2] + wss[3]) * (1.0f / 128.0f);
    xs[d] = x * rsqrtf(var + 1e-6f) * w[d];
    __syncthreads();

    if (d < 64) {
        float p = (float)s;
        float e = (float)(2 * d) * (1.0f / 128.0f);
        float invf = powf(1000000.0f, -e);
        float si, c;
        sincosf(p * invf, &si, &c);
        float x1 = xs[d], x2 = xs[d + 64];
        float r1 = x1 * c - x2 * si;
        float r2 = x2 * c + x1 * si;
        size_t base = ((size_t)h * S_LEN + s) * HDIM;
        outf[base + d]      = r1;
        outf[base + d + 64] = r2;
        __nv_bfloat16 h1 = __float2bfloat16(r1);
        __nv_bfloat16 h2 = __float2bfloat16(r2);
        khi[base + d]      = h1;
        khi[base + d + 64] = h2;
        klo[base + d]      = __float2bfloat16(r1 - __bfloat162float(h1));
        klo[base + d + 64] = __float2bfloat16(r2 - __bfloat162float(h2));
    }
}

// ---------------------------------------------------------------------------
// V: [s][kv*128+d] -> new_v f32 [kv][s][d] + V^T splits [kv][d][s] bf16
// ---------------------------------------------------------------------------
__global__ __launch_bounds__(256) void v_split_transpose(
    const float* __restrict__ vt, float* __restrict__ outf,
    __nv_bfloat16* __restrict__ vthi, __nv_bfloat16* __restrict__ vtlo) {
    __shared__ float t[32][33];
    const int kv = blockIdx.z;
    const int s0 = blockIdx.x * 32;
    const int d0 = blockIdx.y * 32;
    const int tx = threadIdx.x;
    for (int r = threadIdx.y; r < 32; r += 8) {
        float v = vt[(size_t)(s0 + r) * (NKV * HDIM) + kv * HDIM + d0 + tx];
        t[r][tx] = v;
        outf[((size_t)kv * S_LEN + s0 + r) * HDIM + d0 + tx] = v;
    }
    __syncthreads();
    for (int r = threadIdx.y; r < 32; r += 8) {
        float v = t[tx][r];
        __nv_bfloat16 h = __float2bfloat16(v);
        size_t o = ((size_t)kv * HDIM + d0 + r) * S_LEN + s0 + tx;
        vthi[o] = h;
        vtlo[o] = __float2bfloat16(v - __bfloat162float(h));
    }
}

// ---------------------------------------------------------------------------
// Tensor-core attention v2: pipelined K (double-buffered) + early-issued V.
// ---------------------------------------------------------------------------
#define AT_QP 136
#define AT_VP 72
// element offsets in smem (bf16 units)
#define SQHI 0
#define SQLO (128 * AT_QP)                           // 17408
#define SKST (2 * 128 * AT_QP)                       // 34816, K stages base
#define KSTAGE_ELEMS (2 * 64 * AT_QP)                // 17408 per stage (hi+lo)
#define SVHI (SKST + 2 * KSTAGE_ELEMS)               // 69632
#define SVLO (SVHI + 128 * AT_VP)                    // 78848
#define SPHI (SVLO + 128 * AT_VP)                    // 88064
#define SPLO (SPHI + 128 * AT_VP)                    // 97280
#define AT_SMEM_ELEMS (SPLO + 128 * AT_VP)           // 106496
#define AT_SMEM_BYTES (AT_SMEM_ELEMS * 2)            // 212992

__global__ __launch_bounds__(256) void attention_mma(
    const __nv_bfloat16* __restrict__ qhi, const __nv_bfloat16* __restrict__ qlo,
    const __nv_bfloat16* __restrict__ khi, const __nv_bfloat16* __restrict__ klo,
    const __nv_bfloat16* __restrict__ vthi, const __nv_bfloat16* __restrict__ vtlo,
    float* __restrict__ probs,
    __nv_bfloat16* __restrict__ ahi, __nv_bfloat16* __restrict__ alo) {
    extern __shared__ __align__(16) __nv_bfloat16 smbuf[];
    const uint32_t sb = smem_to_u32(smbuf);
    const int h   = blockIdx.y;
    const int kvh = h >> 2;
    const int q0  = (int)(gridDim.x - 1 - blockIdx.x) * 128;
    const int tid = threadIdx.x;
    const int lane = tid & 31;
    const int wid  = tid >> 5;
    const int quad = lane >> 3, wi = lane & 7;
    const int wm   = wid * 16;
    const int arow = (quad & 1) * 8 + wi, acol = (quad >> 1) * 8;
    const int brow = (quad >> 1) * 8 + wi, bcol = (quad & 1) * 8;
    const int erow = lane >> 2, fc = (lane & 3) * 2;
    const int grow0 = q0 + wm + erow;
    const int grow1 = grow0 + 8;

    auto issue_K = [&](int jt, int buf) {
        const int c0 = jt * 64;
        const uint32_t kbase = SKST + (uint32_t)buf * KSTAGE_ELEMS;
#pragma unroll
        for (int i = 0; i < 4; i++) {
            int idx = tid + i * 256;
            int row = idx >> 4, ch = idx & 15;
            size_t go = ((size_t)kvh * S_LEN + c0 + row) * HDIM + ch * 8;
            cpasync16(sb + (uint32_t)(kbase + row * AT_QP + ch * 8) * 2, khi + go);
            cpasync16(sb + (uint32_t)(kbase + 64 * AT_QP + row * AT_QP + ch * 8) * 2, klo + go);
        }
    };
    auto issue_V = [&](int jt) {
        const int c0 = jt * 64;
#pragma unroll
        for (int i = 0; i < 4; i++) {
            int idx = tid + i * 256;
            int row = idx >> 3, ch = idx & 7;
            size_t go = ((size_t)kvh * HDIM + row) * S_LEN + c0 + ch * 8;
            cpasync16(sb + (uint32_t)(SVHI + row * AT_VP + ch * 8) * 2, vthi + go);
            cpasync16(sb + (uint32_t)(SVLO + row * AT_VP + ch * 8) * 2, vtlo + go);
        }
    };
    // compute S tile from K stage buf into s[8][4]
    auto compute_S = [&](int buf, float s[8][4]) {
        const uint32_t kbase = SKST + (uint32_t)buf * KSTAGE_ELEMS;
#pragma unroll
        for (int nt = 0; nt < 8; nt++)
#pragma unroll
            for (int q = 0; q < 4; q++) s[nt][q] = 0.f;
#pragma unroll
        for (int term = 0; term < 3; term++) {
            const uint32_t qb = (term == 1) ? SQLO : SQHI;
            const uint32_t kb = kbase + ((term == 2) ? (uint32_t)(64 * AT_QP) : 0u);
#pragma unroll
            for (int kk = 0; kk < 8; kk++) {
                uint32_t a[4], b[4][4];
                ldsm_x4(sb + (uint32_t)(qb + (wm + arow) * AT_QP + kk * 16 + acol) * 2, a);
#pragma unroll
                for (int nt2 = 0; nt2 < 4; nt2++)
                    ldsm_x4(sb + (uint32_t)(kb + (nt2 * 16 + brow) * AT_QP + kk * 16 + bcol) * 2, b[nt2]);
#pragma unroll
                for (int nt = 0; nt < 8; nt++)
                    mma16816(s[nt], a, b[nt >> 1][(nt & 1) * 2], b[nt >> 1][(nt & 1) * 2 + 1]);
            }
        }
    };

    const int jmax = (q0 + 127) >> 6;     // last valid KV tile index
    float m0 = -1e30f, m1 = -1e30f, l0 = 0.f, l1 = 0.f;

    // ---- prologue pass 1: Q + K(0) in one group ----
#pragma unroll
    for (int i = 0; i < 8; i++) {
        int idx = tid + i * 256;
        int row = idx >> 4, ch = idx & 15;
        size_t go = ((size_t)h * S_LEN + q0 + row) * HDIM + ch * 8;
        cpasync16(sb + (uint32_t)(SQHI + row * AT_QP + ch * 8) * 2, qhi + go);
        cpasync16(sb + (uint32_t)(SQLO + row * AT_QP + ch * 8) * 2, qlo + go);
    }
    issue_K(0, 0);
    CP_COMMIT();

    // ================= PASS 1 (K double-buffered) =================
    for (int jt = 0; jt <= jmax; jt++) {
        if (jt < jmax) {
            issue_K(jt + 1, (jt + 1) & 1);
            CP_COMMIT();
            CP_WAIT(1);
        } else {
            CP_WAIT(0);
        }
        __syncthreads();

        float s[8][4];
        compute_S(jt & 1, s);

        const int c0 = jt * 64;
        float tm0 = -1e30f, tm1 = -1e30f;
#pragma unroll
        for (int nt = 0; nt < 8; nt++) {
            int cb = c0 + nt * 8 + fc;
            if (cb     > grow0) s[nt][0] = -1e30f;
            if (cb + 1 > grow0) s[nt][1] = -1e30f;
            if (cb     > grow1) s[nt][2] = -1e30f;
            if (cb + 1 > grow1) s[nt][3] = -1e30f;
            tm0 = fmaxf(tm0, fmaxf(s[nt][0], s[nt][1]));
            tm1 = fmaxf(tm1, fmaxf(s[nt][2], s[nt][3]));
        }
        tm0 = fmaxf(tm0, __shfl_xor_sync(0xffffffffu, tm0, 1));
        tm0 = fmaxf(tm0, __shfl_xor_sync(0xffffffffu, tm0, 2));
        tm1 = fmaxf(tm1, __shfl_xor_sync(0xffffffffu, tm1, 1));
        tm1 = fmaxf(tm1, __shfl_xor_sync(0xffffffffu, tm1, 2));
        float mn0 = fmaxf(m0, tm0), mn1 = fmaxf(m1, tm1);
        float su0 = 0.f, su1 = 0.f;
#pragma unroll
        for (int nt = 0; nt < 8; nt++) {
            su0 += __expf(s[nt][0] - mn0) + __expf(s[nt][1] - mn0);
            su1 += __expf(s[nt][2] - mn1) + __expf(s[nt][3] - mn1);
        }
        su0 += __shfl_xor_sync(0xffffffffu, su0, 1);
        su0 += __shfl_xor_sync(0xffffffffu, su0, 2);
        su1 += __shfl_xor_sync(0xffffffffu, su1, 1);
        su1 += __shfl_xor_sync(0xffffffffu, su1, 2);
        l0 = l0 * __expf(m0 - mn0) + su0; m0 = mn0;
        l1 = l1 * __expf(m1 - mn1) + su1; m1 = mn1;
        __syncthreads();   // protect K buffer before next prefetch overwrites
    }
    const float li0 = 1.0f / l0, li1 = 1.0f / l1;

    // ---- zero-fill masked probs region (no smem involved) ----
    {
        float2 z = make_float2(0.f, 0.f);
        for (int jt = jmax + 1; jt < S_LEN / 64; jt++) {
            const int c0 = jt * 64;
#pragma unroll
            for (int nt = 0; nt < 8; nt++) {
                int col = c0 + nt * 8 + fc;
                *(float2*)&probs[((size_t)h * S_LEN + grow0) * S_LEN + col] = z;
                *(float2*)&probs[((size_t)h * S_LEN + grow1) * S_LEN + col] = z;
            }
        }
    }

    float o[16][4];
#pragma unroll
    for (int nt = 0; nt < 16; nt++)
#pragma unroll
        for (int q = 0; q < 4; q++) o[nt][q] = 0.f;

    // ---- prologue pass 2: K(0) group, then V(0) group ----
    issue_K(0, 0);
    CP_COMMIT();
    issue_V(0);
    CP_COMMIT();

    // ================= PASS 2 (K double-buffered, V early-issued) ==========
    for (int jt = 0; jt <= jmax; jt++) {
        // top: prefetch K(jt+1); ensure K(jt) arrived
        if (jt < jmax) {
            issue_K(jt + 1, (jt + 1) & 1);
            CP_COMMIT();
            CP_WAIT(2);          // completes K(jt); leaves V(jt), K(jt+1)
        } else {
            CP_WAIT(1);          // completes K(jt); leaves V(jt)
        }
        __syncthreads();

        float s[8][4];
        compute_S(jt & 1, s);

        const int c0 = jt * 64;
        const int pr0 = wm + erow, pr1 = pr0 + 8;
#pragma unroll
        for (int nt = 0; nt < 8; nt++) {
            int cb = c0 + nt * 8 + fc;
            float sv0 = (cb     > grow0) ? -1e30f : s[nt][0];
            float sv1 = (cb + 1 > grow0) ? -1e30f : s[nt][1];
            float sv2 = (cb     > grow1) ? -1e30f : s[nt][2];
            float sv3 = (cb + 1 > grow1) ? -1e30f : s[nt][3];
            float p0 = __expf(sv0 - m0) * li0;
            float p1 = __expf(sv1 - m0) * li0;
            float p2 = __expf(sv2 - m1) * li1;
            float p3 = __expf(sv3 - m1) * li1;
            *(float2*)&probs[((size_t)h * S_LEN + grow0) * S_LEN + cb] = make_float2(p0, p1);
            *(float2*)&probs[((size_t)h * S_LEN + grow1) * S_LEN + cb] = make_float2(p2, p3);
            int cl = nt * 8 + fc;
            __nv_bfloat16 h0 = __float2bfloat16(p0), h1 = __float2bfloat16(p1);
            __nv_bfloat16 h2 = __float2bfloat16(p2), h3 = __float2bfloat16(p3);
            __nv_bfloat162 hp01; hp01.x = h0; hp01.y = h1;
            __nv_bfloat162 hp23; hp23.x = h2; hp23.y = h3;
            __nv_bfloat162 lp01, lp23;
            lp01.x = __float2bfloat16(p0 - __bfloat162float(h0));
            lp01.y = __float2bfloat16(p1 - __bfloat162float(h1));
            lp23.x = __float2bfloat16(p2 - __bfloat162float(h2));
            lp23.y = __float2bfloat16(p3 - __bfloat162float(h3));
            *(__nv_bfloat162*)&smbuf[SPHI + pr0 * AT_VP + cl] = hp01;
            *(__nv_bfloat162*)&smbuf[SPHI + pr1 * AT_VP + cl] = hp23;
            *(__nv_bfloat162*)&smbuf[SPLO + pr0 * AT_VP + cl] = lp01;
            *(__nv_bfloat162*)&smbuf[SPLO + pr1 * AT_VP + cl] = lp23;
        }

        // ensure V(jt) arrived (issued one iteration ago; latency hidden)
        if (jt < jmax) CP_WAIT(1); else CP_WAIT(0);
        __syncthreads();

        // P @ V
#pragma unroll
        for (int term = 0; term < 3; term++) {
            const int pb = (term == 1) ? SPLO : SPHI;
            const int vb = (term == 2) ? SVLO : SVHI;
#pragma unroll
            for (int kk = 0; kk < 4; kk++) {
                uint32_t a[4], b[8][4];
                ldsm_x4(sb + (uint32_t)(pb + (wm + arow) * AT_VP + kk * 16 + acol) * 2, a);
#pragma unroll
                for (int nt2 = 0; nt2 < 8; nt2++)
                    ldsm_x4(sb + (uint32_t)(vb + (nt2 * 16 + brow) * AT_VP + kk * 16 + bcol) * 2, b[nt2]);
#pragma unroll
                for (int nt = 0; nt < 16; nt++)
                    mma16816(o[nt], a, b[nt >> 1][(nt & 1) * 2], b[nt >> 1][(nt & 1) * 2 + 1]);
            }
        }
        __syncthreads();       // all done reading V(jt) / P

        if (jt < jmax) {
            issue_V(jt + 1);   // overwrite V buffer (safe after barrier)
            CP_COMMIT();
        }
    }

    // ---- epilogue: split O to bf16 hi/lo in [s][h*128+d] layout ----
#pragma unroll
    for (int nt = 0; nt < 16; nt++) {
        int d = nt * 8 + fc;
        size_t b0 = (size_t)grow0 * HIDDEN + h * HDIM + d;
        size_t b1 = (size_t)grow1 * HIDDEN + h * HDIM + d;
        float v0 = o[nt][0], v1 = o[nt][1], v2 = o[nt][2], v3 = o[nt][3];
        __nv_bfloat16 h0 = __float2bfloat16(v0), h1 = __float2bfloat16(v1);
        __nv_bfloat16 h2 = __float2bfloat16(v2), h3 = __float2bfloat16(v3);
        __nv_bfloat162 hp01; hp01.x = h0; hp01.y = h1;
        __nv_bfloat162 hp23; hp23.x = h2; hp23.y = h3;
        __nv_bfloat162 lp01, lp23;
        lp01.x = __float2bfloat16(v0 - __bfloat162float(h0));
        lp01.y = __float2bfloat16(v1 - __bfloat162float(h1));
        lp23.x = __float2bfloat16(v2 - __bfloat162float(h2));
        lp23.y = __float2bfloat16(v3 - __bfloat162float(h3));
        *(__nv_bfloat162*)&ahi[b0] = hp01;
        *(__nv_bfloat162*)&ahi[b1] = hp23;
        *(__nv_bfloat162*)&alo[b0] = lp01;
        *(__nv_bfloat162*)&alo[b1] = lp23;
    }
}

// ---------------------------------------------------------------------------
// Launch
// ---------------------------------------------------------------------------
extern "C" void kernel_launch(void* const* d_in, const int* in_sizes, int n_in,
                              void* d_out, int out_size) {
    const float* X  = (const float*)d_in[0];
    const float* Wq = (const float*)d_in[2];
    const float* Wk = (const float*)d_in[3];
    const float* Wv = (const float*)d_in[4];
    const float* Wo = (const float*)d_in[5];
    const float* qw = (const float*)d_in[6];
    const float* kw = (const float*)d_in[7];

    float* out   = (float*)d_out;
    float* new_k = out + (size_t)S_LEN * HIDDEN;
    float* new_v = new_k + (size_t)NKV * S_LEN * HDIM;
    float* probs = new_v + (size_t)NKV * S_LEN * HDIM;

    float *qtmp, *ktmp, *vtmp;
    __nv_bfloat16 *xhi, *xlo, *ahi, *alo, *qhi, *qlo, *khi, *klo, *vthi, *vtlo;
    __nv_bfloat16 *wqh, *wql, *wkh, *wkl, *wvh, *wvl, *woh, *wol;
    cudaGetSymbolAddress((void**)&qtmp, g_qtmp);
    cudaGetSymbolAddress((void**)&ktmp, g_ktmp);
    cudaGetSymbolAddress((void**)&vtmp, g_vtmp);
    cudaGetSymbolAddress((void**)&xhi, g_xhi);
    cudaGetSymbolAddress((void**)&xlo, g_xlo);
    cudaGetSymbolAddress((void**)&ahi, g_ahi);
    cudaGetSymbolAddress((void**)&alo, g_alo);
    cudaGetSymbolAddress((void**)&qhi, g_qhi);
    cudaGetSymbolAddress((void**)&qlo, g_qlo);
    cudaGetSymbolAddress((void**)&khi, g_khi);
    cudaGetSymbolAddress((void**)&klo, g_klo);
    cudaGetSymbolAddress((void**)&vthi, g_vthi);
    cudaGetSymbolAddress((void**)&vtlo, g_vtlo);
    cudaGetSymbolAddress((void**)&wqh, g_wqthi);
    cudaGetSymbolAddress((void**)&wql, g_wqtlo);
    cudaGetSymbolAddress((void**)&wkh, g_wkthi);
    cudaGetSymbolAddress((void**)&wkl, g_wktlo);
    cudaGetSymbolAddress((void**)&wvh, g_wvthi);
    cudaGetSymbolAddress((void**)&wvl, g_wvtlo);
    cudaGetSymbolAddress((void**)&woh, g_wothi);
    cudaGetSymbolAddress((void**)&wol, g_wotlo);

    // ---- conversions ----
    {
        int n = S_LEN * HIDDEN;
        split_kernel<<<(n + 255) / 256, 256>>>(X, xhi, xlo, n);
    }
    transpose_split<<<dim3(HIDDEN / 32, HIDDEN / 32), dim3(32, 8)>>>(Wq, wqh, wql, HIDDEN);
    transpose_split<<<dim3((NKV * HDIM) / 32, HIDDEN / 32), dim3(32, 8)>>>(Wk, wkh, wkl, NKV * HDIM);
    transpose_split<<<dim3((NKV * HDIM) / 32, HIDDEN / 32), dim3(32, 8)>>>(Wv, wvh, wvl, NKV * HDIM);
    transpose_split<<<dim3(HIDDEN / 32, HIDDEN / 32), dim3(32, 8)>>>(Wo, woh, wol, HIDDEN);

    // ---- Q, K, V projections fused in one launch ----
    cudaFuncSetAttribute(gemm_mma3, cudaFuncAttributeMaxDynamicSharedMemorySize,
                         GEMM3_SMEM);
    gemm_mma3<<<dim3(HIDDEN / 128, S_LEN / 256, 3), 256, GEMM3_SMEM>>>(
        xhi, xlo,
        wqh, wql, qtmp, HIDDEN,
        wkh, wkl, ktmp, NKV * HDIM,
        wvh, wvl, vtmp, NKV * HDIM);

    // ---- RMSNorm + RoPE + splits ----
    norm_rope_q<<<dim3(S_LEN, NHEADS), 128>>>(qtmp, qw, qhi, qlo);
    norm_rope_k<<<dim3(S_LEN, NKV), 128>>>(ktmp, kw, new_k, khi, klo);

    // ---- V transpose + split ----
    v_split_transpose<<<dim3(S_LEN / 32, HDIM / 32, NKV), dim3(32, 8)>>>(
        vtmp, new_v, vthi, vtlo);

    // ---- attention ----
    cudaFuncSetAttribute(attention_mma,
                         cudaFuncAttributeMaxDynamicSharedMemorySize, AT_SMEM_BYTES);
    attention_mma<<<dim3(S_LEN / 128, NHEADS), 256, AT_SMEM_BYTES>>>(
        qhi, qlo, khi, klo, vthi, vtlo, probs, ahi, alo);

    // ---- O projection ----
    gemm_mma3<<<dim3(HIDDEN / 128, S_LEN / 256, 1), 256, GEMM3_SMEM>>>(
        ahi, alo,
        woh, wol, out, HIDDEN,
        woh, wol, out, HIDDEN,
        woh, wol, out, HIDDEN);
}

// round 9
// speedup vs baseline: 3.2758x; 1.0306x over previous
#include <cuda_runtime.h>
#include <cuda_bf16.h>
#include <math.h>
#include <stdint.h>

// ---------------------------------------------------------------------------
// Problem constants
// ---------------------------------------------------------------------------
#define S_LEN   2048
#define HIDDEN  4096
#define NHEADS  32
#define NKV     8
#define HDIM    128

// ---------------------------------------------------------------------------
// Device scratch
// ---------------------------------------------------------------------------
__device__ float g_qtmp[S_LEN * NHEADS * HDIM];
__device__ float g_ktmp[S_LEN * NKV * HDIM];
__device__ float g_vtmp[S_LEN * NKV * HDIM];

__device__ __nv_bfloat16 g_xhi[S_LEN * HIDDEN];
__device__ __nv_bfloat16 g_xlo[S_LEN * HIDDEN];
__device__ __nv_bfloat16 g_ahi[S_LEN * HIDDEN];
__device__ __nv_bfloat16 g_alo[S_LEN * HIDDEN];
__device__ __nv_bfloat16 g_qhi[NHEADS * S_LEN * HDIM];   // [h][s][d], pre-scaled
__device__ __nv_bfloat16 g_qlo[NHEADS * S_LEN * HDIM];
__device__ __nv_bfloat16 g_khi[NKV * S_LEN * HDIM];      // [kv][s][d]
__device__ __nv_bfloat16 g_klo[NKV * S_LEN * HDIM];
__device__ __nv_bfloat16 g_vthi[NKV * HDIM * S_LEN];     // [kv][d][s]
__device__ __nv_bfloat16 g_vtlo[NKV * HDIM * S_LEN];
__device__ __nv_bfloat16 g_wqthi[HIDDEN * HIDDEN];
__device__ __nv_bfloat16 g_wqtlo[HIDDEN * HIDDEN];
__device__ __nv_bfloat16 g_wkthi[(NKV * HDIM) * HIDDEN];
__device__ __nv_bfloat16 g_wktlo[(NKV * HDIM) * HIDDEN];
__device__ __nv_bfloat16 g_wvthi[(NKV * HDIM) * HIDDEN];
__device__ __nv_bfloat16 g_wvtlo[(NKV * HDIM) * HIDDEN];
__device__ __nv_bfloat16 g_wothi[HIDDEN * HIDDEN];
__device__ __nv_bfloat16 g_wotlo[HIDDEN * HIDDEN];

// ---------------------------------------------------------------------------
// Low-level helpers
// ---------------------------------------------------------------------------
__device__ __forceinline__ uint32_t smem_to_u32(const void* p) {
    uint32_t a;
    asm("{ .reg .u64 t; cvta.to.shared.u64 t, %1; cvt.u32.u64 %0, t; }"
        : "=r"(a) : "l"(p));
    return a;
}
__device__ __forceinline__ void cpasync16(uint32_t saddr, const void* g) {
    asm volatile("cp.async.cg.shared.global [%0], [%1], 16;"
                 :: "r"(saddr), "l"(g));
}
#define CP_COMMIT() asm volatile("cp.async.commit_group;" ::: "memory")
#define CP_WAIT(n)  asm volatile("cp.async.wait_group %0;" :: "n"(n) : "memory")

__device__ __forceinline__ void ldsm_x4(uint32_t addr, uint32_t r[4]) {
    asm volatile("ldmatrix.sync.aligned.m8n8.x4.shared.b16 {%0,%1,%2,%3}, [%4];"
        : "=r"(r[0]), "=r"(r[1]), "=r"(r[2]), "=r"(r[3]) : "r"(addr));
}
__device__ __forceinline__ void mma16816(float d[4], const uint32_t a[4],
                                         const uint32_t b0, const uint32_t b1) {
    asm volatile(
        "mma.sync.aligned.m16n8k16.row.col.f32.bf16.bf16.f32 "
        "{%0,%1,%2,%3}, {%4,%5,%6,%7}, {%8,%9}, {%0,%1,%2,%3};"
        : "+f"(d[0]), "+f"(d[1]), "+f"(d[2]), "+f"(d[3])
        : "r"(a[0]), "r"(a[1]), "r"(a[2]), "r"(a[3]), "r"(b0), "r"(b1));
}

// ---------------------------------------------------------------------------
// Projection GEMM: 256x128 tile, BK=64, single-sync multistage, serpentine
// swizzle, hi/lo 3-term. blockIdx.z selects operand set.
// ---------------------------------------------------------------------------
#define SP3       72
#define A3_ELEMS  (256 * SP3)
#define B3_ELEMS  (128 * SP3)
#define STG3      (2 * A3_ELEMS + 2 * B3_ELEMS)
#define GEMM3_SMEM (2 * STG3 * 2)
#define NCH3      (HIDDEN / 64)

__global__ __launch_bounds__(256) void gemm_mma3(
    const __nv_bfloat16* __restrict__ Ahi, const __nv_bfloat16* __restrict__ Alo,
    const __nv_bfloat16* __restrict__ Bh0, const __nv_bfloat16* __restrict__ Bl0,
    float* __restrict__ C0, int N0,
    const __nv_bfloat16* __restrict__ Bh1, const __nv_bfloat16* __restrict__ Bl1,
    float* __restrict__ C1, int N1) {
    extern __shared__ __align__(16) __nv_bfloat16 smbuf[];
    const __nv_bfloat16* Bhi;
    const __nv_bfloat16* Blo;
    float* C;
    int Ntot;
    if (blockIdx.z == 0) { Bhi = Bh0; Blo = Bl0; C = C0; Ntot = N0; }
    else                 { Bhi = Bh1; Blo = Bl1; C = C1; Ntot = N1; }

    const int nx_eff = Ntot >> 7;
    const int flat = blockIdx.y * gridDim.x + blockIdx.x;
    if (flat >= nx_eff * (S_LEN / 256)) return;
    const int per = 4 * nx_eff;
    const int grp = flat / per, rem = flat % per;
    const int m0 = (grp * 4 + (rem & 3)) * 256;
    const int n0 = (rem >> 2) * 128;

    const uint32_t sb = smem_to_u32(smbuf);
    const int tid  = threadIdx.x;
    const int lane = tid & 31;
    const int wid  = tid >> 5;
    const int wm = (wid >> 1) * 64;
    const int wn = (wid & 1) * 64;
    const int quad = lane >> 3;
    const int wi   = lane & 7;
    const int arow = (quad & 1) * 8 + wi;
    const int acol = (quad >> 1) * 8;
    const int brow = (quad >> 1) * 8 + wi;
    const int bcol = (quad & 1) * 8;

    float acc[4][8][4];
#pragma unroll
    for (int mt = 0; mt < 4; mt++)
#pragma unroll
        for (int nt = 0; nt < 8; nt++)
#pragma unroll
            for (int q = 0; q < 4; q++) acc[mt][nt][q] = 0.f;

    auto load_stage = [&](int buf, int chunk) {
        const int k0 = chunk * 64;
        const uint32_t sbase = sb + (uint32_t)buf * STG3 * 2;
#pragma unroll
        for (int t = 0; t < 8; t++) {
            int c = tid + t * 256;
            int row = c >> 3;
            int kc  = (c & 7) * 8;
            uint32_t so = sbase + (uint32_t)(row * SP3 + kc) * 2;
            size_t goA = (size_t)(m0 + row) * HIDDEN + k0 + kc;
            cpasync16(so,                Ahi + goA);
            cpasync16(so + A3_ELEMS * 2, Alo + goA);
        }
#pragma unroll
        for (int t = 0; t < 4; t++) {
            int c = tid + t * 256;
            int row = c >> 3;
            int kc  = (c & 7) * 8;
            uint32_t so = sbase + (uint32_t)(2 * A3_ELEMS + row * SP3 + kc) * 2;
            size_t goB = (size_t)(n0 + row) * HIDDEN + k0 + kc;
            cpasync16(so,                Bhi + goB);
            cpasync16(so + B3_ELEMS * 2, Blo + goB);
        }
    };

    load_stage(0, 0);
    CP_COMMIT();

    for (int chunk = 0; chunk < NCH3; chunk++) {
        CP_WAIT(0);
        __syncthreads();
        if (chunk + 1 < NCH3) {
            load_stage((chunk + 1) & 1, chunk + 1);
            CP_COMMIT();
        }
        const uint32_t stage = sb + (uint32_t)(chunk & 1) * STG3 * 2;
#pragma unroll
        for (int kk = 0; kk < 4; kk++) {
            uint32_t aH[4][4], aL[4][4], bH[4][4], bL[4][4];
#pragma unroll
            for (int mt = 0; mt < 4; mt++) {
                uint32_t ao = (uint32_t)((wm + mt * 16 + arow) * SP3 + kk * 16 + acol) * 2;
                ldsm_x4(stage + ao, aH[mt]);
                ldsm_x4(stage + A3_ELEMS * 2 + ao, aL[mt]);
            }
#pragma unroll
            for (int nt2 = 0; nt2 < 4; nt2++) {
                uint32_t bo = (uint32_t)(2 * A3_ELEMS + (wn + nt2 * 16 + brow) * SP3 +
                                         kk * 16 + bcol) * 2;
                ldsm_x4(stage + bo, bH[nt2]);
                ldsm_x4(stage + B3_ELEMS * 2 + bo, bL[nt2]);
            }
#pragma unroll
            for (int mt = 0; mt < 4; mt++)
#pragma unroll
                for (int nt = 0; nt < 8; nt++) {
                    uint32_t h0 = bH[nt >> 1][(nt & 1) * 2];
                    uint32_t h1 = bH[nt >> 1][(nt & 1) * 2 + 1];
                    uint32_t l0 = bL[nt >> 1][(nt & 1) * 2];
                    uint32_t l1 = bL[nt >> 1][(nt & 1) * 2 + 1];
                    mma16816(acc[mt][nt], aH[mt], h0, h1);
                    mma16816(acc[mt][nt], aL[mt], h0, h1);
                    mma16816(acc[mt][nt], aH[mt], l0, l1);
                }
        }
    }

    __syncthreads();
    const int erow = lane >> 2;
    const int ecol = (lane & 3) * 2;
#pragma unroll
    for (int mt = 0; mt < 4; mt++) {
#pragma unroll
        for (int nt = 0; nt < 8; nt++) {
            int r = m0 + wm + mt * 16 + erow;
            int c = n0 + wn + nt * 8 + ecol;
            *(float2*)&C[(size_t)r * Ntot + c] =
                make_float2(acc[mt][nt][0], acc[mt][nt][1]);
            *(float2*)&C[(size_t)(r + 8) * Ntot + c] =
                make_float2(acc[mt][nt][2], acc[mt][nt][3]);
        }
    }
}

// ---------------------------------------------------------------------------
// f32 -> bf16 hi/lo split
// ---------------------------------------------------------------------------
__global__ void split_kernel(const float* __restrict__ x,
                             __nv_bfloat16* __restrict__ hi,
                             __nv_bfloat16* __restrict__ lo, int n) {
    int i = blockIdx.x * 256 + threadIdx.x;
    if (i >= n) return;
    float v = x[i];
    __nv_bfloat16 h = __float2bfloat16(v);
    hi[i] = h;
    lo[i] = __float2bfloat16(v - __bfloat162float(h));
}

// ---------------------------------------------------------------------------
// All 4 weight transposes fused: W [4096][N] f32 -> W^T hi/lo [N][4096] bf16
// grid (128, 128, 4); CTAs with n0 >= N[z] exit.
// ---------------------------------------------------------------------------
__global__ __launch_bounds__(256) void transpose_split_all(
    const float* __restrict__ Wq, const float* __restrict__ Wk,
    const float* __restrict__ Wv, const float* __restrict__ Wo,
    __nv_bfloat16* __restrict__ qh, __nv_bfloat16* __restrict__ ql,
    __nv_bfloat16* __restrict__ kh, __nv_bfloat16* __restrict__ kl,
    __nv_bfloat16* __restrict__ vh, __nv_bfloat16* __restrict__ vl,
    __nv_bfloat16* __restrict__ oh, __nv_bfloat16* __restrict__ ol) {
    const float* W; __nv_bfloat16 *hi, *lo; int N;
    switch (blockIdx.z) {
        case 0: W = Wq; hi = qh; lo = ql; N = HIDDEN; break;
        case 1: W = Wk; hi = kh; lo = kl; N = NKV * HDIM; break;
        case 2: W = Wv; hi = vh; lo = vl; N = NKV * HDIM; break;
        default: W = Wo; hi = oh; lo = ol; N = HIDDEN; break;
    }
    const int n0 = blockIdx.x * 32;
    if (n0 >= N) return;
    const int k0 = blockIdx.y * 32;
    __shared__ float t[32][33];
    const int tx = threadIdx.x;
    for (int r = threadIdx.y; r < 32; r += 8)
        t[r][tx] = W[(size_t)(k0 + r) * N + n0 + tx];
    __syncthreads();
    for (int r = threadIdx.y; r < 32; r += 8) {
        float v = t[tx][r];
        __nv_bfloat16 h = __float2bfloat16(v);
        size_t o = (size_t)(n0 + r) * HIDDEN + k0 + tx;
        hi[o] = h;
        lo[o] = __float2bfloat16(v - __bfloat162float(h));
    }
}

// ---------------------------------------------------------------------------
// RMSNorm + RoPE for Q (pre-scaled hi/lo splits)
// ---------------------------------------------------------------------------
__global__ __launch_bounds__(128) void norm_rope_q(
    const float* __restrict__ inp, const float* __restrict__ w,
    __nv_bfloat16* __restrict__ qhi, __nv_bfloat16* __restrict__ qlo) {
    const int s = blockIdx.x;
    const int h = blockIdx.y;
    const int d = threadIdx.x;

    float x = inp[((size_t)s * NHEADS + h) * HDIM + d];
    float ss = x * x;
#pragma unroll
    for (int o = 16; o; o >>= 1) ss += __shfl_xor_sync(0xffffffffu, ss, o);
    __shared__ float wss[4];
    __shared__ float xs[HDIM];
    if ((d & 31) == 0) wss[d >> 5] = ss;
    __syncthreads();
    float var = (wss[0] + wss[1] + wss[2] + wss[3]) * (1.0f / 128.0f);
    xs[d] = x * rsqrtf(var + 1e-6f) * w[d];
    __syncthreads();

    if (d < 64) {
        const float scale = 0.08838834764831845f;
        float p = (float)s;
        float e = (float)(2 * d) * (1.0f / 128.0f);
        float invf = powf(1000000.0f, -e);
        float si, c;
        sincosf(p * invf, &si, &c);
        float x1 = xs[d], x2 = xs[d + 64];
        float r1 = (x1 * c - x2 * si) * scale;
        float r2 = (x2 * c + x1 * si) * scale;
        size_t base = ((size_t)h * S_LEN + s) * HDIM;
        __nv_bfloat16 h1 = __float2bfloat16(r1);
        __nv_bfloat16 h2 = __float2bfloat16(r2);
        qhi[base + d]      = h1;
        qhi[base + d + 64] = h2;
        qlo[base + d]      = __float2bfloat16(r1 - __bfloat162float(h1));
        qlo[base + d + 64] = __float2bfloat16(r2 - __bfloat162float(h2));
    }
}

// ---------------------------------------------------------------------------
// RMSNorm + RoPE for K (f32 new_k + hi/lo splits)
// ---------------------------------------------------------------------------
__global__ __launch_bounds__(128) void norm_rope_k(
    const float* __restrict__ inp, const float* __restrict__ w,
    float* __restrict__ outf,
    __nv_bfloat16* __restrict__ khi, __nv_bfloat16* __restrict__ klo) {
    const int s = blockIdx.x;
    const int h = blockIdx.y;
    const int d = threadIdx.x;

    float x = inp[((size_t)s * NKV + h) * HDIM + d];
    float ss = x * x;
#pragma unroll
    for (int o = 16; o; o >>= 1) ss += __shfl_xor_sync(0xffffffffu, ss, o);
    __shared__ float wss[4];
    __shared__ float xs[HDIM];
    if ((d & 31) == 0) wss[d >> 5] = ss;
    __syncthreads();
    float var = (wss[0] + wss[1] + wss[2] + wss[3]) * (1.0f / 128.0f);
    xs[d] = x * rsqrtf(var + 1e-6f) * w[d];
    __syncthreads();

    if (d < 64) {
        float p = (float)s;
        float e = (float)(2 * d) * (1.0f / 128.0f);
        float invf = powf(1000000.0f, -e);
        float si, c;
        sincosf(p * invf, &si, &c);
        float x1 = xs[d], x2 = xs[d + 64];
        float r1 = x1 * c - x2 * si;
        float r2 = x2 * c + x1 * si;
        size_t base = ((size_t)h * S_LEN + s) * HDIM;
        outf[base + d]      = r1;
        outf[base + d + 64] = r2;
        __nv_bfloat16 h1 = __float2bfloat16(r1);
        __nv_bfloat16 h2 = __float2bfloat16(r2);
        khi[base + d]      = h1;
        khi[base + d + 64] = h2;
        klo[base + d]      = __float2bfloat16(r1 - __bfloat162float(h1));
        klo[base + d + 64] = __float2bfloat16(r2 - __bfloat162float(h2));
    }
}

// ---------------------------------------------------------------------------
// V: [s][kv*128+d] -> new_v f32 [kv][s][d] + V^T splits [kv][d][s] bf16
// ---------------------------------------------------------------------------
__global__ __launch_bounds__(256) void v_split_transpose(
    const float* __restrict__ vt, float* __restrict__ outf,
    __nv_bfloat16* __restrict__ vthi, __nv_bfloat16* __restrict__ vtlo) {
    __shared__ float t[32][33];
    const int kv = blockIdx.z;
    const int s0 = blockIdx.x * 32;
    const int d0 = blockIdx.y * 32;
    const int tx = threadIdx.x;
    for (int r = threadIdx.y; r < 32; r += 8) {
        float v = vt[(size_t)(s0 + r) * (NKV * HDIM) + kv * HDIM + d0 + tx];
        t[r][tx] = v;
        outf[((size_t)kv * S_LEN + s0 + r) * HDIM + d0 + tx] = v;
    }
    __syncthreads();
    for (int r = threadIdx.y; r < 32; r += 8) {
        float v = t[tx][r];
        __nv_bfloat16 h = __float2bfloat16(v);
        size_t o = ((size_t)kv * HDIM + d0 + r) * S_LEN + s0 + tx;
        vthi[o] = h;
        vtlo[o] = __float2bfloat16(v - __bfloat162float(h));
    }
}

// ---------------------------------------------------------------------------
// Tensor-core attention v3:
//  Pass 1: QK^T (3-term), mask, store RAW scores into probs, online m/l.
//  Pass 2: stream scores back (cp.async double-buffered f32 stage), exp/normalize,
//          rewrite probs, P@V (3-term) with early-issued V. No S recompute.
// ---------------------------------------------------------------------------
#define AT_QP 136
#define AT_VP 72
#define S_PITCH_F 72
#define SQHI 0
#define SQLO (128 * AT_QP)                     // 17408
#define SSST (2 * 128 * AT_QP)                 // 34816 : K stages (p1) / s stages (p2)
#define SSTAGE_UNITS (128 * S_PITCH_F * 2)     // 18432 bf16-units per stage
#define SVHI (SSST + 2 * SSTAGE_UNITS)         // 71680
#define SVLO (SVHI + 128 * AT_VP)              // 80896
#define SPHI (SVLO + 128 * AT_VP)              // 90112
#define SPLO (SPHI + 128 * AT_VP)              // 99328
#define AT_SMEM_ELEMS (SPLO + 128 * AT_VP)     // 108544
#define AT_SMEM_BYTES (AT_SMEM_ELEMS * 2)      // 217088

__global__ __launch_bounds__(256) void attention_mma(
    const __nv_bfloat16* __restrict__ qhi, const __nv_bfloat16* __restrict__ qlo,
    const __nv_bfloat16* __restrict__ khi, const __nv_bfloat16* __restrict__ klo,
    const __nv_bfloat16* __restrict__ vthi, const __nv_bfloat16* __restrict__ vtlo,
    float* __restrict__ probs,
    __nv_bfloat16* __restrict__ ahi, __nv_bfloat16* __restrict__ alo) {
    extern __shared__ __align__(16) __nv_bfloat16 smbuf[];
    const uint32_t sb = smem_to_u32(smbuf);
    const int h   = blockIdx.y;
    const int kvh = h >> 2;
    const int q0  = (int)(gridDim.x - 1 - blockIdx.x) * 128;
    const int tid = threadIdx.x;
    const int lane = tid & 31;
    const int wid  = tid >> 5;
    const int quad = lane >> 3, wi = lane & 7;
    const int wm   = wid * 16;
    const int arow = (quad & 1) * 8 + wi, acol = (quad >> 1) * 8;
    const int brow = (quad >> 1) * 8 + wi, bcol = (quad & 1) * 8;
    const int erow = lane >> 2, fc = (lane & 3) * 2;
    const int grow0 = q0 + wm + erow;
    const int grow1 = grow0 + 8;

    auto issue_K = [&](int jt, int buf) {
        const int c0 = jt * 64;
        const uint32_t kbase = SSST + (uint32_t)buf * SSTAGE_UNITS;
#pragma unroll
        for (int i = 0; i < 4; i++) {
            int idx = tid + i * 256;
            int row = idx >> 4, ch = idx & 15;
            size_t go = ((size_t)kvh * S_LEN + c0 + row) * HDIM + ch * 8;
            cpasync16(sb + (uint32_t)(kbase + row * AT_QP + ch * 8) * 2, khi + go);
            cpasync16(sb + (uint32_t)(kbase + 64 * AT_QP + row * AT_QP + ch * 8) * 2, klo + go);
        }
    };
    auto issue_V = [&](int jt) {
        const int c0 = jt * 64;
#pragma unroll
        for (int i = 0; i < 4; i++) {
            int idx = tid + i * 256;
            int row = idx >> 3, ch = idx & 7;
            size_t go = ((size_t)kvh * HDIM + row) * S_LEN + c0 + ch * 8;
            cpasync16(sb + (uint32_t)(SVHI + row * AT_VP + ch * 8) * 2, vthi + go);
            cpasync16(sb + (uint32_t)(SVLO + row * AT_VP + ch * 8) * 2, vtlo + go);
        }
    };
    // stage raw scores (f32) from probs into smem
    auto issue_S = [&](int jt, int buf) {
        const int c0 = jt * 64;
        const uint32_t sbase = (uint32_t)((SSST + buf * SSTAGE_UNITS) * 2);
#pragma unroll
        for (int i = 0; i < 8; i++) {
            int idx = tid + i * 256;
            int row = idx >> 4, ch = idx & 15;   // row 0..127, ch 0..15 (x4 floats)
            const float* g = &probs[((size_t)h * S_LEN + q0 + row) * S_LEN + c0 + ch * 4];
            cpasync16(sb + sbase + (uint32_t)(row * S_PITCH_F + ch * 4) * 4, g);
        }
    };
    auto compute_S = [&](int buf, float s[8][4]) {
        const uint32_t kbase = SSST + (uint32_t)buf * SSTAGE_UNITS;
#pragma unroll
        for (int nt = 0; nt < 8; nt++)
#pragma unroll
            for (int q = 0; q < 4; q++) s[nt][q] = 0.f;
#pragma unroll
        for (int term = 0; term < 3; term++) {
            const uint32_t qb = (term == 1) ? SQLO : SQHI;
            const uint32_t kb = kbase + ((term == 2) ? (uint32_t)(64 * AT_QP) : 0u);
#pragma unroll
            for (int kk = 0; kk < 8; kk++) {
                uint32_t a[4], b[4][4];
                ldsm_x4(sb + (uint32_t)(qb + (wm + arow) * AT_QP + kk * 16 + acol) * 2, a);
#pragma unroll
                for (int nt2 = 0; nt2 < 4; nt2++)
                    ldsm_x4(sb + (uint32_t)(kb + (nt2 * 16 + brow) * AT_QP + kk * 16 + bcol) * 2, b[nt2]);
#pragma unroll
                for (int nt = 0; nt < 8; nt++)
                    mma16816(s[nt], a, b[nt >> 1][(nt & 1) * 2], b[nt >> 1][(nt & 1) * 2 + 1]);
            }
        }
    };

    const int jmax = (q0 + 127) >> 6;
    float m0 = -1e30f, m1 = -1e30f, l0 = 0.f, l1 = 0.f;

    // ---- prologue pass 1: Q + K(0) ----
#pragma unroll
    for (int i = 0; i < 8; i++) {
        int idx = tid + i * 256;
        int row = idx >> 4, ch = idx & 15;
        size_t go = ((size_t)h * S_LEN + q0 + row) * HDIM + ch * 8;
        cpasync16(sb + (uint32_t)(SQHI + row * AT_QP + ch * 8) * 2, qhi + go);
        cpasync16(sb + (uint32_t)(SQLO + row * AT_QP + ch * 8) * 2, qlo + go);
    }
    issue_K(0, 0);
    CP_COMMIT();

    // ================= PASS 1: scores -> probs (raw), stats =================
    for (int jt = 0; jt <= jmax; jt++) {
        if (jt < jmax) {
            issue_K(jt + 1, (jt + 1) & 1);
            CP_COMMIT();
            CP_WAIT(1);
        } else {
            CP_WAIT(0);
        }
        __syncthreads();

        float s[8][4];
        compute_S(jt & 1, s);

        const int c0 = jt * 64;
        float tm0 = -1e30f, tm1 = -1e30f;
#pragma unroll
        for (int nt = 0; nt < 8; nt++) {
            int cb = c0 + nt * 8 + fc;
            if (cb     > grow0) s[nt][0] = -1e30f;
            if (cb + 1 > grow0) s[nt][1] = -1e30f;
            if (cb     > grow1) s[nt][2] = -1e30f;
            if (cb + 1 > grow1) s[nt][3] = -1e30f;
            // store raw masked scores; pass 2 reads them back
            *(float2*)&probs[((size_t)h * S_LEN + grow0) * S_LEN + cb] =
                make_float2(s[nt][0], s[nt][1]);
            *(float2*)&probs[((size_t)h * S_LEN + grow1) * S_LEN + cb] =
                make_float2(s[nt][2], s[nt][3]);
            tm0 = fmaxf(tm0, fmaxf(s[nt][0], s[nt][1]));
            tm1 = fmaxf(tm1, fmaxf(s[nt][2], s[nt][3]));
        }
        tm0 = fmaxf(tm0, __shfl_xor_sync(0xffffffffu, tm0, 1));
        tm0 = fmaxf(tm0, __shfl_xor_sync(0xffffffffu, tm0, 2));
        tm1 = fmaxf(tm1, __shfl_xor_sync(0xffffffffu, tm1, 1));
        tm1 = fmaxf(tm1, __shfl_xor_sync(0xffffffffu, tm1, 2));
        float mn0 = fmaxf(m0, tm0), mn1 = fmaxf(m1, tm1);
        float su0 = 0.f, su1 = 0.f;
#pragma unroll
        for (int nt = 0; nt < 8; nt++) {
            su0 += __expf(s[nt][0] - mn0) + __expf(s[nt][1] - mn0);
            su1 += __expf(s[nt][2] - mn1) + __expf(s[nt][3] - mn1);
        }
        su0 += __shfl_xor_sync(0xffffffffu, su0, 1);
        su0 += __shfl_xor_sync(0xffffffffu, su0, 2);
        su1 += __shfl_xor_sync(0xffffffffu, su1, 1);
        su1 += __shfl_xor_sync(0xffffffffu, su1, 2);
        l0 = l0 * __expf(m0 - mn0) + su0; m0 = mn0;
        l1 = l1 * __expf(m1 - mn1) + su1; m1 = mn1;
        __syncthreads();
    }
    const float li0 = 1.0f / l0, li1 = 1.0f / l1;

    // ---- zero-fill masked probs tiles ----
    {
        float2 z = make_float2(0.f, 0.f);
        for (int jt = jmax + 1; jt < S_LEN / 64; jt++) {
            const int c0 = jt * 64;
#pragma unroll
            for (int nt = 0; nt < 8; nt++) {
                int col = c0 + nt * 8 + fc;
                *(float2*)&probs[((size_t)h * S_LEN + grow0) * S_LEN + col] = z;
                *(float2*)&probs[((size_t)h * S_LEN + grow1) * S_LEN + col] = z;
            }
        }
    }

    float o[16][4];
#pragma unroll
    for (int nt = 0; nt < 16; nt++)
#pragma unroll
        for (int q = 0; q < 4; q++) o[nt][q] = 0.f;

    // ---- prologue pass 2: s(0) then V(0) ----
    issue_S(0, 0);
    CP_COMMIT();
    issue_V(0);
    CP_COMMIT();

    // ================= PASS 2: normalize + P@V (no S recompute) ============
    for (int jt = 0; jt <= jmax; jt++) {
        if (jt < jmax) {
            issue_S(jt + 1, (jt + 1) & 1);
            CP_COMMIT();
            CP_WAIT(2);          // completes s(jt); leaves V(jt), s(jt+1)
        } else {
            CP_WAIT(1);          // completes s(jt); leaves V(jt)
        }
        __syncthreads();

        const float* sf = (const float*)&smbuf[SSST + (jt & 1) * SSTAGE_UNITS];
        const int c0 = jt * 64;
        const int pr0 = wm + erow, pr1 = pr0 + 8;
#pragma unroll
        for (int nt = 0; nt < 8; nt++) {
            int cl = nt * 8 + fc;
            float2 s01 = *(const float2*)&sf[pr0 * S_PITCH_F + cl];
            float2 s23 = *(const float2*)&sf[pr1 * S_PITCH_F + cl];
            float p0 = __expf(s01.x - m0) * li0;
            float p1 = __expf(s01.y - m0) * li0;
            float p2 = __expf(s23.x - m1) * li1;
            float p3 = __expf(s23.y - m1) * li1;
            int cb = c0 + cl;
            *(float2*)&probs[((size_t)h * S_LEN + grow0) * S_LEN + cb] = make_float2(p0, p1);
            *(float2*)&probs[((size_t)h * S_LEN + grow1) * S_LEN + cb] = make_float2(p2, p3);
            __nv_bfloat16 h0 = __float2bfloat16(p0), h1 = __float2bfloat16(p1);
            __nv_bfloat16 h2 = __float2bfloat16(p2), h3 = __float2bfloat16(p3);
            __nv_bfloat162 hp01; hp01.x = h0; hp01.y = h1;
            __nv_bfloat162 hp23; hp23.x = h2; hp23.y = h3;
            __nv_bfloat162 lp01, lp23;
            lp01.x = __float2bfloat16(p0 - __bfloat162float(h0));
            lp01.y = __float2bfloat16(p1 - __bfloat162float(h1));
            lp23.x = __float2bfloat16(p2 - __bfloat162float(h2));
            lp23.y = __float2bfloat16(p3 - __bfloat162float(h3));
            *(__nv_bfloat162*)&smbuf[SPHI + pr0 * AT_VP + cl] = hp01;
            *(__nv_bfloat162*)&smbuf[SPHI + pr1 * AT_VP + cl] = hp23;
            *(__nv_bfloat162*)&smbuf[SPLO + pr0 * AT_VP + cl] = lp01;
            *(__nv_bfloat162*)&smbuf[SPLO + pr1 * AT_VP + cl] = lp23;
        }
        __syncwarp();

        if (jt < jmax) CP_WAIT(1); else CP_WAIT(0);   // completes V(jt)
        __syncthreads();

        // P @ V
#pragma unroll
        for (int term = 0; term < 3; term++) {
            const int pb = (term == 1) ? SPLO : SPHI;
            const int vb = (term == 2) ? SVLO : SVHI;
#pragma unroll
            for (int kk = 0; kk < 4; kk++) {
                uint32_t a[4], b[8][4];
                ldsm_x4(sb + (uint32_t)(pb + (wm + arow) * AT_VP + kk * 16 + acol) * 2, a);
#pragma unroll
                for (int nt2 = 0; nt2 < 8; nt2++)
                    ldsm_x4(sb + (uint32_t)(vb + (nt2 * 16 + brow) * AT_VP + kk * 16 + bcol) * 2, b[nt2]);
#pragma unroll
                for (int nt = 0; nt < 16; nt++)
                    mma16816(o[nt], a, b[nt >> 1][(nt & 1) * 2], b[nt >> 1][(nt & 1) * 2 + 1]);
            }
        }
        __syncthreads();

        if (jt < jmax) {
            issue_V(jt + 1);
            CP_COMMIT();
        }
    }

    // ---- epilogue: split O to bf16 hi/lo in [s][h*128+d] layout ----
#pragma unroll
    for (int nt = 0; nt < 16; nt++) {
        int d = nt * 8 + fc;
        size_t b0 = (size_t)grow0 * HIDDEN + h * HDIM + d;
        size_t b1 = (size_t)grow1 * HIDDEN + h * HDIM + d;
        float v0 = o[nt][0], v1 = o[nt][1], v2 = o[nt][2], v3 = o[nt][3];
        __nv_bfloat16 h0 = __float2bfloat16(v0), h1 = __float2bfloat16(v1);
        __nv_bfloat16 h2 = __float2bfloat16(v2), h3 = __float2bfloat16(v3);
        __nv_bfloat162 hp01; hp01.x = h0; hp01.y = h1;
        __nv_bfloat162 hp23; hp23.x = h2; hp23.y = h3;
        __nv_bfloat162 lp01, lp23;
        lp01.x = __float2bfloat16(v0 - __bfloat162float(h0));
        lp01.y = __float2bfloat16(v1 - __bfloat162float(h1));
        lp23.x = __float2bfloat16(v2 - __bfloat162float(h2));
        lp23.y = __float2bfloat16(v3 - __bfloat162float(h3));
        *(__nv_bfloat162*)&ahi[b0] = hp01;
        *(__nv_bfloat162*)&ahi[b1] = hp23;
        *(__nv_bfloat162*)&alo[b0] = lp01;
        *(__nv_bfloat162*)&alo[b1] = lp23;
    }
}

// ---------------------------------------------------------------------------
// Launch
// ---------------------------------------------------------------------------
extern "C" void kernel_launch(void* const* d_in, const int* in_sizes, int n_in,
                              void* d_out, int out_size) {
    const float* X  = (const float*)d_in[0];
    const float* Wq = (const float*)d_in[2];
    const float* Wk = (const float*)d_in[3];
    const float* Wv = (const float*)d_in[4];
    const float* Wo = (const float*)d_in[5];
    const float* qw = (const float*)d_in[6];
    const float* kw = (const float*)d_in[7];

    float* out   = (float*)d_out;
    float* new_k = out + (size_t)S_LEN * HIDDEN;
    float* new_v = new_k + (size_t)NKV * S_LEN * HDIM;
    float* probs = new_v + (size_t)NKV * S_LEN * HDIM;

    float *qtmp, *ktmp, *vtmp;
    __nv_bfloat16 *xhi, *xlo, *ahi, *alo, *qhi, *qlo, *khi, *klo, *vthi, *vtlo;
    __nv_bfloat16 *wqh, *wql, *wkh, *wkl, *wvh, *wvl, *woh, *wol;
    cudaGetSymbolAddress((void**)&qtmp, g_qtmp);
    cudaGetSymbolAddress((void**)&ktmp, g_ktmp);
    cudaGetSymbolAddress((void**)&vtmp, g_vtmp);
    cudaGetSymbolAddress((void**)&xhi, g_xhi);
    cudaGetSymbolAddress((void**)&xlo, g_xlo);
    cudaGetSymbolAddress((void**)&ahi, g_ahi);
    cudaGetSymbolAddress((void**)&alo, g_alo);
    cudaGetSymbolAddress((void**)&qhi, g_qhi);
    cudaGetSymbolAddress((void**)&qlo, g_qlo);
    cudaGetSymbolAddress((void**)&khi, g_khi);
    cudaGetSymbolAddress((void**)&klo, g_klo);
    cudaGetSymbolAddress((void**)&vthi, g_vthi);
    cudaGetSymbolAddress((void**)&vtlo, g_vtlo);
    cudaGetSymbolAddress((void**)&wqh, g_wqthi);
    cudaGetSymbolAddress((void**)&wql, g_wqtlo);
    cudaGetSymbolAddress((void**)&wkh, g_wkthi);
    cudaGetSymbolAddress((void**)&wkl, g_wktlo);
    cudaGetSymbolAddress((void**)&wvh, g_wvthi);
    cudaGetSymbolAddress((void**)&wvl, g_wvtlo);
    cudaGetSymbolAddress((void**)&woh, g_wothi);
    cudaGetSymbolAddress((void**)&wol, g_wotlo);

    // ---- conversions ----
    transpose_split_all<<<dim3(128, 128, 4), dim3(32, 8)>>>(
        Wq, Wk, Wv, Wo, wqh, wql, wkh, wkl, wvh, wvl, woh, wol);
    {
        int n = S_LEN * HIDDEN;
        split_kernel<<<(n + 255) / 256, 256>>>(X, xhi, xlo, n);
    }

    // ---- projections: Q, then K+V (split so ncu sample lands on a GEMM) ----
    cudaFuncSetAttribute(gemm_mma3, cudaFuncAttributeMaxDynamicSharedMemorySize,
                         GEMM3_SMEM);
    gemm_mma3<<<dim3(HIDDEN / 128, S_LEN / 256, 1), 256, GEMM3_SMEM>>>(
        xhi, xlo, wqh, wql, qtmp, HIDDEN, wqh, wql, qtmp, HIDDEN);
    gemm_mma3<<<dim3((NKV * HDIM) / 128, S_LEN / 256, 2), 256, GEMM3_SMEM>>>(
        xhi, xlo, wkh, wkl, ktmp, NKV * HDIM, wvh, wvl, vtmp, NKV * HDIM);

    // ---- RMSNorm + RoPE + splits ----
    norm_rope_q<<<dim3(S_LEN, NHEADS), 128>>>(qtmp, qw, qhi, qlo);
    norm_rope_k<<<dim3(S_LEN, NKV), 128>>>(ktmp, kw, new_k, khi, klo);

    // ---- V transpose + split ----
    v_split_transpose<<<dim3(S_LEN / 32, HDIM / 32, NKV), dim3(32, 8)>>>(
        vtmp, new_v, vthi, vtlo);

    // ---- attention ----
    cudaFuncSetAttribute(attention_mma,
                         cudaFuncAttributeMaxDynamicSharedMemorySize, AT_SMEM_BYTES);
    attention_mma<<<dim3(S_LEN / 128, NHEADS), 256, AT_SMEM_BYTES>>>(
        qhi, qlo, khi, klo, vthi, vtlo, probs, ahi, alo);

    // ---- O projection ----
    gemm_mma3<<<dim3(HIDDEN / 128, S_LEN / 256, 1), 256, GEMM3_SMEM>>>(
        ahi, alo, woh, wol, out, HIDDEN, woh, wol, out, HIDDEN);
}

// round 10
// speedup vs baseline: 3.2993x; 1.0072x over previous
#include <cuda_runtime.h>
#include <cuda_bf16.h>
#include <math.h>
#include <stdint.h>

// ---------------------------------------------------------------------------
// Problem constants
// ---------------------------------------------------------------------------
#define S_LEN   2048
#define HIDDEN  4096
#define NHEADS  32
#define NKV     8
#define HDIM    128

// ---------------------------------------------------------------------------
// Device scratch
// ---------------------------------------------------------------------------
__device__ float g_qtmp[S_LEN * NHEADS * HDIM];
__device__ float g_ktmp[S_LEN * NKV * HDIM];
__device__ float g_vtmp[S_LEN * NKV * HDIM];

__device__ __nv_bfloat16 g_xhi[S_LEN * HIDDEN];
__device__ __nv_bfloat16 g_xlo[S_LEN * HIDDEN];
__device__ __nv_bfloat16 g_ahi[S_LEN * HIDDEN];
__device__ __nv_bfloat16 g_alo[S_LEN * HIDDEN];
__device__ __nv_bfloat16 g_qhi[NHEADS * S_LEN * HDIM];
__device__ __nv_bfloat16 g_qlo[NHEADS * S_LEN * HDIM];
__device__ __nv_bfloat16 g_khi[NKV * S_LEN * HDIM];
__device__ __nv_bfloat16 g_klo[NKV * S_LEN * HDIM];
__device__ __nv_bfloat16 g_vthi[NKV * HDIM * S_LEN];
__device__ __nv_bfloat16 g_vtlo[NKV * HDIM * S_LEN];
__device__ __nv_bfloat16 g_wqthi[HIDDEN * HIDDEN];
__device__ __nv_bfloat16 g_wqtlo[HIDDEN * HIDDEN];
__device__ __nv_bfloat16 g_wkthi[(NKV * HDIM) * HIDDEN];
__device__ __nv_bfloat16 g_wktlo[(NKV * HDIM) * HIDDEN];
__device__ __nv_bfloat16 g_wvthi[(NKV * HDIM) * HIDDEN];
__device__ __nv_bfloat16 g_wvtlo[(NKV * HDIM) * HIDDEN];
__device__ __nv_bfloat16 g_wothi[HIDDEN * HIDDEN];
__device__ __nv_bfloat16 g_wotlo[HIDDEN * HIDDEN];

// ---------------------------------------------------------------------------
// Low-level helpers
// ---------------------------------------------------------------------------
__device__ __forceinline__ uint32_t smem_to_u32(const void* p) {
    uint32_t a;
    asm("{ .reg .u64 t; cvta.to.shared.u64 t, %1; cvt.u32.u64 %0, t; }"
        : "=r"(a) : "l"(p));
    return a;
}
__device__ __forceinline__ void cpasync16(uint32_t saddr, const void* g) {
    asm volatile("cp.async.cg.shared.global [%0], [%1], 16;"
                 :: "r"(saddr), "l"(g));
}
#define CP_COMMIT() asm volatile("cp.async.commit_group;" ::: "memory")
#define CP_WAIT(n)  asm volatile("cp.async.wait_group %0;" :: "n"(n) : "memory")

__device__ __forceinline__ void ldsm_x4(uint32_t addr, uint32_t r[4]) {
    asm volatile("ldmatrix.sync.aligned.m8n8.x4.shared.b16 {%0,%1,%2,%3}, [%4];"
        : "=r"(r[0]), "=r"(r[1]), "=r"(r[2]), "=r"(r[3]) : "r"(addr));
}
__device__ __forceinline__ void mma16816(float d[4], const uint32_t a[4],
                                         const uint32_t b0, const uint32_t b1) {
    asm volatile(
        "mma.sync.aligned.m16n8k16.row.col.f32.bf16.bf16.f32 "
        "{%0,%1,%2,%3}, {%4,%5,%6,%7}, {%8,%9}, {%0,%1,%2,%3};"
        : "+f"(d[0]), "+f"(d[1]), "+f"(d[2]), "+f"(d[3])
        : "r"(a[0]), "r"(a[1]), "r"(a[2]), "r"(a[3]), "r"(b0), "r"(b1));
}

// ---------------------------------------------------------------------------
// Projection GEMM v5: 256x128 tile, BK=64, 512 threads (16 warps, 4x4),
// warp tile 64x32, single-sync multistage, flat segmented grid (Q|K|V fused),
// serpentine within each segment, hi/lo 3-term.
// ---------------------------------------------------------------------------
#define SP3       72
#define A3_ELEMS  (256 * SP3)
#define B3_ELEMS  (128 * SP3)
#define STG3      (2 * A3_ELEMS + 2 * B3_ELEMS)
#define GEMM3_SMEM (2 * STG3 * 2)
#define NCH3      (HIDDEN / 64)

__global__ __launch_bounds__(512) void gemm_mma3(
    const __nv_bfloat16* __restrict__ Ahi, const __nv_bfloat16* __restrict__ Alo,
    const __nv_bfloat16* __restrict__ Bh0, const __nv_bfloat16* __restrict__ Bl0,
    float* __restrict__ C0, int N0,
    const __nv_bfloat16* __restrict__ Bh1, const __nv_bfloat16* __restrict__ Bl1,
    float* __restrict__ C1, int N1,
    const __nv_bfloat16* __restrict__ Bh2, const __nv_bfloat16* __restrict__ Bl2,
    float* __restrict__ C2, int N2,
    int seg1, int seg2) {
    extern __shared__ __align__(16) __nv_bfloat16 smbuf[];
    const int flat = blockIdx.x;
    const __nv_bfloat16* Bhi;
    const __nv_bfloat16* Blo;
    float* C;
    int Ntot, local;
    if (flat < seg1)      { Bhi = Bh0; Blo = Bl0; C = C0; Ntot = N0; local = flat; }
    else if (flat < seg2) { Bhi = Bh1; Blo = Bl1; C = C1; Ntot = N1; local = flat - seg1; }
    else                  { Bhi = Bh2; Blo = Bl2; C = C2; Ntot = N2; local = flat - seg2; }

    const int nx_eff = Ntot >> 7;
    const int per = 4 * nx_eff;
    const int grp = local / per, rem = local % per;
    const int m0 = (grp * 4 + (rem & 3)) * 256;
    const int n0 = (rem >> 2) * 128;

    const uint32_t sb = smem_to_u32(smbuf);
    const int tid  = threadIdx.x;
    const int lane = tid & 31;
    const int wid  = tid >> 5;              // 0..15
    const int wm = (wid >> 2) * 64;         // 4 m-groups
    const int wn = (wid & 3) * 32;          // 4 n-groups
    const int quad = lane >> 3;
    const int wi   = lane & 7;
    const int arow = (quad & 1) * 8 + wi;
    const int acol = (quad >> 1) * 8;
    const int brow = (quad >> 1) * 8 + wi;
    const int bcol = (quad & 1) * 8;

    float acc[4][4][4];                      // 64 regs
#pragma unroll
    for (int mt = 0; mt < 4; mt++)
#pragma unroll
        for (int nt = 0; nt < 4; nt++)
#pragma unroll
            for (int q = 0; q < 4; q++) acc[mt][nt][q] = 0.f;

    auto load_stage = [&](int buf, int chunk) {
        const int k0 = chunk * 64;
        const uint32_t sbase = sb + (uint32_t)buf * STG3 * 2;
#pragma unroll
        for (int t = 0; t < 4; t++) {           // A: 2048 chunks of 16B
            int c = tid + t * 512;
            int row = c >> 3;
            int kc  = (c & 7) * 8;
            uint32_t so = sbase + (uint32_t)(row * SP3 + kc) * 2;
            size_t goA = (size_t)(m0 + row) * HIDDEN + k0 + kc;
            cpasync16(so,                Ahi + goA);
            cpasync16(so + A3_ELEMS * 2, Alo + goA);
        }
#pragma unroll
        for (int t = 0; t < 2; t++) {           // B: 1024 chunks of 16B
            int c = tid + t * 512;
            int row = c >> 3;
            int kc  = (c & 7) * 8;
            uint32_t so = sbase + (uint32_t)(2 * A3_ELEMS + row * SP3 + kc) * 2;
            size_t goB = (size_t)(n0 + row) * HIDDEN + k0 + kc;
            cpasync16(so,                Bhi + goB);
            cpasync16(so + B3_ELEMS * 2, Blo + goB);
        }
    };

    load_stage(0, 0);
    CP_COMMIT();

    for (int chunk = 0; chunk < NCH3; chunk++) {
        CP_WAIT(0);
        __syncthreads();
        if (chunk + 1 < NCH3) {
            load_stage((chunk + 1) & 1, chunk + 1);
            CP_COMMIT();
        }
        const uint32_t stage = sb + (uint32_t)(chunk & 1) * STG3 * 2;
#pragma unroll
        for (int kk = 0; kk < 4; kk++) {
            uint32_t bH[2][4], bL[2][4];
#pragma unroll
            for (int nt2 = 0; nt2 < 2; nt2++) {
                uint32_t bo = (uint32_t)(2 * A3_ELEMS + (wn + nt2 * 16 + brow) * SP3 +
                                         kk * 16 + bcol) * 2;
                ldsm_x4(stage + bo, bH[nt2]);
                ldsm_x4(stage + B3_ELEMS * 2 + bo, bL[nt2]);
            }
#pragma unroll
            for (int mt = 0; mt < 4; mt++) {
                uint32_t aH[4], aL[4];
                uint32_t ao = (uint32_t)((wm + mt * 16 + arow) * SP3 + kk * 16 + acol) * 2;
                ldsm_x4(stage + ao, aH);
                ldsm_x4(stage + A3_ELEMS * 2 + ao, aL);
#pragma unroll
                for (int nt = 0; nt < 4; nt++) {
                    uint32_t h0 = bH[nt >> 1][(nt & 1) * 2];
                    uint32_t h1 = bH[nt >> 1][(nt & 1) * 2 + 1];
                    uint32_t l0 = bL[nt >> 1][(nt & 1) * 2];
                    uint32_t l1 = bL[nt >> 1][(nt & 1) * 2 + 1];
                    mma16816(acc[mt][nt], aH, h0, h1);
                    mma16816(acc[mt][nt], aL, h0, h1);
                    mma16816(acc[mt][nt], aH, l0, l1);
                }
            }
        }
    }

    __syncthreads();
    const int erow = lane >> 2;
    const int ecol = (lane & 3) * 2;
#pragma unroll
    for (int mt = 0; mt < 4; mt++) {
#pragma unroll
        for (int nt = 0; nt < 4; nt++) {
            int r = m0 + wm + mt * 16 + erow;
            int c = n0 + wn + nt * 8 + ecol;
            *(float2*)&C[(size_t)r * Ntot + c] =
                make_float2(acc[mt][nt][0], acc[mt][nt][1]);
            *(float2*)&C[(size_t)(r + 8) * Ntot + c] =
                make_float2(acc[mt][nt][2], acc[mt][nt][3]);
        }
    }
}

// ---------------------------------------------------------------------------
// f32 -> bf16 hi/lo split
// ---------------------------------------------------------------------------
__global__ void split_kernel(const float* __restrict__ x,
                             __nv_bfloat16* __restrict__ hi,
                             __nv_bfloat16* __restrict__ lo, int n) {
    int i = blockIdx.x * 256 + threadIdx.x;
    if (i >= n) return;
    float v = x[i];
    __nv_bfloat16 h = __float2bfloat16(v);
    hi[i] = h;
    lo[i] = __float2bfloat16(v - __bfloat162float(h));
}

// ---------------------------------------------------------------------------
// All 4 weight transposes fused
// ---------------------------------------------------------------------------
__global__ __launch_bounds__(256) void transpose_split_all(
    const float* __restrict__ Wq, const float* __restrict__ Wk,
    const float* __restrict__ Wv, const float* __restrict__ Wo,
    __nv_bfloat16* __restrict__ qh, __nv_bfloat16* __restrict__ ql,
    __nv_bfloat16* __restrict__ kh, __nv_bfloat16* __restrict__ kl,
    __nv_bfloat16* __restrict__ vh, __nv_bfloat16* __restrict__ vl,
    __nv_bfloat16* __restrict__ oh, __nv_bfloat16* __restrict__ ol) {
    const float* W; __nv_bfloat16 *hi, *lo; int N;
    switch (blockIdx.z) {
        case 0: W = Wq; hi = qh; lo = ql; N = HIDDEN; break;
        case 1: W = Wk; hi = kh; lo = kl; N = NKV * HDIM; break;
        case 2: W = Wv; hi = vh; lo = vl; N = NKV * HDIM; break;
        default: W = Wo; hi = oh; lo = ol; N = HIDDEN; break;
    }
    const int n0 = blockIdx.x * 32;
    if (n0 >= N) return;
    const int k0 = blockIdx.y * 32;
    __shared__ float t[32][33];
    const int tx = threadIdx.x;
    for (int r = threadIdx.y; r < 32; r += 8)
        t[r][tx] = W[(size_t)(k0 + r) * N + n0 + tx];
    __syncthreads();
    for (int r = threadIdx.y; r < 32; r += 8) {
        float v = t[tx][r];
        __nv_bfloat16 h = __float2bfloat16(v);
        size_t o = (size_t)(n0 + r) * HIDDEN + k0 + tx;
        hi[o] = h;
        lo[o] = __float2bfloat16(v - __bfloat162float(h));
    }
}

// ---------------------------------------------------------------------------
// RMSNorm + RoPE for Q (pre-scaled hi/lo splits)
// ---------------------------------------------------------------------------
__global__ __launch_bounds__(128) void norm_rope_q(
    const float* __restrict__ inp, const float* __restrict__ w,
    __nv_bfloat16* __restrict__ qhi, __nv_bfloat16* __restrict__ qlo) {
    const int s = blockIdx.x;
    const int h = blockIdx.y;
    const int d = threadIdx.x;

    float x = inp[((size_t)s * NHEADS + h) * HDIM + d];
    float ss = x * x;
#pragma unroll
    for (int o = 16; o; o >>= 1) ss += __shfl_xor_sync(0xffffffffu, ss, o);
    __shared__ float wss[4];
    __shared__ float xs[HDIM];
    if ((d & 31) == 0) wss[d >> 5] = ss;
    __syncthreads();
    float var = (wss[0] + wss[1] + wss[2] + wss[3]) * (1.0f / 128.0f);
    xs[d] = x * rsqrtf(var + 1e-6f) * w[d];
    __syncthreads();

    if (d < 64) {
        const float scale = 0.08838834764831845f;
        float p = (float)s;
        float e = (float)(2 * d) * (1.0f / 128.0f);
        float invf = powf(1000000.0f, -e);
        float si, c;
        sincosf(p * invf, &si, &c);
        float x1 = xs[d], x2 = xs[d + 64];
        float r1 = (x1 * c - x2 * si) * scale;
        float r2 = (x2 * c + x1 * si) * scale;
        size_t base = ((size_t)h * S_LEN + s) * HDIM;
        __nv_bfloat16 h1 = __float2bfloat16(r1);
        __nv_bfloat16 h2 = __float2bfloat16(r2);
        qhi[base + d]      = h1;
        qhi[base + d + 64] = h2;
        qlo[base + d]      = __float2bfloat16(r1 - __bfloat162float(h1));
        qlo[base + d + 64] = __float2bfloat16(r2 - __bfloat162float(h2));
    }
}

// ---------------------------------------------------------------------------
// RMSNorm + RoPE for K (f32 new_k + hi/lo splits)
// ---------------------------------------------------------------------------
__global__ __launch_bounds__(128) void norm_rope_k(
    const float* __restrict__ inp, const float* __restrict__ w,
    float* __restrict__ outf,
    __nv_bfloat16* __restrict__ khi, __nv_bfloat16* __restrict__ klo) {
    const int s = blockIdx.x;
    const int h = blockIdx.y;
    const int d = threadIdx.x;

    float x = inp[((size_t)s * NKV + h) * HDIM + d];
    float ss = x * x;
#pragma unroll
    for (int o = 16; o; o >>= 1) ss += __shfl_xor_sync(0xffffffffu, ss, o);
    __shared__ float wss[4];
    __shared__ float xs[HDIM];
    if ((d & 31) == 0) wss[d >> 5] = ss;
    __syncthreads();
    float var = (wss[0] + wss[1] + wss[2] + wss[3]) * (1.0f / 128.0f);
    xs[d] = x * rsqrtf(var + 1e-6f) * w[d];
    __syncthreads();

    if (d < 64) {
        float p = (float)s;
        float e = (float)(2 * d) * (1.0f / 128.0f);
        float invf = powf(1000000.0f, -e);
        float si, c;
        sincosf(p * invf, &si, &c);
        float x1 = xs[d], x2 = xs[d + 64];
        float r1 = x1 * c - x2 * si;
        float r2 = x2 * c + x1 * si;
        size_t base = ((size_t)h * S_LEN + s) * HDIM;
        outf[base + d]      = r1;
        outf[base + d + 64] = r2;
        __nv_bfloat16 h1 = __float2bfloat16(r1);
        __nv_bfloat16 h2 = __float2bfloat16(r2);
        khi[base + d]      = h1;
        khi[base + d + 64] = h2;
        klo[base + d]      = __float2bfloat16(r1 - __bfloat162float(h1));
        klo[base + d + 64] = __float2bfloat16(r2 - __bfloat162float(h2));
    }
}

// ---------------------------------------------------------------------------
// V: [s][kv*128+d] -> new_v f32 [kv][s][d] + V^T splits [kv][d][s] bf16
// ---------------------------------------------------------------------------
__global__ __launch_bounds__(256) void v_split_transpose(
    const float* __restrict__ vt, float* __restrict__ outf,
    __nv_bfloat16* __restrict__ vthi, __nv_bfloat16* __restrict__ vtlo) {
    __shared__ float t[32][33];
    const int kv = blockIdx.z;
    const int s0 = blockIdx.x * 32;
    const int d0 = blockIdx.y * 32;
    const int tx = threadIdx.x;
    for (int r = threadIdx.y; r < 32; r += 8) {
        float v = vt[(size_t)(s0 + r) * (NKV * HDIM) + kv * HDIM + d0 + tx];
        t[r][tx] = v;
        outf[((size_t)kv * S_LEN + s0 + r) * HDIM + d0 + tx] = v;
    }
    __syncthreads();
    for (int r = threadIdx.y; r < 32; r += 8) {
        float v = t[tx][r];
        __nv_bfloat16 h = __float2bfloat16(v);
        size_t o = ((size_t)kv * HDIM + d0 + r) * S_LEN + s0 + tx;
        vthi[o] = h;
        vtlo[o] = __float2bfloat16(v - __bfloat162float(h));
    }
}

// ---------------------------------------------------------------------------
// Tensor-core attention (unchanged from round 9 — passing)
//  Pass 1: QK^T raw scores -> probs, online stats.
//  Pass 2: stream scores back, normalize, P@V.
// ---------------------------------------------------------------------------
#define AT_QP 136
#define AT_VP 72
#define S_PITCH_F 72
#define SQHI 0
#define SQLO (128 * AT_QP)
#define SSST (2 * 128 * AT_QP)
#define SSTAGE_UNITS (128 * S_PITCH_F * 2)
#define SVHI (SSST + 2 * SSTAGE_UNITS)
#define SVLO (SVHI + 128 * AT_VP)
#define SPHI (SVLO + 128 * AT_VP)
#define SPLO (SPHI + 128 * AT_VP)
#define AT_SMEM_ELEMS (SPLO + 128 * AT_VP)
#define AT_SMEM_BYTES (AT_SMEM_ELEMS * 2)

__global__ __launch_bounds__(256) void attention_mma(
    const __nv_bfloat16* __restrict__ qhi, const __nv_bfloat16* __restrict__ qlo,
    const __nv_bfloat16* __restrict__ khi, const __nv_bfloat16* __restrict__ klo,
    const __nv_bfloat16* __restrict__ vthi, const __nv_bfloat16* __restrict__ vtlo,
    float* __restrict__ probs,
    __nv_bfloat16* __restrict__ ahi, __nv_bfloat16* __restrict__ alo) {
    extern __shared__ __align__(16) __nv_bfloat16 smbuf[];
    const uint32_t sb = smem_to_u32(smbuf);
    const int h   = blockIdx.y;
    const int kvh = h >> 2;
    const int q0  = (int)(gridDim.x - 1 - blockIdx.x) * 128;
    const int tid = threadIdx.x;
    const int lane = tid & 31;
    const int wid  = tid >> 5;
    const int quad = lane >> 3, wi = lane & 7;
    const int wm   = wid * 16;
    const int arow = (quad & 1) * 8 + wi, acol = (quad >> 1) * 8;
    const int brow = (quad >> 1) * 8 + wi, bcol = (quad & 1) * 8;
    const int erow = lane >> 2, fc = (lane & 3) * 2;
    const int grow0 = q0 + wm + erow;
    const int grow1 = grow0 + 8;

    auto issue_K = [&](int jt, int buf) {
        const int c0 = jt * 64;
        const uint32_t kbase = SSST + (uint32_t)buf * SSTAGE_UNITS;
#pragma unroll
        for (int i = 0; i < 4; i++) {
            int idx = tid + i * 256;
            int row = idx >> 4, ch = idx & 15;
            size_t go = ((size_t)kvh * S_LEN + c0 + row) * HDIM + ch * 8;
            cpasync16(sb + (uint32_t)(kbase + row * AT_QP + ch * 8) * 2, khi + go);
            cpasync16(sb + (uint32_t)(kbase + 64 * AT_QP + row * AT_QP + ch * 8) * 2, klo + go);
        }
    };
    auto issue_V = [&](int jt) {
        const int c0 = jt * 64;
#pragma unroll
        for (int i = 0; i < 4; i++) {
            int idx = tid + i * 256;
            int row = idx >> 3, ch = idx & 7;
            size_t go = ((size_t)kvh * HDIM + row) * S_LEN + c0 + ch * 8;
            cpasync16(sb + (uint32_t)(SVHI + row * AT_VP + ch * 8) * 2, vthi + go);
            cpasync16(sb + (uint32_t)(SVLO + row * AT_VP + ch * 8) * 2, vtlo + go);
        }
    };
    auto issue_S = [&](int jt, int buf) {
        const int c0 = jt * 64;
        const uint32_t sbase = (uint32_t)((SSST + buf * SSTAGE_UNITS) * 2);
#pragma unroll
        for (int i = 0; i < 8; i++) {
            int idx = tid + i * 256;
            int row = idx >> 4, ch = idx & 15;
            const float* g = &probs[((size_t)h * S_LEN + q0 + row) * S_LEN + c0 + ch * 4];
            cpasync16(sb + sbase + (uint32_t)(row * S_PITCH_F + ch * 4) * 4, g);
        }
    };
    auto compute_S = [&](int buf, float s[8][4]) {
        const uint32_t kbase = SSST + (uint32_t)buf * SSTAGE_UNITS;
#pragma unroll
        for (int nt = 0; nt < 8; nt++)
#pragma unroll
            for (int q = 0; q < 4; q++) s[nt][q] = 0.f;
#pragma unroll
        for (int term = 0; term < 3; term++) {
            const uint32_t qb = (term == 1) ? SQLO : SQHI;
            const uint32_t kb = kbase + ((term == 2) ? (uint32_t)(64 * AT_QP) : 0u);
#pragma unroll
            for (int kk = 0; kk < 8; kk++) {
                uint32_t a[4], b[4][4];
                ldsm_x4(sb + (uint32_t)(qb + (wm + arow) * AT_QP + kk * 16 + acol) * 2, a);
#pragma unroll
                for (int nt2 = 0; nt2 < 4; nt2++)
                    ldsm_x4(sb + (uint32_t)(kb + (nt2 * 16 + brow) * AT_QP + kk * 16 + bcol) * 2, b[nt2]);
#pragma unroll
                for (int nt = 0; nt < 8; nt++)
                    mma16816(s[nt], a, b[nt >> 1][(nt & 1) * 2], b[nt >> 1][(nt & 1) * 2 + 1]);
            }
        }
    };

    const int jmax = (q0 + 127) >> 6;
    float m0 = -1e30f, m1 = -1e30f, l0 = 0.f, l1 = 0.f;

#pragma unroll
    for (int i = 0; i < 8; i++) {
        int idx = tid + i * 256;
        int row = idx >> 4, ch = idx & 15;
        size_t go = ((size_t)h * S_LEN + q0 + row) * HDIM + ch * 8;
        cpasync16(sb + (uint32_t)(SQHI + row * AT_QP + ch * 8) * 2, qhi + go);
        cpasync16(sb + (uint32_t)(SQLO + row * AT_QP + ch * 8) * 2, qlo + go);
    }
    issue_K(0, 0);
    CP_COMMIT();

    // ================= PASS 1 =================
    for (int jt = 0; jt <= jmax; jt++) {
        if (jt < jmax) {
            issue_K(jt + 1, (jt + 1) & 1);
            CP_COMMIT();
            CP_WAIT(1);
        } else {
            CP_WAIT(0);
        }
        __syncthreads();

        float s[8][4];
        compute_S(jt & 1, s);

        const int c0 = jt * 64;
        float tm0 = -1e30f, tm1 = -1e30f;
#pragma unroll
        for (int nt = 0; nt < 8; nt++) {
            int cb = c0 + nt * 8 + fc;
            if (cb     > grow0) s[nt][0] = -1e30f;
            if (cb + 1 > grow0) s[nt][1] = -1e30f;
            if (cb     > grow1) s[nt][2] = -1e30f;
            if (cb + 1 > grow1) s[nt][3] = -1e30f;
            *(float2*)&probs[((size_t)h * S_LEN + grow0) * S_LEN + cb] =
                make_float2(s[nt][0], s[nt][1]);
            *(float2*)&probs[((size_t)h * S_LEN + grow1) * S_LEN + cb] =
                make_float2(s[nt][2], s[nt][3]);
            tm0 = fmaxf(tm0, fmaxf(s[nt][0], s[nt][1]));
            tm1 = fmaxf(tm1, fmaxf(s[nt][2], s[nt][3]));
        }
        tm0 = fmaxf(tm0, __shfl_xor_sync(0xffffffffu, tm0, 1));
        tm0 = fmaxf(tm0, __shfl_xor_sync(0xffffffffu, tm0, 2));
        tm1 = fmaxf(tm1, __shfl_xor_sync(0xffffffffu, tm1, 1));
        tm1 = fmaxf(tm1, __shfl_xor_sync(0xffffffffu, tm1, 2));
        float mn0 = fmaxf(m0, tm0), mn1 = fmaxf(m1, tm1);
        float su0 = 0.f, su1 = 0.f;
#pragma unroll
        for (int nt = 0; nt < 8; nt++) {
            su0 += __expf(s[nt][0] - mn0) + __expf(s[nt][1] - mn0);
            su1 += __expf(s[nt][2] - mn1) + __expf(s[nt][3] - mn1);
        }
        su0 += __shfl_xor_sync(0xffffffffu, su0, 1);
        su0 += __shfl_xor_sync(0xffffffffu, su0, 2);
        su1 += __shfl_xor_sync(0xffffffffu, su1, 1);
        su1 += __shfl_xor_sync(0xffffffffu, su1, 2);
        l0 = l0 * __expf(m0 - mn0) + su0; m0 = mn0;
        l1 = l1 * __expf(m1 - mn1) + su1; m1 = mn1;
        __syncthreads();
    }
    const float li0 = 1.0f / l0, li1 = 1.0f / l1;

    {
        float2 z = make_float2(0.f, 0.f);
        for (int jt = jmax + 1; jt < S_LEN / 64; jt++) {
            const int c0 = jt * 64;
#pragma unroll
            for (int nt = 0; nt < 8; nt++) {
                int col = c0 + nt * 8 + fc;
                *(float2*)&probs[((size_t)h * S_LEN + grow0) * S_LEN + col] = z;
                *(float2*)&probs[((size_t)h * S_LEN + grow1) * S_LEN + col] = z;
            }
        }
    }

    float o[16][4];
#pragma unroll
    for (int nt = 0; nt < 16; nt++)
#pragma unroll
        for (int q = 0; q < 4; q++) o[nt][q] = 0.f;

    issue_S(0, 0);
    CP_COMMIT();
    issue_V(0);
    CP_COMMIT();

    // ================= PASS 2 =================
    for (int jt = 0; jt <= jmax; jt++) {
        if (jt < jmax) {
            issue_S(jt + 1, (jt + 1) & 1);
            CP_COMMIT();
            CP_WAIT(2);
        } else {
            CP_WAIT(1);
        }
        __syncthreads();

        const float* sf = (const float*)&smbuf[SSST + (jt & 1) * SSTAGE_UNITS];
        const int c0 = jt * 64;
        const int pr0 = wm + erow, pr1 = pr0 + 8;
#pragma unroll
        for (int nt = 0; nt < 8; nt++) {
            int cl = nt * 8 + fc;
            float2 s01 = *(const float2*)&sf[pr0 * S_PITCH_F + cl];
            float2 s23 = *(const float2*)&sf[pr1 * S_PITCH_F + cl];
            float p0 = __expf(s01.x - m0) * li0;
            float p1 = __expf(s01.y - m0) * li0;
            float p2 = __expf(s23.x - m1) * li1;
            float p3 = __expf(s23.y - m1) * li1;
            int cb = c0 + cl;
            *(float2*)&probs[((size_t)h * S_LEN + grow0) * S_LEN + cb] = make_float2(p0, p1);
            *(float2*)&probs[((size_t)h * S_LEN + grow1) * S_LEN + cb] = make_float2(p2, p3);
            __nv_bfloat16 h0 = __float2bfloat16(p0), h1 = __float2bfloat16(p1);
            __nv_bfloat16 h2 = __float2bfloat16(p2), h3 = __float2bfloat16(p3);
            __nv_bfloat162 hp01; hp01.x = h0; hp01.y = h1;
            __nv_bfloat162 hp23; hp23.x = h2; hp23.y = h3;
            __nv_bfloat162 lp01, lp23;
            lp01.x = __float2bfloat16(p0 - __bfloat162float(h0));
            lp01.y = __float2bfloat16(p1 - __bfloat162float(h1));
            lp23.x = __float2bfloat16(p2 - __bfloat162float(h2));
            lp23.y = __float2bfloat16(p3 - __bfloat162float(h3));
            *(__nv_bfloat162*)&smbuf[SPHI + pr0 * AT_VP + cl] = hp01;
            *(__nv_bfloat162*)&smbuf[SPHI + pr1 * AT_VP + cl] = hp23;
            *(__nv_bfloat162*)&smbuf[SPLO + pr0 * AT_VP + cl] = lp01;
            *(__nv_bfloat162*)&smbuf[SPLO + pr1 * AT_VP + cl] = lp23;
        }
        __syncwarp();

        if (jt < jmax) CP_WAIT(1); else CP_WAIT(0);
        __syncthreads();

#pragma unroll
        for (int term = 0; term < 3; term++) {
            const int pb = (term == 1) ? SPLO : SPHI;
            const int vb = (term == 2) ? SVLO : SVHI;
#pragma unroll
            for (int kk = 0; kk < 4; kk++) {
                uint32_t a[4], b[8][4];
                ldsm_x4(sb + (uint32_t)(pb + (wm + arow) * AT_VP + kk * 16 + acol) * 2, a);
#pragma unroll
                for (int nt2 = 0; nt2 < 8; nt2++)
                    ldsm_x4(sb + (uint32_t)(vb + (nt2 * 16 + brow) * AT_VP + kk * 16 + bcol) * 2, b[nt2]);
#pragma unroll
                for (int nt = 0; nt < 16; nt++)
                    mma16816(o[nt], a, b[nt >> 1][(nt & 1) * 2], b[nt >> 1][(nt & 1) * 2 + 1]);
            }
        }
        __syncthreads();

        if (jt < jmax) {
            issue_V(jt + 1);
            CP_COMMIT();
        }
    }

#pragma unroll
    for (int nt = 0; nt < 16; nt++) {
        int d = nt * 8 + fc;
        size_t b0 = (size_t)grow0 * HIDDEN + h * HDIM + d;
        size_t b1 = (size_t)grow1 * HIDDEN + h * HDIM + d;
        float v0 = o[nt][0], v1 = o[nt][1], v2 = o[nt][2], v3 = o[nt][3];
        __nv_bfloat16 h0 = __float2bfloat16(v0), h1 = __float2bfloat16(v1);
        __nv_bfloat16 h2 = __float2bfloat16(v2), h3 = __float2bfloat16(v3);
        __nv_bfloat162 hp01; hp01.x = h0; hp01.y = h1;
        __nv_bfloat162 hp23; hp23.x = h2; hp23.y = h3;
        __nv_bfloat162 lp01, lp23;
        lp01.x = __float2bfloat16(v0 - __bfloat162float(h0));
        lp01.y = __float2bfloat16(v1 - __bfloat162float(h1));
        lp23.x = __float2bfloat16(v2 - __bfloat162float(h2));
        lp23.y = __float2bfloat16(v3 - __bfloat162float(h3));
        *(__nv_bfloat162*)&ahi[b0] = hp01;
        *(__nv_bfloat162*)&ahi[b1] = hp23;
        *(__nv_bfloat162*)&alo[b0] = lp01;
        *(__nv_bfloat162*)&alo[b1] = lp23;
    }
}

// ---------------------------------------------------------------------------
// Launch
// ---------------------------------------------------------------------------
extern "C" void kernel_launch(void* const* d_in, const int* in_sizes, int n_in,
                              void* d_out, int out_size) {
    const float* X  = (const float*)d_in[0];
    const float* Wq = (const float*)d_in[2];
    const float* Wk = (const float*)d_in[3];
    const float* Wv = (const float*)d_in[4];
    const float* Wo = (const float*)d_in[5];
    const float* qw = (const float*)d_in[6];
    const float* kw = (const float*)d_in[7];

    float* out   = (float*)d_out;
    float* new_k = out + (size_t)S_LEN * HIDDEN;
    float* new_v = new_k + (size_t)NKV * S_LEN * HDIM;
    float* probs = new_v + (size_t)NKV * S_LEN * HDIM;

    float *qtmp, *ktmp, *vtmp;
    __nv_bfloat16 *xhi, *xlo, *ahi, *alo, *qhi, *qlo, *khi, *klo, *vthi, *vtlo;
    __nv_bfloat16 *wqh, *wql, *wkh, *wkl, *wvh, *wvl, *woh, *wol;
    cudaGetSymbolAddress((void**)&qtmp, g_qtmp);
    cudaGetSymbolAddress((void**)&ktmp, g_ktmp);
    cudaGetSymbolAddress((void**)&vtmp, g_vtmp);
    cudaGetSymbolAddress((void**)&xhi, g_xhi);
    cudaGetSymbolAddress((void**)&xlo, g_xlo);
    cudaGetSymbolAddress((void**)&ahi, g_ahi);
    cudaGetSymbolAddress((void**)&alo, g_alo);
    cudaGetSymbolAddress((void**)&qhi, g_qhi);
    cudaGetSymbolAddress((void**)&qlo, g_qlo);
    cudaGetSymbolAddress((void**)&khi, g_khi);
    cudaGetSymbolAddress((void**)&klo, g_klo);
    cudaGetSymbolAddress((void**)&vthi, g_vthi);
    cudaGetSymbolAddress((void**)&vtlo, g_vtlo);
    cudaGetSymbolAddress((void**)&wqh, g_wqthi);
    cudaGetSymbolAddress((void**)&wql, g_wqtlo);
    cudaGetSymbolAddress((void**)&wkh, g_wkthi);
    cudaGetSymbolAddress((void**)&wkl, g_wktlo);
    cudaGetSymbolAddress((void**)&wvh, g_wvthi);
    cudaGetSymbolAddress((void**)&wvl, g_wvtlo);
    cudaGetSymbolAddress((void**)&woh, g_wothi);
    cudaGetSymbolAddress((void**)&wol, g_wotlo);

    // ---- conversions ----
    transpose_split_all<<<dim3(128, 128, 4), dim3(32, 8)>>>(
        Wq, Wk, Wv, Wo, wqh, wql, wkh, wkl, wvh, wvl, woh, wol);
    {
        int n = S_LEN * HIDDEN;
        split_kernel<<<(n + 255) / 256, 256>>>(X, xhi, xlo, n);
    }

    // ---- Q+K+V fused: 256 Q-tiles + 64 K-tiles + 64 V-tiles = 384 CTAs ----
    cudaFuncSetAttribute(gemm_mma3, cudaFuncAttributeMaxDynamicSharedMemorySize,
                         GEMM3_SMEM);
    gemm_mma3<<<384, 512, GEMM3_SMEM>>>(
        xhi, xlo,
        wqh, wql, qtmp, HIDDEN,
        wkh, wkl, ktmp, NKV * HDIM,
        wvh, wvl, vtmp, NKV * HDIM,
        256, 320);

    // ---- RMSNorm + RoPE + splits ----
    norm_rope_q<<<dim3(S_LEN, NHEADS), 128>>>(qtmp, qw, qhi, qlo);
    norm_rope_k<<<dim3(S_LEN, NKV), 128>>>(ktmp, kw, new_k, khi, klo);

    // ---- V transpose + split ----
    v_split_transpose<<<dim3(S_LEN / 32, HDIM / 32, NKV), dim3(32, 8)>>>(
        vtmp, new_v, vthi, vtlo);

    // ---- attention ----
    cudaFuncSetAttribute(attention_mma,
                         cudaFuncAttributeMaxDynamicSharedMemorySize, AT_SMEM_BYTES);
    attention_mma<<<dim3(S_LEN / 128, NHEADS), 256, AT_SMEM_BYTES>>>(
        qhi, qlo, khi, klo, vthi, vtlo, probs, ahi, alo);

    // ---- O projection (Q-style segment only) ----
    gemm_mma3<<<256, 512, GEMM3_SMEM>>>(
        ahi, alo,
        woh, wol, out, HIDDEN,
        woh, wol, out, HIDDEN,
        woh, wol, out, HIDDEN,
        256, 256);
}

// round 11
// speedup vs baseline: 4.3061x; 1.3052x over previous
#include <cuda_runtime.h>
#include <cuda_fp16.h>
#include <math.h>
#include <stdint.h>

// ---------------------------------------------------------------------------
// Problem constants
// ---------------------------------------------------------------------------
#define S_LEN   2048
#define HIDDEN  4096
#define NHEADS  32
#define NKV     8
#define HDIM    128

// ---------------------------------------------------------------------------
// Device scratch (fp16 splits: hi/lo where split; single fp16 elsewhere)
// ---------------------------------------------------------------------------
__device__ float g_qtmp[S_LEN * NHEADS * HDIM];
__device__ float g_ktmp[S_LEN * NKV * HDIM];
__device__ float g_vtmp[S_LEN * NKV * HDIM];

__device__ __half g_xhi[S_LEN * HIDDEN];
__device__ __half g_xlo[S_LEN * HIDDEN];
__device__ __half g_ahi[S_LEN * HIDDEN];
__device__ __half g_alo[S_LEN * HIDDEN];
__device__ __half g_qhi[NHEADS * S_LEN * HDIM];   // pre-scaled, split
__device__ __half g_qlo[NHEADS * S_LEN * HDIM];
__device__ __half g_kh[NKV * S_LEN * HDIM];       // single fp16
__device__ __half g_vth[NKV * HDIM * S_LEN];      // single fp16, [kv][d][s]
__device__ __half g_wqt[HIDDEN * HIDDEN];         // W^T single fp16
__device__ __half g_wkt[(NKV * HDIM) * HIDDEN];
__device__ __half g_wvt[(NKV * HDIM) * HIDDEN];
__device__ __half g_wot[HIDDEN * HIDDEN];

// ---------------------------------------------------------------------------
// Low-level helpers
// ---------------------------------------------------------------------------
__device__ __forceinline__ uint32_t smem_to_u32(const void* p) {
    uint32_t a;
    asm("{ .reg .u64 t; cvta.to.shared.u64 t, %1; cvt.u32.u64 %0, t; }"
        : "=r"(a) : "l"(p));
    return a;
}
__device__ __forceinline__ void cpasync16(uint32_t saddr, const void* g) {
    asm volatile("cp.async.cg.shared.global [%0], [%1], 16;"
                 :: "r"(saddr), "l"(g));
}
#define CP_COMMIT() asm volatile("cp.async.commit_group;" ::: "memory")
#define CP_WAIT(n)  asm volatile("cp.async.wait_group %0;" :: "n"(n) : "memory")

__device__ __forceinline__ void ldsm_x4(uint32_t addr, uint32_t r[4]) {
    asm volatile("ldmatrix.sync.aligned.m8n8.x4.shared.b16 {%0,%1,%2,%3}, [%4];"
        : "=r"(r[0]), "=r"(r[1]), "=r"(r[2]), "=r"(r[3]) : "r"(addr));
}
// fp16 MMA, fp32 accum (base ISA sm_80+)
__device__ __forceinline__ void mma16816(float d[4], const uint32_t a[4],
                                         const uint32_t b0, const uint32_t b1) {
    asm volatile(
        "mma.sync.aligned.m16n8k16.row.col.f32.f16.f16.f32 "
        "{%0,%1,%2,%3}, {%4,%5,%6,%7}, {%8,%9}, {%0,%1,%2,%3};"
        : "+f"(d[0]), "+f"(d[1]), "+f"(d[2]), "+f"(d[3])
        : "r"(a[0]), "r"(a[1]), "r"(a[2]), "r"(a[3]), "r"(b0), "r"(b1));
}

__device__ __forceinline__ void split16(float v, __half& hi, __half& lo) {
    hi = __float2half(v);
    lo = __float2half(v - __half2float(hi));
}

// ---------------------------------------------------------------------------
// Projection GEMM v6: 256x128 tile, BK=64, 512 threads (16 warps 4x4),
// A split fp16 (2 tiles) x B single fp16 (1 tile) -> 2-term MMA.
// Flat segmented grid (Q|K|V fused), serpentine per segment.
// ---------------------------------------------------------------------------
#define SP3       72
#define A3_ELEMS  (256 * SP3)                  // 18432
#define B3_ELEMS  (128 * SP3)                  // 9216
#define STG3      (2 * A3_ELEMS + B3_ELEMS)    // 46080
#define GEMM3_SMEM (2 * STG3 * 2)              // 184320 B
#define NCH3      (HIDDEN / 64)

__global__ __launch_bounds__(512) void gemm_mma3(
    const __half* __restrict__ Ahi, const __half* __restrict__ Alo,
    const __half* __restrict__ B0, float* __restrict__ C0, int N0,
    const __half* __restrict__ B1, float* __restrict__ C1, int N1,
    const __half* __restrict__ B2, float* __restrict__ C2, int N2,
    int seg1, int seg2) {
    extern __shared__ __align__(16) __half smbuf[];
    const int flat = blockIdx.x;
    const __half* B;
    float* C;
    int Ntot, local;
    if (flat < seg1)      { B = B0; C = C0; Ntot = N0; local = flat; }
    else if (flat < seg2) { B = B1; C = C1; Ntot = N1; local = flat - seg1; }
    else                  { B = B2; C = C2; Ntot = N2; local = flat - seg2; }

    const int nx_eff = Ntot >> 7;
    const int per = 4 * nx_eff;
    const int grp = local / per, rem = local % per;
    const int m0 = (grp * 4 + (rem & 3)) * 256;
    const int n0 = (rem >> 2) * 128;

    const uint32_t sb = smem_to_u32(smbuf);
    const int tid  = threadIdx.x;
    const int lane = tid & 31;
    const int wid  = tid >> 5;
    const int wm = (wid >> 2) * 64;
    const int wn = (wid & 3) * 32;
    const int quad = lane >> 3;
    const int wi   = lane & 7;
    const int arow = (quad & 1) * 8 + wi;
    const int acol = (quad >> 1) * 8;
    const int brow = (quad >> 1) * 8 + wi;
    const int bcol = (quad & 1) * 8;

    float acc[4][4][4];
#pragma unroll
    for (int mt = 0; mt < 4; mt++)
#pragma unroll
        for (int nt = 0; nt < 4; nt++)
#pragma unroll
            for (int q = 0; q < 4; q++) acc[mt][nt][q] = 0.f;

    auto load_stage = [&](int buf, int chunk) {
        const int k0 = chunk * 64;
        const uint32_t sbase = sb + (uint32_t)buf * STG3 * 2;
#pragma unroll
        for (int t = 0; t < 4; t++) {            // A: 2048 slots (hi+lo)
            int c = tid + t * 512;
            int row = c >> 3;
            int kc  = (c & 7) * 8;
            uint32_t so = sbase + (uint32_t)(row * SP3 + kc) * 2;
            size_t goA = (size_t)(m0 + row) * HIDDEN + k0 + kc;
            cpasync16(so,                Ahi + goA);
            cpasync16(so + A3_ELEMS * 2, Alo + goA);
        }
#pragma unroll
        for (int t = 0; t < 2; t++) {            // B: 1024 slots (single)
            int c = tid + t * 512;
            int row = c >> 3;
            int kc  = (c & 7) * 8;
            uint32_t so = sbase + (uint32_t)(2 * A3_ELEMS + row * SP3 + kc) * 2;
            size_t goB = (size_t)(n0 + row) * HIDDEN + k0 + kc;
            cpasync16(so, B + goB);
        }
    };

    load_stage(0, 0);
    CP_COMMIT();

    for (int chunk = 0; chunk < NCH3; chunk++) {
        CP_WAIT(0);
        __syncthreads();
        if (chunk + 1 < NCH3) {
            load_stage((chunk + 1) & 1, chunk + 1);
            CP_COMMIT();
        }
        const uint32_t stage = sb + (uint32_t)(chunk & 1) * STG3 * 2;
#pragma unroll
        for (int kk = 0; kk < 4; kk++) {
            uint32_t bF[2][4];
#pragma unroll
            for (int nt2 = 0; nt2 < 2; nt2++) {
                uint32_t bo = (uint32_t)(2 * A3_ELEMS + (wn + nt2 * 16 + brow) * SP3 +
                                         kk * 16 + bcol) * 2;
                ldsm_x4(stage + bo, bF[nt2]);
            }
#pragma unroll
            for (int mt = 0; mt < 4; mt++) {
                uint32_t aH[4], aL[4];
                uint32_t ao = (uint32_t)((wm + mt * 16 + arow) * SP3 + kk * 16 + acol) * 2;
                ldsm_x4(stage + ao, aH);
                ldsm_x4(stage + A3_ELEMS * 2 + ao, aL);
#pragma unroll
                for (int nt = 0; nt < 4; nt++) {
                    uint32_t b0 = bF[nt >> 1][(nt & 1) * 2];
                    uint32_t b1 = bF[nt >> 1][(nt & 1) * 2 + 1];
                    mma16816(acc[mt][nt], aH, b0, b1);
                    mma16816(acc[mt][nt], aL, b0, b1);
                }
            }
        }
    }

    __syncthreads();
    const int erow = lane >> 2;
    const int ecol = (lane & 3) * 2;
#pragma unroll
    for (int mt = 0; mt < 4; mt++) {
#pragma unroll
        for (int nt = 0; nt < 4; nt++) {
            int r = m0 + wm + mt * 16 + erow;
            int c = n0 + wn + nt * 8 + ecol;
            *(float2*)&C[(size_t)r * Ntot + c] =
                make_float2(acc[mt][nt][0], acc[mt][nt][1]);
            *(float2*)&C[(size_t)(r + 8) * Ntot + c] =
                make_float2(acc[mt][nt][2], acc[mt][nt][3]);
        }
    }
}

// ---------------------------------------------------------------------------
// f32 -> fp16 hi/lo split
// ---------------------------------------------------------------------------
__global__ void split_kernel(const float* __restrict__ x,
                             __half* __restrict__ hi,
                             __half* __restrict__ lo, int n) {
    int i = blockIdx.x * 256 + threadIdx.x;
    if (i >= n) return;
    __half h, l;
    split16(x[i], h, l);
    hi[i] = h; lo[i] = l;
}

// ---------------------------------------------------------------------------
// All 4 weight transposes fused: W [4096][N] f32 -> W^T single fp16 [N][4096]
// ---------------------------------------------------------------------------
__global__ __launch_bounds__(256) void transpose_all(
    const float* __restrict__ Wq, const float* __restrict__ Wk,
    const float* __restrict__ Wv, const float* __restrict__ Wo,
    __half* __restrict__ oq, __half* __restrict__ ok,
    __half* __restrict__ ov, __half* __restrict__ oo) {
    const float* W; __half* dst; int N;
    switch (blockIdx.z) {
        case 0: W = Wq; dst = oq; N = HIDDEN; break;
        case 1: W = Wk; dst = ok; N = NKV * HDIM; break;
        case 2: W = Wv; dst = ov; N = NKV * HDIM; break;
        default: W = Wo; dst = oo; N = HIDDEN; break;
    }
    const int n0 = blockIdx.x * 32;
    if (n0 >= N) return;
    const int k0 = blockIdx.y * 32;
    __shared__ float t[32][33];
    const int tx = threadIdx.x;
    for (int r = threadIdx.y; r < 32; r += 8)
        t[r][tx] = W[(size_t)(k0 + r) * N + n0 + tx];
    __syncthreads();
    for (int r = threadIdx.y; r < 32; r += 8)
        dst[(size_t)(n0 + r) * HIDDEN + k0 + tx] = __float2half(t[tx][r]);
}

// ---------------------------------------------------------------------------
// RMSNorm + RoPE for Q (pre-scaled fp16 hi/lo splits)
// ---------------------------------------------------------------------------
__global__ __launch_bounds__(128) void norm_rope_q(
    const float* __restrict__ inp, const float* __restrict__ w,
    __half* __restrict__ qhi, __half* __restrict__ qlo) {
    const int s = blockIdx.x;
    const int h = blockIdx.y;
    const int d = threadIdx.x;

    float x = inp[((size_t)s * NHEADS + h) * HDIM + d];
    float ss = x * x;
#pragma unroll
    for (int o = 16; o; o >>= 1) ss += __shfl_xor_sync(0xffffffffu, ss, o);
    __shared__ float wss[4];
    __shared__ float xs[HDIM];
    if ((d & 31) == 0) wss[d >> 5] = ss;
    __syncthreads();
    float var = (wss[0] + wss[1] + wss[2] + wss[3]) * (1.0f / 128.0f);
    xs[d] = x * rsqrtf(var + 1e-6f) * w[d];
    __syncthreads();

    if (d < 64) {
        const float scale = 0.08838834764831845f;
        float p = (float)s;
        float e = (float)(2 * d) * (1.0f / 128.0f);
        float invf = powf(1000000.0f, -e);
        float si, c;
        sincosf(p * invf, &si, &c);
        float x1 = xs[d], x2 = xs[d + 64];
        float r1 = (x1 * c - x2 * si) * scale;
        float r2 = (x2 * c + x1 * si) * scale;
        size_t base = ((size_t)h * S_LEN + s) * HDIM;
        __half h1, l1, h2, l2;
        split16(r1, h1, l1);
        split16(r2, h2, l2);
        qhi[base + d] = h1; qhi[base + d + 64] = h2;
        qlo[base + d] = l1; qlo[base + d + 64] = l2;
    }
}

// ---------------------------------------------------------------------------
// RMSNorm + RoPE for K: f32 new_k [kv][s][d] + single fp16
// ---------------------------------------------------------------------------
__global__ __launch_bounds__(128) void norm_rope_k(
    const float* __restrict__ inp, const float* __restrict__ w,
    float* __restrict__ outf, __half* __restrict__ kh) {
    const int s = blockIdx.x;
    const int h = blockIdx.y;
    const int d = threadIdx.x;

    float x = inp[((size_t)s * NKV + h) * HDIM + d];
    float ss = x * x;
#pragma unroll
    for (int o = 16; o; o >>= 1) ss += __shfl_xor_sync(0xffffffffu, ss, o);
    __shared__ float wss[4];
    __shared__ float xs[HDIM];
    if ((d & 31) == 0) wss[d >> 5] = ss;
    __syncthreads();
    float var = (wss[0] + wss[1] + wss[2] + wss[3]) * (1.0f / 128.0f);
    xs[d] = x * rsqrtf(var + 1e-6f) * w[d];
    __syncthreads();

    if (d < 64) {
        float p = (float)s;
        float e = (float)(2 * d) * (1.0f / 128.0f);
        float invf = powf(1000000.0f, -e);
        float si, c;
        sincosf(p * invf, &si, &c);
        float x1 = xs[d], x2 = xs[d + 64];
        float r1 = x1 * c - x2 * si;
        float r2 = x2 * c + x1 * si;
        size_t base = ((size_t)h * S_LEN + s) * HDIM;
        outf[base + d]      = r1;
        outf[base + d + 64] = r2;
        kh[base + d]      = __float2half(r1);
        kh[base + d + 64] = __float2half(r2);
    }
}

// ---------------------------------------------------------------------------
// V: [s][kv*128+d] -> new_v f32 [kv][s][d] + V^T single fp16 [kv][d][s]
// ---------------------------------------------------------------------------
__global__ __launch_bounds__(256) void v_split_transpose(
    const float* __restrict__ vt, float* __restrict__ outf,
    __half* __restrict__ vth) {
    __shared__ float t[32][33];
    const int kv = blockIdx.z;
    const int s0 = blockIdx.x * 32;
    const int d0 = blockIdx.y * 32;
    const int tx = threadIdx.x;
    for (int r = threadIdx.y; r < 32; r += 8) {
        float v = vt[(size_t)(s0 + r) * (NKV * HDIM) + kv * HDIM + d0 + tx];
        t[r][tx] = v;
        outf[((size_t)kv * S_LEN + s0 + r) * HDIM + d0 + tx] = v;
    }
    __syncthreads();
    for (int r = threadIdx.y; r < 32; r += 8)
        vth[((size_t)kv * HDIM + d0 + r) * S_LEN + s0 + tx] = __float2half(t[tx][r]);
}

// ---------------------------------------------------------------------------
// Tensor-core attention v4 (fp16):
//  Pass 1: QK^T = (Qh+Ql)·K (2-term), raw masked scores -> probs, stats.
//  Pass 2: stream scores back, exp/normalize, rewrite probs, PV = (Ph+Pl)·V.
// ---------------------------------------------------------------------------
#define AT_QP 136
#define AT_VP 72
#define S_PITCH_F 72
#define SQHI 0
#define SQLO (128 * AT_QP)                     // 17408
#define SSST (2 * 128 * AT_QP)                 // 34816
#define KSTAGE_UNITS (64 * AT_QP)              // 8704 (single K per stage)
#define SSTAGE_UNITS (128 * S_PITCH_F * 2)     // 18432 (f32 scores per stage)
#define SVH  (SSST + 2 * SSTAGE_UNITS)         // 71680 (s stages > K stages)
#define SPHI (SVH + 128 * AT_VP)               // 80896
#define SPLO (SPHI + 128 * AT_VP)              // 90112
#define AT_SMEM_ELEMS (SPLO + 128 * AT_VP)     // 99328
#define AT_SMEM_BYTES (AT_SMEM_ELEMS * 2)      // 198656

__global__ __launch_bounds__(256) void attention_mma(
    const __half* __restrict__ qhi, const __half* __restrict__ qlo,
    const __half* __restrict__ kh, const __half* __restrict__ vth,
    float* __restrict__ probs,
    __half* __restrict__ ahi, __half* __restrict__ alo) {
    extern __shared__ __align__(16) __half smbuf[];
    const uint32_t sb = smem_to_u32(smbuf);
    const int h   = blockIdx.y;
    const int kvh = h >> 2;
    const int q0  = (int)(gridDim.x - 1 - blockIdx.x) * 128;
    const int tid = threadIdx.x;
    const int lane = tid & 31;
    const int wid  = tid >> 5;
    const int quad = lane >> 3, wi = lane & 7;
    const int wm   = wid * 16;
    const int arow = (quad & 1) * 8 + wi, acol = (quad >> 1) * 8;
    const int brow = (quad >> 1) * 8 + wi, bcol = (quad & 1) * 8;
    const int erow = lane >> 2, fc = (lane & 3) * 2;
    const int grow0 = q0 + wm + erow;
    const int grow1 = grow0 + 8;

    auto issue_K = [&](int jt, int buf) {
        const int c0 = jt * 64;
        const uint32_t kbase = SSST + (uint32_t)buf * KSTAGE_UNITS;
#pragma unroll
        for (int i = 0; i < 4; i++) {
            int idx = tid + i * 256;
            int row = idx >> 4, ch = idx & 15;
            size_t go = ((size_t)kvh * S_LEN + c0 + row) * HDIM + ch * 8;
            cpasync16(sb + (uint32_t)(kbase + row * AT_QP + ch * 8) * 2, kh + go);
        }
    };
    auto issue_V = [&](int jt) {
        const int c0 = jt * 64;
#pragma unroll
        for (int i = 0; i < 4; i++) {
            int idx = tid + i * 256;
            int row = idx >> 3, ch = idx & 7;
            size_t go = ((size_t)kvh * HDIM + row) * S_LEN + c0 + ch * 8;
            cpasync16(sb + (uint32_t)(SVH + row * AT_VP + ch * 8) * 2, vth + go);
        }
    };
    auto issue_S = [&](int jt, int buf) {
        const int c0 = jt * 64;
        const uint32_t sbase = (uint32_t)((SSST + buf * SSTAGE_UNITS) * 2);
#pragma unroll
        for (int i = 0; i < 8; i++) {
            int idx = tid + i * 256;
            int row = idx >> 4, ch = idx & 15;
            const float* g = &probs[((size_t)h * S_LEN + q0 + row) * S_LEN + c0 + ch * 4];
            cpasync16(sb + sbase + (uint32_t)(row * S_PITCH_F + ch * 4) * 4, g);
        }
    };
    auto compute_S = [&](int buf, float s[8][4]) {
        const uint32_t kbase = SSST + (uint32_t)buf * KSTAGE_UNITS;
#pragma unroll
        for (int nt = 0; nt < 8; nt++)
#pragma unroll
            for (int q = 0; q < 4; q++) s[nt][q] = 0.f;
#pragma unroll
        for (int term = 0; term < 2; term++) {
            const uint32_t qb = (term == 1) ? SQLO : SQHI;
#pragma unroll
            for (int kk = 0; kk < 8; kk++) {
                uint32_t a[4], b[4][4];
                ldsm_x4(sb + (uint32_t)(qb + (wm + arow) * AT_QP + kk * 16 + acol) * 2, a);
#pragma unroll
                for (int nt2 = 0; nt2 < 4; nt2++)
                    ldsm_x4(sb + (uint32_t)(kbase + (nt2 * 16 + brow) * AT_QP + kk * 16 + bcol) * 2, b[nt2]);
#pragma unroll
                for (int nt = 0; nt < 8; nt++)
                    mma16816(s[nt], a, b[nt >> 1][(nt & 1) * 2], b[nt >> 1][(nt & 1) * 2 + 1]);
            }
        }
    };

    const int jmax = (q0 + 127) >> 6;
    float m0 = -1e30f, m1 = -1e30f, l0 = 0.f, l1 = 0.f;

    // ---- prologue pass 1: Q hi/lo + K(0) ----
#pragma unroll
    for (int i = 0; i < 8; i++) {
        int idx = tid + i * 256;
        int row = idx >> 4, ch = idx & 15;
        size_t go = ((size_t)h * S_LEN + q0 + row) * HDIM + ch * 8;
        cpasync16(sb + (uint32_t)(SQHI + row * AT_QP + ch * 8) * 2, qhi + go);
        cpasync16(sb + (uint32_t)(SQLO + row * AT_QP + ch * 8) * 2, qlo + go);
    }
    issue_K(0, 0);
    CP_COMMIT();

    // ================= PASS 1 =================
    for (int jt = 0; jt <= jmax; jt++) {
        if (jt < jmax) {
            issue_K(jt + 1, (jt + 1) & 1);
            CP_COMMIT();
            CP_WAIT(1);
        } else {
            CP_WAIT(0);
        }
        __syncthreads();

        float s[8][4];
        compute_S(jt & 1, s);

        const int c0 = jt * 64;
        float tm0 = -1e30f, tm1 = -1e30f;
#pragma unroll
        for (int nt = 0; nt < 8; nt++) {
            int cb = c0 + nt * 8 + fc;
            if (cb     > grow0) s[nt][0] = -1e30f;
            if (cb + 1 > grow0) s[nt][1] = -1e30f;
            if (cb     > grow1) s[nt][2] = -1e30f;
            if (cb + 1 > grow1) s[nt][3] = -1e30f;
            *(float2*)&probs[((size_t)h * S_LEN + grow0) * S_LEN + cb] =
                make_float2(s[nt][0], s[nt][1]);
            *(float2*)&probs[((size_t)h * S_LEN + grow1) * S_LEN + cb] =
                make_float2(s[nt][2], s[nt][3]);
            tm0 = fmaxf(tm0, fmaxf(s[nt][0], s[nt][1]));
            tm1 = fmaxf(tm1, fmaxf(s[nt][2], s[nt][3]));
        }
        tm0 = fmaxf(tm0, __shfl_xor_sync(0xffffffffu, tm0, 1));
        tm0 = fmaxf(tm0, __shfl_xor_sync(0xffffffffu, tm0, 2));
        tm1 = fmaxf(tm1, __shfl_xor_sync(0xffffffffu, tm1, 1));
        tm1 = fmaxf(tm1, __shfl_xor_sync(0xffffffffu, tm1, 2));
        float mn0 = fmaxf(m0, tm0), mn1 = fmaxf(m1, tm1);
        float su0 = 0.f, su1 = 0.f;
#pragma unroll
        for (int nt = 0; nt < 8; nt++) {
            su0 += __expf(s[nt][0] - mn0) + __expf(s[nt][1] - mn0);
            su1 += __expf(s[nt][2] - mn1) + __expf(s[nt][3] - mn1);
        }
        su0 += __shfl_xor_sync(0xffffffffu, su0, 1);
        su0 += __shfl_xor_sync(0xffffffffu, su0, 2);
        su1 += __shfl_xor_sync(0xffffffffu, su1, 1);
        su1 += __shfl_xor_sync(0xffffffffu, su1, 2);
        l0 = l0 * __expf(m0 - mn0) + su0; m0 = mn0;
        l1 = l1 * __expf(m1 - mn1) + su1; m1 = mn1;
        __syncthreads();
    }
    const float li0 = 1.0f / l0, li1 = 1.0f / l1;

    // ---- zero-fill masked probs tiles ----
    {
        float2 z = make_float2(0.f, 0.f);
        for (int jt = jmax + 1; jt < S_LEN / 64; jt++) {
            const int c0 = jt * 64;
#pragma unroll
            for (int nt = 0; nt < 8; nt++) {
                int col = c0 + nt * 8 + fc;
                *(float2*)&probs[((size_t)h * S_LEN + grow0) * S_LEN + col] = z;
                *(float2*)&probs[((size_t)h * S_LEN + grow1) * S_LEN + col] = z;
            }
        }
    }

    float o[16][4];
#pragma unroll
    for (int nt = 0; nt < 16; nt++)
#pragma unroll
        for (int q = 0; q < 4; q++) o[nt][q] = 0.f;

    issue_S(0, 0);
    CP_COMMIT();
    issue_V(0);
    CP_COMMIT();

    // ================= PASS 2 =================
    for (int jt = 0; jt <= jmax; jt++) {
        if (jt < jmax) {
            issue_S(jt + 1, (jt + 1) & 1);
            CP_COMMIT();
            CP_WAIT(2);
        } else {
            CP_WAIT(1);
        }
        __syncthreads();

        const float* sf = (const float*)&smbuf[SSST + (jt & 1) * SSTAGE_UNITS];
        const int c0 = jt * 64;
        const int pr0 = wm + erow, pr1 = pr0 + 8;
#pragma unroll
        for (int nt = 0; nt < 8; nt++) {
            int cl = nt * 8 + fc;
            float2 s01 = *(const float2*)&sf[pr0 * S_PITCH_F + cl];
            float2 s23 = *(const float2*)&sf[pr1 * S_PITCH_F + cl];
            float p0 = __expf(s01.x - m0) * li0;
            float p1 = __expf(s01.y - m0) * li0;
            float p2 = __expf(s23.x - m1) * li1;
            float p3 = __expf(s23.y - m1) * li1;
            int cb = c0 + cl;
            *(float2*)&probs[((size_t)h * S_LEN + grow0) * S_LEN + cb] = make_float2(p0, p1);
            *(float2*)&probs[((size_t)h * S_LEN + grow1) * S_LEN + cb] = make_float2(p2, p3);
            __half h0, l0h, h1, l1h, h2, l2h, h3, l3h;
            split16(p0, h0, l0h); split16(p1, h1, l1h);
            split16(p2, h2, l2h); split16(p3, h3, l3h);
            __half2 hp01; hp01.x = h0;  hp01.y = h1;
            __half2 hp23; hp23.x = h2;  hp23.y = h3;
            __half2 lp01; lp01.x = l0h; lp01.y = l1h;
            __half2 lp23; lp23.x = l2h; lp23.y = l3h;
            *(__half2*)&smbuf[SPHI + pr0 * AT_VP + cl] = hp01;
            *(__half2*)&smbuf[SPHI + pr1 * AT_VP + cl] = hp23;
            *(__half2*)&smbuf[SPLO + pr0 * AT_VP + cl] = lp01;
            *(__half2*)&smbuf[SPLO + pr1 * AT_VP + cl] = lp23;
        }
        __syncwarp();

        if (jt < jmax) CP_WAIT(1); else CP_WAIT(0);
        __syncthreads();

        // P @ V (2-term: Ph·V + Pl·V)
#pragma unroll
        for (int term = 0; term < 2; term++) {
            const int pb = (term == 1) ? SPLO : SPHI;
#pragma unroll
            for (int kk = 0; kk < 4; kk++) {
                uint32_t a[4], b[8][4];
                ldsm_x4(sb + (uint32_t)(pb + (wm + arow) * AT_VP + kk * 16 + acol) * 2, a);
#pragma unroll
                for (int nt2 = 0; nt2 < 8; nt2++)
                    ldsm_x4(sb + (uint32_t)(SVH + (nt2 * 16 + brow) * AT_VP + kk * 16 + bcol) * 2, b[nt2]);
#pragma unroll
                for (int nt = 0; nt < 16; nt++)
                    mma16816(o[nt], a, b[nt >> 1][(nt & 1) * 2], b[nt >> 1][(nt & 1) * 2 + 1]);
            }
        }
        __syncthreads();

        if (jt < jmax) {
            issue_V(jt + 1);
            CP_COMMIT();
        }
    }

    // ---- epilogue: split O to fp16 hi/lo in [s][h*128+d] layout ----
#pragma unroll
    for (int nt = 0; nt < 16; nt++) {
        int d = nt * 8 + fc;
        size_t b0 = (size_t)grow0 * HIDDEN + h * HDIM + d;
        size_t b1 = (size_t)grow1 * HIDDEN + h * HDIM + d;
        __half h0, l0h, h1, l1h, h2, l2h, h3, l3h;
        split16(o[nt][0], h0, l0h); split16(o[nt][1], h1, l1h);
        split16(o[nt][2], h2, l2h); split16(o[nt][3], h3, l3h);
        __half2 hp01; hp01.x = h0;  hp01.y = h1;
        __half2 hp23; hp23.x = h2;  hp23.y = h3;
        __half2 lp01; lp01.x = l0h; lp01.y = l1h;
        __half2 lp23; lp23.x = l2h; lp23.y = l3h;
        *(__half2*)&ahi[b0] = hp01;
        *(__half2*)&ahi[b1] = hp23;
        *(__half2*)&alo[b0] = lp01;
        *(__half2*)&alo[b1] = lp23;
    }
}

// ---------------------------------------------------------------------------
// Launch
// ---------------------------------------------------------------------------
extern "C" void kernel_launch(void* const* d_in, const int* in_sizes, int n_in,
                              void* d_out, int out_size) {
    const float* X  = (const float*)d_in[0];
    const float* Wq = (const float*)d_in[2];
    const float* Wk = (const float*)d_in[3];
    const float* Wv = (const float*)d_in[4];
    const float* Wo = (const float*)d_in[5];
    const float* qw = (const float*)d_in[6];
    const float* kw = (const float*)d_in[7];

    float* out   = (float*)d_out;
    float* new_k = out + (size_t)S_LEN * HIDDEN;
    float* new_v = new_k + (size_t)NKV * S_LEN * HDIM;
    float* probs = new_v + (size_t)NKV * S_LEN * HDIM;

    float *qtmp, *ktmp, *vtmp;
    __half *xhi, *xlo, *ahi, *alo, *qhi, *qlo, *khs, *vth;
    __half *wq, *wk, *wv, *wo;
    cudaGetSymbolAddress((void**)&qtmp, g_qtmp);
    cudaGetSymbolAddress((void**)&ktmp, g_ktmp);
    cudaGetSymbolAddress((void**)&vtmp, g_vtmp);
    cudaGetSymbolAddress((void**)&xhi, g_xhi);
    cudaGetSymbolAddress((void**)&xlo, g_xlo);
    cudaGetSymbolAddress((void**)&ahi, g_ahi);
    cudaGetSymbolAddress((void**)&alo, g_alo);
    cudaGetSymbolAddress((void**)&qhi, g_qhi);
    cudaGetSymbolAddress((void**)&qlo, g_qlo);
    cudaGetSymbolAddress((void**)&khs, g_kh);
    cudaGetSymbolAddress((void**)&vth, g_vth);
    cudaGetSymbolAddress((void**)&wq, g_wqt);
    cudaGetSymbolAddress((void**)&wk, g_wkt);
    cudaGetSymbolAddress((void**)&wv, g_wvt);
    cudaGetSymbolAddress((void**)&wo, g_wot);

    // ---- conversions ----
    transpose_all<<<dim3(128, 128, 4), dim3(32, 8)>>>(
        Wq, Wk, Wv, Wo, wq, wk, wv, wo);
    {
        int n = S_LEN * HIDDEN;
        split_kernel<<<(n + 255) / 256, 256>>>(X, xhi, xlo, n);
    }

    // ---- Q+K+V fused: 256 + 64 + 64 = 384 CTAs ----
    cudaFuncSetAttribute(gemm_mma3, cudaFuncAttributeMaxDynamicSharedMemorySize,
                         GEMM3_SMEM);
    gemm_mma3<<<384, 512, GEMM3_SMEM>>>(
        xhi, xlo,
        wq, qtmp, HIDDEN,
        wk, ktmp, NKV * HDIM,
        wv, vtmp, NKV * HDIM,
        256, 320);

    // ---- RMSNorm + RoPE + splits ----
    norm_rope_q<<<dim3(S_LEN, NHEADS), 128>>>(qtmp, qw, qhi, qlo);
    norm_rope_k<<<dim3(S_LEN, NKV), 128>>>(ktmp, kw, new_k, khs);

    // ---- V transpose + fp16 ----
    v_split_transpose<<<dim3(S_LEN / 32, HDIM / 32, NKV), dim3(32, 8)>>>(
        vtmp, new_v, vth);

    // ---- attention ----
    cudaFuncSetAttribute(attention_mma,
                         cudaFuncAttributeMaxDynamicSharedMemorySize, AT_SMEM_BYTES);
    attention_mma<<<dim3(S_LEN / 128, NHEADS), 256, AT_SMEM_BYTES>>>(
        qhi, qlo, khs, vth, probs, ahi, alo);

    // ---- O projection ----
    gemm_mma3<<<256, 512, GEMM3_SMEM>>>(
        ahi, alo,
        wo, out, HIDDEN,
        wo, out, HIDDEN,
        wo, out, HIDDEN,
        256, 256);
}

// round 12
// speedup vs baseline: 4.4632x; 1.0365x over previous
#include <cuda_runtime.h>
#include <cuda_fp16.h>
#include <math.h>
#include <stdint.h>

// ---------------------------------------------------------------------------
// Problem constants
// ---------------------------------------------------------------------------
#define S_LEN   2048
#define HIDDEN  4096
#define NHEADS  32
#define NKV     8
#define HDIM    128

// ---------------------------------------------------------------------------
// Device scratch
// ---------------------------------------------------------------------------
__device__ float g_qtmp[S_LEN * NHEADS * HDIM];
__device__ float g_ktmp[S_LEN * NKV * HDIM];
__device__ float g_vtmp[S_LEN * NKV * HDIM];

__device__ __half g_xhi[S_LEN * HIDDEN];
__device__ __half g_xlo[S_LEN * HIDDEN];
__device__ __half g_ahi[S_LEN * HIDDEN];
__device__ __half g_alo[S_LEN * HIDDEN];
__device__ __half g_qhi[NHEADS * S_LEN * HDIM];
__device__ __half g_qlo[NHEADS * S_LEN * HDIM];
__device__ __half g_kh[NKV * S_LEN * HDIM];
__device__ __half g_vth[NKV * HDIM * S_LEN];
__device__ __half g_wqt[HIDDEN * HIDDEN];
__device__ __half g_wkt[(NKV * HDIM) * HIDDEN];
__device__ __half g_wvt[(NKV * HDIM) * HIDDEN];
__device__ __half g_wot[HIDDEN * HIDDEN];

// ---------------------------------------------------------------------------
// Low-level helpers
// ---------------------------------------------------------------------------
__device__ __forceinline__ uint32_t smem_to_u32(const void* p) {
    uint32_t a;
    asm("{ .reg .u64 t; cvta.to.shared.u64 t, %1; cvt.u32.u64 %0, t; }"
        : "=r"(a) : "l"(p));
    return a;
}
__device__ __forceinline__ void cpasync16(uint32_t saddr, const void* g) {
    asm volatile("cp.async.cg.shared.global [%0], [%1], 16;"
                 :: "r"(saddr), "l"(g));
}
#define CP_COMMIT() asm volatile("cp.async.commit_group;" ::: "memory")
#define CP_WAIT(n)  asm volatile("cp.async.wait_group %0;" :: "n"(n) : "memory")

__device__ __forceinline__ void ldsm_x4(uint32_t addr, uint32_t r[4]) {
    asm volatile("ldmatrix.sync.aligned.m8n8.x4.shared.b16 {%0,%1,%2,%3}, [%4];"
        : "=r"(r[0]), "=r"(r[1]), "=r"(r[2]), "=r"(r[3]) : "r"(addr));
}
__device__ __forceinline__ void mma16816(float d[4], const uint32_t a[4],
                                         const uint32_t b0, const uint32_t b1) {
    asm volatile(
        "mma.sync.aligned.m16n8k16.row.col.f32.f16.f16.f32 "
        "{%0,%1,%2,%3}, {%4,%5,%6,%7}, {%8,%9}, {%0,%1,%2,%3};"
        : "+f"(d[0]), "+f"(d[1]), "+f"(d[2]), "+f"(d[3])
        : "r"(a[0]), "r"(a[1]), "r"(a[2]), "r"(a[3]), "r"(b0), "r"(b1));
}
__device__ __forceinline__ void split16(float v, __half& hi, __half& lo) {
    hi = __float2half(v);
    lo = __float2half(v - __half2float(hi));
}
__device__ __forceinline__ uint32_t packh2(__half a, __half b) {
    __half2 h; h.x = a; h.y = b;
    return *(uint32_t*)&h;
}

// ---------------------------------------------------------------------------
// Projection GEMM v7: 256x128 tile, BK=64, 512 threads, warp grid 8m x 2n
// (warp tile 32x64), A split fp16 x B single fp16 (2-term MMA).
// Flat segmented grid (Q|K|V fused).
// ---------------------------------------------------------------------------
#define SP3       72
#define A3_ELEMS  (256 * SP3)
#define B3_ELEMS  (128 * SP3)
#define STG3      (2 * A3_ELEMS + B3_ELEMS)
#define GEMM3_SMEM (2 * STG3 * 2)
#define NCH3      (HIDDEN / 64)

__global__ __launch_bounds__(512) void gemm_mma3(
    const __half* __restrict__ Ahi, const __half* __restrict__ Alo,
    const __half* __restrict__ B0, float* __restrict__ C0, int N0,
    const __half* __restrict__ B1, float* __restrict__ C1, int N1,
    const __half* __restrict__ B2, float* __restrict__ C2, int N2,
    int seg1, int seg2) {
    extern __shared__ __align__(16) __half smbuf[];
    const int flat = blockIdx.x;
    const __half* B;
    float* C;
    int Ntot, local;
    if (flat < seg1)      { B = B0; C = C0; Ntot = N0; local = flat; }
    else if (flat < seg2) { B = B1; C = C1; Ntot = N1; local = flat - seg1; }
    else                  { B = B2; C = C2; Ntot = N2; local = flat - seg2; }

    const int nx_eff = Ntot >> 7;
    const int per = 4 * nx_eff;
    const int grp = local / per, rem = local % per;
    const int m0 = (grp * 4 + (rem & 3)) * 256;
    const int n0 = (rem >> 2) * 128;

    const uint32_t sb = smem_to_u32(smbuf);
    const int tid  = threadIdx.x;
    const int lane = tid & 31;
    const int wid  = tid >> 5;
    const int wm = (wid >> 1) * 32;      // 8 m-groups of 32 rows
    const int wn = (wid & 1) * 64;       // 2 n-groups of 64 cols
    const int quad = lane >> 3;
    const int wi   = lane & 7;
    const int arow = (quad & 1) * 8 + wi;
    const int acol = (quad >> 1) * 8;
    const int brow = (quad >> 1) * 8 + wi;
    const int bcol = (quad & 1) * 8;

    float acc[2][8][4];
#pragma unroll
    for (int mt = 0; mt < 2; mt++)
#pragma unroll
        for (int nt = 0; nt < 8; nt++)
#pragma unroll
            for (int q = 0; q < 4; q++) acc[mt][nt][q] = 0.f;

    auto load_stage = [&](int buf, int chunk) {
        const int k0 = chunk * 64;
        const uint32_t sbase = sb + (uint32_t)buf * STG3 * 2;
#pragma unroll
        for (int t = 0; t < 4; t++) {
            int c = tid + t * 512;
            int row = c >> 3;
            int kc  = (c & 7) * 8;
            uint32_t so = sbase + (uint32_t)(row * SP3 + kc) * 2;
            size_t goA = (size_t)(m0 + row) * HIDDEN + k0 + kc;
            cpasync16(so,                Ahi + goA);
            cpasync16(so + A3_ELEMS * 2, Alo + goA);
        }
#pragma unroll
        for (int t = 0; t < 2; t++) {
            int c = tid + t * 512;
            int row = c >> 3;
            int kc  = (c & 7) * 8;
            uint32_t so = sbase + (uint32_t)(2 * A3_ELEMS + row * SP3 + kc) * 2;
            size_t goB = (size_t)(n0 + row) * HIDDEN + k0 + kc;
            cpasync16(so, B + goB);
        }
    };

    load_stage(0, 0);
    CP_COMMIT();

    for (int chunk = 0; chunk < NCH3; chunk++) {
        CP_WAIT(0);
        __syncthreads();
        if (chunk + 1 < NCH3) {
            load_stage((chunk + 1) & 1, chunk + 1);
            CP_COMMIT();
        }
        const uint32_t stage = sb + (uint32_t)(chunk & 1) * STG3 * 2;
#pragma unroll
        for (int kk = 0; kk < 4; kk++) {
            uint32_t bF[4][4];
#pragma unroll
            for (int nt2 = 0; nt2 < 4; nt2++) {
                uint32_t bo = (uint32_t)(2 * A3_ELEMS + (wn + nt2 * 16 + brow) * SP3 +
                                         kk * 16 + bcol) * 2;
                ldsm_x4(stage + bo, bF[nt2]);
            }
#pragma unroll
            for (int mt = 0; mt < 2; mt++) {
                uint32_t aH[4], aL[4];
                uint32_t ao = (uint32_t)((wm + mt * 16 + arow) * SP3 + kk * 16 + acol) * 2;
                ldsm_x4(stage + ao, aH);
                ldsm_x4(stage + A3_ELEMS * 2 + ao, aL);
#pragma unroll
                for (int nt = 0; nt < 8; nt++) {
                    uint32_t b0 = bF[nt >> 1][(nt & 1) * 2];
                    uint32_t b1 = bF[nt >> 1][(nt & 1) * 2 + 1];
                    mma16816(acc[mt][nt], aH, b0, b1);
                    mma16816(acc[mt][nt], aL, b0, b1);
                }
            }
        }
    }

    __syncthreads();
    const int erow = lane >> 2;
    const int ecol = (lane & 3) * 2;
#pragma unroll
    for (int mt = 0; mt < 2; mt++) {
#pragma unroll
        for (int nt = 0; nt < 8; nt++) {
            int r = m0 + wm + mt * 16 + erow;
            int c = n0 + wn + nt * 8 + ecol;
            *(float2*)&C[(size_t)r * Ntot + c] =
                make_float2(acc[mt][nt][0], acc[mt][nt][1]);
            *(float2*)&C[(size_t)(r + 8) * Ntot + c] =
                make_float2(acc[mt][nt][2], acc[mt][nt][3]);
        }
    }
}

// ---------------------------------------------------------------------------
// f32 -> fp16 hi/lo split
// ---------------------------------------------------------------------------
__global__ void split_kernel(const float* __restrict__ x,
                             __half* __restrict__ hi,
                             __half* __restrict__ lo, int n) {
    int i = blockIdx.x * 256 + threadIdx.x;
    if (i >= n) return;
    __half h, l;
    split16(x[i], h, l);
    hi[i] = h; lo[i] = l;
}

// ---------------------------------------------------------------------------
// All 4 weight transposes fused: W [4096][N] f32 -> W^T fp16 [N][4096]
// ---------------------------------------------------------------------------
__global__ __launch_bounds__(256) void transpose_all(
    const float* __restrict__ Wq, const float* __restrict__ Wk,
    const float* __restrict__ Wv, const float* __restrict__ Wo,
    __half* __restrict__ oq, __half* __restrict__ ok,
    __half* __restrict__ ov, __half* __restrict__ oo) {
    const float* W; __half* dst; int N;
    switch (blockIdx.z) {
        case 0: W = Wq; dst = oq; N = HIDDEN; break;
        case 1: W = Wk; dst = ok; N = NKV * HDIM; break;
        case 2: W = Wv; dst = ov; N = NKV * HDIM; break;
        default: W = Wo; dst = oo; N = HIDDEN; break;
    }
    const int n0 = blockIdx.x * 32;
    if (n0 >= N) return;
    const int k0 = blockIdx.y * 32;
    __shared__ float t[32][33];
    const int tx = threadIdx.x;
    for (int r = threadIdx.y; r < 32; r += 8)
        t[r][tx] = W[(size_t)(k0 + r) * N + n0 + tx];
    __syncthreads();
    for (int r = threadIdx.y; r < 32; r += 8)
        dst[(size_t)(n0 + r) * HIDDEN + k0 + tx] = __float2half(t[tx][r]);
}

// ---------------------------------------------------------------------------
// RMSNorm + RoPE for Q (pre-scaled fp16 hi/lo splits)
// ---------------------------------------------------------------------------
__global__ __launch_bounds__(128) void norm_rope_q(
    const float* __restrict__ inp, const float* __restrict__ w,
    __half* __restrict__ qhi, __half* __restrict__ qlo) {
    const int s = blockIdx.x;
    const int h = blockIdx.y;
    const int d = threadIdx.x;

    float x = inp[((size_t)s * NHEADS + h) * HDIM + d];
    float ss = x * x;
#pragma unroll
    for (int o = 16; o; o >>= 1) ss += __shfl_xor_sync(0xffffffffu, ss, o);
    __shared__ float wss[4];
    __shared__ float xs[HDIM];
    if ((d & 31) == 0) wss[d >> 5] = ss;
    __syncthreads();
    float var = (wss[0] + wss[1] + wss[2] + wss[3]) * (1.0f / 128.0f);
    xs[d] = x * rsqrtf(var + 1e-6f) * w[d];
    __syncthreads();

    if (d < 64) {
        const float scale = 0.08838834764831845f;
        float p = (float)s;
        float e = (float)(2 * d) * (1.0f / 128.0f);
        float invf = powf(1000000.0f, -e);
        float si, c;
        sincosf(p * invf, &si, &c);
        float x1 = xs[d], x2 = xs[d + 64];
        float r1 = (x1 * c - x2 * si) * scale;
        float r2 = (x2 * c + x1 * si) * scale;
        size_t base = ((size_t)h * S_LEN + s) * HDIM;
        __half h1, l1, h2, l2;
        split16(r1, h1, l1);
        split16(r2, h2, l2);
        qhi[base + d] = h1; qhi[base + d + 64] = h2;
        qlo[base + d] = l1; qlo[base + d + 64] = l2;
    }
}

// ---------------------------------------------------------------------------
// RMSNorm + RoPE for K: f32 new_k [kv][s][d] + single fp16
// ---------------------------------------------------------------------------
__global__ __launch_bounds__(128) void norm_rope_k(
    const float* __restrict__ inp, const float* __restrict__ w,
    float* __restrict__ outf, __half* __restrict__ kh) {
    const int s = blockIdx.x;
    const int h = blockIdx.y;
    const int d = threadIdx.x;

    float x = inp[((size_t)s * NKV + h) * HDIM + d];
    float ss = x * x;
#pragma unroll
    for (int o = 16; o; o >>= 1) ss += __shfl_xor_sync(0xffffffffu, ss, o);
    __shared__ float wss[4];
    __shared__ float xs[HDIM];
    if ((d & 31) == 0) wss[d >> 5] = ss;
    __syncthreads();
    float var = (wss[0] + wss[1] + wss[2] + wss[3]) * (1.0f / 128.0f);
    xs[d] = x * rsqrtf(var + 1e-6f) * w[d];
    __syncthreads();

    if (d < 64) {
        float p = (float)s;
        float e = (float)(2 * d) * (1.0f / 128.0f);
        float invf = powf(1000000.0f, -e);
        float si, c;
        sincosf(p * invf, &si, &c);
        float x1 = xs[d], x2 = xs[d + 64];
        float r1 = x1 * c - x2 * si;
        float r2 = x2 * c + x1 * si;
        size_t base = ((size_t)h * S_LEN + s) * HDIM;
        outf[base + d]      = r1;
        outf[base + d + 64] = r2;
        kh[base + d]      = __float2half(r1);
        kh[base + d + 64] = __float2half(r2);
    }
}

// ---------------------------------------------------------------------------
// V: [s][kv*128+d] -> new_v f32 [kv][s][d] + V^T fp16 [kv][d][s]
// ---------------------------------------------------------------------------
__global__ __launch_bounds__(256) void v_split_transpose(
    const float* __restrict__ vt, float* __restrict__ outf,
    __half* __restrict__ vth) {
    __shared__ float t[32][33];
    const int kv = blockIdx.z;
    const int s0 = blockIdx.x * 32;
    const int d0 = blockIdx.y * 32;
    const int tx = threadIdx.x;
    for (int r = threadIdx.y; r < 32; r += 8) {
        float v = vt[(size_t)(s0 + r) * (NKV * HDIM) + kv * HDIM + d0 + tx];
        t[r][tx] = v;
        outf[((size_t)kv * S_LEN + s0 + r) * HDIM + d0 + tx] = v;
    }
    __syncthreads();
    for (int r = threadIdx.y; r < 32; r += 8)
        vth[((size_t)kv * HDIM + d0 + r) * S_LEN + s0 + tx] = __float2half(t[tx][r]);
}

// ---------------------------------------------------------------------------
// Tensor-core attention v5 (fp16, P kept in registers as A-fragments):
//  Pass 1: QK^T (2-term), raw masked scores -> probs, online stats.
//  Pass 2: stream scores back, exp/normalize, rewrite probs, pack P hi/lo
//          straight into mma A-fragments (no smem round-trip), PV (2-term).
// ---------------------------------------------------------------------------
#define AT_QP 136
#define AT_VP 72
#define S_PITCH_F 72
#define SQHI 0
#define SQLO (128 * AT_QP)                     // 17408
#define SSST (2 * 128 * AT_QP)                 // 34816
#define KSTAGE_UNITS (64 * AT_QP)              // 8704
#define SSTAGE_UNITS (128 * S_PITCH_F * 2)     // 18432
#define SVH  (SSST + 2 * SSTAGE_UNITS)         // 71680
#define AT_SMEM_ELEMS (SVH + 128 * AT_VP)      // 80896
#define AT_SMEM_BYTES (AT_SMEM_ELEMS * 2)      // 161792

__global__ __launch_bounds__(256) void attention_mma(
    const __half* __restrict__ qhi, const __half* __restrict__ qlo,
    const __half* __restrict__ kh, const __half* __restrict__ vth,
    float* __restrict__ probs,
    __half* __restrict__ ahi, __half* __restrict__ alo) {
    extern __shared__ __align__(16) __half smbuf[];
    const uint32_t sb = smem_to_u32(smbuf);
    const int h   = blockIdx.y;
    const int kvh = h >> 2;
    const int q0  = (int)(gridDim.x - 1 - blockIdx.x) * 128;
    const int tid = threadIdx.x;
    const int lane = tid & 31;
    const int wid  = tid >> 5;
    const int quad = lane >> 3, wi = lane & 7;
    const int wm   = wid * 16;
    const int arow = (quad & 1) * 8 + wi, acol = (quad >> 1) * 8;
    const int brow = (quad >> 1) * 8 + wi, bcol = (quad & 1) * 8;
    const int erow = lane >> 2, fc = (lane & 3) * 2;
    const int grow0 = q0 + wm + erow;
    const int grow1 = grow0 + 8;

    auto issue_K = [&](int jt, int buf) {
        const int c0 = jt * 64;
        const uint32_t kbase = SSST + (uint32_t)buf * KSTAGE_UNITS;
#pragma unroll
        for (int i = 0; i < 4; i++) {
            int idx = tid + i * 256;
            int row = idx >> 4, ch = idx & 15;
            size_t go = ((size_t)kvh * S_LEN + c0 + row) * HDIM + ch * 8;
            cpasync16(sb + (uint32_t)(kbase + row * AT_QP + ch * 8) * 2, kh + go);
        }
    };
    auto issue_V = [&](int jt) {
        const int c0 = jt * 64;
#pragma unroll
        for (int i = 0; i < 4; i++) {
            int idx = tid + i * 256;
            int row = idx >> 3, ch = idx & 7;
            size_t go = ((size_t)kvh * HDIM + row) * S_LEN + c0 + ch * 8;
            cpasync16(sb + (uint32_t)(SVH + row * AT_VP + ch * 8) * 2, vth + go);
        }
    };
    auto issue_S = [&](int jt, int buf) {
        const int c0 = jt * 64;
        const uint32_t sbase = (uint32_t)((SSST + buf * SSTAGE_UNITS) * 2);
#pragma unroll
        for (int i = 0; i < 8; i++) {
            int idx = tid + i * 256;
            int row = idx >> 4, ch = idx & 15;
            const float* g = &probs[((size_t)h * S_LEN + q0 + row) * S_LEN + c0 + ch * 4];
            cpasync16(sb + sbase + (uint32_t)(row * S_PITCH_F + ch * 4) * 4, g);
        }
    };
    auto compute_S = [&](int buf, float s[8][4]) {
        const uint32_t kbase = SSST + (uint32_t)buf * KSTAGE_UNITS;
#pragma unroll
        for (int nt = 0; nt < 8; nt++)
#pragma unroll
            for (int q = 0; q < 4; q++) s[nt][q] = 0.f;
#pragma unroll
        for (int term = 0; term < 2; term++) {
            const uint32_t qb = (term == 1) ? SQLO : SQHI;
#pragma unroll
            for (int kk = 0; kk < 8; kk++) {
                uint32_t a[4], b[4][4];
                ldsm_x4(sb + (uint32_t)(qb + (wm + arow) * AT_QP + kk * 16 + acol) * 2, a);
#pragma unroll
                for (int nt2 = 0; nt2 < 4; nt2++)
                    ldsm_x4(sb + (uint32_t)(kbase + (nt2 * 16 + brow) * AT_QP + kk * 16 + bcol) * 2, b[nt2]);
#pragma unroll
                for (int nt = 0; nt < 8; nt++)
                    mma16816(s[nt], a, b[nt >> 1][(nt & 1) * 2], b[nt >> 1][(nt & 1) * 2 + 1]);
            }
        }
    };

    const int jmax = (q0 + 127) >> 6;
    float m0 = -1e30f, m1 = -1e30f, l0 = 0.f, l1 = 0.f;

    // ---- prologue pass 1: Q hi/lo + K(0) ----
#pragma unroll
    for (int i = 0; i < 8; i++) {
        int idx = tid + i * 256;
        int row = idx >> 4, ch = idx & 15;
        size_t go = ((size_t)h * S_LEN + q0 + row) * HDIM + ch * 8;
        cpasync16(sb + (uint32_t)(SQHI + row * AT_QP + ch * 8) * 2, qhi + go);
        cpasync16(sb + (uint32_t)(SQLO + row * AT_QP + ch * 8) * 2, qlo + go);
    }
    issue_K(0, 0);
    CP_COMMIT();

    // ================= PASS 1 =================
    for (int jt = 0; jt <= jmax; jt++) {
        if (jt < jmax) {
            issue_K(jt + 1, (jt + 1) & 1);
            CP_COMMIT();
            CP_WAIT(1);
        } else {
            CP_WAIT(0);
        }
        __syncthreads();

        float s[8][4];
        compute_S(jt & 1, s);

        const int c0 = jt * 64;
        float tm0 = -1e30f, tm1 = -1e30f;
#pragma unroll
        for (int nt = 0; nt < 8; nt++) {
            int cb = c0 + nt * 8 + fc;
            if (cb     > grow0) s[nt][0] = -1e30f;
            if (cb + 1 > grow0) s[nt][1] = -1e30f;
            if (cb     > grow1) s[nt][2] = -1e30f;
            if (cb + 1 > grow1) s[nt][3] = -1e30f;
            *(float2*)&probs[((size_t)h * S_LEN + grow0) * S_LEN + cb] =
                make_float2(s[nt][0], s[nt][1]);
            *(float2*)&probs[((size_t)h * S_LEN + grow1) * S_LEN + cb] =
                make_float2(s[nt][2], s[nt][3]);
            tm0 = fmaxf(tm0, fmaxf(s[nt][0], s[nt][1]));
            tm1 = fmaxf(tm1, fmaxf(s[nt][2], s[nt][3]));
        }
        tm0 = fmaxf(tm0, __shfl_xor_sync(0xffffffffu, tm0, 1));
        tm0 = fmaxf(tm0, __shfl_xor_sync(0xffffffffu, tm0, 2));
        tm1 = fmaxf(tm1, __shfl_xor_sync(0xffffffffu, tm1, 1));
        tm1 = fmaxf(tm1, __shfl_xor_sync(0xffffffffu, tm1, 2));
        float mn0 = fmaxf(m0, tm0), mn1 = fmaxf(m1, tm1);
        float su0 = 0.f, su1 = 0.f;
#pragma unroll
        for (int nt = 0; nt < 8; nt++) {
            su0 += __expf(s[nt][0] - mn0) + __expf(s[nt][1] - mn0);
            su1 += __expf(s[nt][2] - mn1) + __expf(s[nt][3] - mn1);
        }
        su0 += __shfl_xor_sync(0xffffffffu, su0, 1);
        su0 += __shfl_xor_sync(0xffffffffu, su0, 2);
        su1 += __shfl_xor_sync(0xffffffffu, su1, 1);
        su1 += __shfl_xor_sync(0xffffffffu, su1, 2);
        l0 = l0 * __expf(m0 - mn0) + su0; m0 = mn0;
        l1 = l1 * __expf(m1 - mn1) + su1; m1 = mn1;
        __syncthreads();
    }
    const float li0 = 1.0f / l0, li1 = 1.0f / l1;

    // ---- zero-fill masked probs tiles ----
    {
        float2 z = make_float2(0.f, 0.f);
        for (int jt = jmax + 1; jt < S_LEN / 64; jt++) {
            const int c0 = jt * 64;
#pragma unroll
            for (int nt = 0; nt < 8; nt++) {
                int col = c0 + nt * 8 + fc;
                *(float2*)&probs[((size_t)h * S_LEN + grow0) * S_LEN + col] = z;
                *(float2*)&probs[((size_t)h * S_LEN + grow1) * S_LEN + col] = z;
            }
        }
    }

    float o[16][4];
#pragma unroll
    for (int nt = 0; nt < 16; nt++)
#pragma unroll
        for (int q = 0; q < 4; q++) o[nt][q] = 0.f;

    issue_S(0, 0);
    CP_COMMIT();
    issue_V(0);
    CP_COMMIT();

    // ================= PASS 2 =================
    for (int jt = 0; jt <= jmax; jt++) {
        if (jt < jmax) {
            issue_S(jt + 1, (jt + 1) & 1);
            CP_COMMIT();
            CP_WAIT(2);
        } else {
            CP_WAIT(1);
        }
        __syncthreads();

        const float* sf = (const float*)&smbuf[SSST + (jt & 1) * SSTAGE_UNITS];
        const int c0 = jt * 64;
        const int pr0 = wm + erow, pr1 = pr0 + 8;

        // exp/normalize -> probs, and pack P hi/lo A-fragments in registers.
        // A-frag for k-slice kk: {ph0[2kk], ph1[2kk], ph0[2kk+1], ph1[2kk+1]}
        uint32_t ph0[8], ph1[8], pl0[8], pl1[8];
#pragma unroll
        for (int nt = 0; nt < 8; nt++) {
            int cl = nt * 8 + fc;
            float2 s01 = *(const float2*)&sf[pr0 * S_PITCH_F + cl];
            float2 s23 = *(const float2*)&sf[pr1 * S_PITCH_F + cl];
            float p0 = __expf(s01.x - m0) * li0;
            float p1 = __expf(s01.y - m0) * li0;
            float p2 = __expf(s23.x - m1) * li1;
            float p3 = __expf(s23.y - m1) * li1;
            int cb = c0 + cl;
            *(float2*)&probs[((size_t)h * S_LEN + grow0) * S_LEN + cb] = make_float2(p0, p1);
            *(float2*)&probs[((size_t)h * S_LEN + grow1) * S_LEN + cb] = make_float2(p2, p3);
            __half h0, l0h, h1, l1h, h2, l2h, h3, l3h;
            split16(p0, h0, l0h); split16(p1, h1, l1h);
            split16(p2, h2, l2h); split16(p3, h3, l3h);
            ph0[nt] = packh2(h0, h1);
            ph1[nt] = packh2(h2, h3);
            pl0[nt] = packh2(l0h, l1h);
            pl1[nt] = packh2(l2h, l3h);
        }

        if (jt < jmax) CP_WAIT(1); else CP_WAIT(0);
        __syncthreads();

        // P @ V: A from registers, B from SVH smem
#pragma unroll
        for (int kk = 0; kk < 4; kk++) {
            uint32_t aH[4] = { ph0[2 * kk], ph1[2 * kk], ph0[2 * kk + 1], ph1[2 * kk + 1] };
            uint32_t aL[4] = { pl0[2 * kk], pl1[2 * kk], pl0[2 * kk + 1], pl1[2 * kk + 1] };
            uint32_t b[8][4];
#pragma unroll
            for (int nt2 = 0; nt2 < 8; nt2++)
                ldsm_x4(sb + (uint32_t)(SVH + (nt2 * 16 + brow) * AT_VP + kk * 16 + bcol) * 2, b[nt2]);
#pragma unroll
            for (int nt = 0; nt < 16; nt++) {
                uint32_t b0 = b[nt >> 1][(nt & 1) * 2];
                uint32_t b1 = b[nt >> 1][(nt & 1) * 2 + 1];
                mma16816(o[nt], aH, b0, b1);
                mma16816(o[nt], aL, b0, b1);
            }
        }
        __syncthreads();

        if (jt < jmax) {
            issue_V(jt + 1);
            CP_COMMIT();
        }
    }

    // ---- epilogue: split O to fp16 hi/lo in [s][h*128+d] layout ----
#pragma unroll
    for (int nt = 0; nt < 16; nt++) {
        int d = nt * 8 + fc;
        size_t b0 = (size_t)grow0 * HIDDEN + h * HDIM + d;
        size_t b1 = (size_t)grow1 * HIDDEN + h * HDIM + d;
        __half h0, l0h, h1, l1h, h2, l2h, h3, l3h;
        split16(o[nt][0], h0, l0h); split16(o[nt][1], h1, l1h);
        split16(o[nt][2], h2, l2h); split16(o[nt][3], h3, l3h);
        __half2 hp01; hp01.x = h0;  hp01.y = h1;
        __half2 hp23; hp23.x = h2;  hp23.y = h3;
        __half2 lp01; lp01.x = l0h; lp01.y = l1h;
        __half2 lp23; lp23.x = l2h; lp23.y = l3h;
        *(__half2*)&ahi[b0] = hp01;
        *(__half2*)&ahi[b1] = hp23;
        *(__half2*)&alo[b0] = lp01;
        *(__half2*)&alo[b1] = lp23;
    }
}

// ---------------------------------------------------------------------------
// Launch
// ---------------------------------------------------------------------------
extern "C" void kernel_launch(void* const* d_in, const int* in_sizes, int n_in,
                              void* d_out, int out_size) {
    const float* X  = (const float*)d_in[0];
    const float* Wq = (const float*)d_in[2];
    const float* Wk = (const float*)d_in[3];
    const float* Wv = (const float*)d_in[4];
    const float* Wo = (const float*)d_in[5];
    const float* qw = (const float*)d_in[6];
    const float* kw = (const float*)d_in[7];

    float* out   = (float*)d_out;
    float* new_k = out + (size_t)S_LEN * HIDDEN;
    float* new_v = new_k + (size_t)NKV * S_LEN * HDIM;
    float* probs = new_v + (size_t)NKV * S_LEN * HDIM;

    float *qtmp, *ktmp, *vtmp;
    __half *xhi, *xlo, *ahi, *alo, *qhi, *qlo, *khs, *vth;
    __half *wq, *wk, *wv, *wo;
    cudaGetSymbolAddress((void**)&qtmp, g_qtmp);
    cudaGetSymbolAddress((void**)&ktmp, g_ktmp);
    cudaGetSymbolAddress((void**)&vtmp, g_vtmp);
    cudaGetSymbolAddress((void**)&xhi, g_xhi);
    cudaGetSymbolAddress((void**)&xlo, g_xlo);
    cudaGetSymbolAddress((void**)&ahi, g_ahi);
    cudaGetSymbolAddress((void**)&alo, g_alo);
    cudaGetSymbolAddress((void**)&qhi, g_qhi);
    cudaGetSymbolAddress((void**)&qlo, g_qlo);
    cudaGetSymbolAddress((void**)&khs, g_kh);
    cudaGetSymbolAddress((void**)&vth, g_vth);
    cudaGetSymbolAddress((void**)&wq, g_wqt);
    cudaGetSymbolAddress((void**)&wk, g_wkt);
    cudaGetSymbolAddress((void**)&wv, g_wvt);
    cudaGetSymbolAddress((void**)&wo, g_wot);

    // ---- conversions ----
    transpose_all<<<dim3(128, 128, 4), dim3(32, 8)>>>(
        Wq, Wk, Wv, Wo, wq, wk, wv, wo);
    {
        int n = S_LEN * HIDDEN;
        split_kernel<<<(n + 255) / 256, 256>>>(X, xhi, xlo, n);
    }

    // ---- Q+K+V fused: 256 + 64 + 64 = 384 CTAs ----
    cudaFuncSetAttribute(gemm_mma3, cudaFuncAttributeMaxDynamicSharedMemorySize,
                         GEMM3_SMEM);
    gemm_mma3<<<384, 512, GEMM3_SMEM>>>(
        xhi, xlo,
        wq, qtmp, HIDDEN,
        wk, ktmp, NKV * HDIM,
        wv, vtmp, NKV * HDIM,
        256, 320);

    // ---- RMSNorm + RoPE + splits ----
    norm_rope_q<<<dim3(S_LEN, NHEADS), 128>>>(qtmp, qw, qhi, qlo);
    norm_rope_k<<<dim3(S_LEN, NKV), 128>>>(ktmp, kw, new_k, khs);

    // ---- V transpose + fp16 ----
    v_split_transpose<<<dim3(S_LEN / 32, HDIM / 32, NKV), dim3(32, 8)>>>(
        vtmp, new_v, vth);

    // ---- attention ----
    cudaFuncSetAttribute(attention_mma,
                         cudaFuncAttributeMaxDynamicSharedMemorySize, AT_SMEM_BYTES);
    attention_mma<<<dim3(S_LEN / 128, NHEADS), 256, AT_SMEM_BYTES>>>(
        qhi, qlo, khs, vth, probs, ahi, alo);

    // ---- O projection ----
    gemm_mma3<<<256, 512, GEMM3_SMEM>>>(
        ahi, alo,
        wo, out, HIDDEN,
        wo, out, HIDDEN,
        wo, out, HIDDEN,
        256, 256);
}